// round 2
// baseline (speedup 1.0000x reference)
#include <cuda_runtime.h>
#include <cuda_bf16.h>
#include <math.h>

// ---------------------------------------------------------------------------
// Static scratch (allocation-free rule: __device__ globals)
// ---------------------------------------------------------------------------
__device__ float g_xn[3 * 800 * 800];
__device__ float g_stem[64 * 400 * 400];
__device__ float g_c2[256 * 200 * 200];
__device__ float g_c3[256 * 100 * 100];
__device__ float g_c4[256 * 50 * 50];
__device__ float g_c5[256 * 25 * 25];
__device__ float g_f2[256 * 200 * 200];
__device__ float g_f3[256 * 100 * 100];
__device__ float g_f4[256 * 50 * 50];
__device__ float g_f5[256 * 25 * 25];
__device__ float g_t[256 * 200 * 200];      // RPN hidden, reused per level
__device__ float g_cls[3 * 200 * 200];      // reused per level
__device__ float g_box[12 * 200 * 200];     // reused per level
__device__ float g_decb[120000 * 4];        // reused per level
__device__ float g_decs[120000];            // reused per level
__device__ float g_boxes4k[4000 * 4];
__device__ float g_scores4k[4000];
__device__ float g_props[512 * 4];
__device__ float g_pooled[512 * 12544];
__device__ float g_fc1[512 * 1024];
__device__ float g_fc2[512 * 1024];

__constant__ float c_mean[3] = {0.485f, 0.456f, 0.406f};
__constant__ float c_std[3]  = {0.229f, 0.224f, 0.225f};

// ---------------------------------------------------------------------------
// Normalize: (x - mean) / std
// ---------------------------------------------------------------------------
__global__ void normalize_kernel(const float* __restrict__ x, float* __restrict__ out) {
    int i = blockIdx.x * blockDim.x + threadIdx.x;
    if (i >= 3 * 800 * 800) return;
    int c = i / (800 * 800);
    out[i] = (x[i] - c_mean[c]) / c_std[c];
}

// ---------------------------------------------------------------------------
// Stem conv: 7x7 stride 2, pad_lo 2, Cin=3, Cout=64, 800->400, ReLU
// ---------------------------------------------------------------------------
__global__ void stem_conv_kernel(const float* __restrict__ in, const float* __restrict__ w,
                                 float* __restrict__ out) {
    int idx = blockIdx.x * blockDim.x + threadIdx.x;
    if (idx >= 64 * 400 * 400) return;
    int ox = idx % 400;
    int oy = (idx / 400) % 400;
    int oc = idx / 160000;
    float acc = 0.f;
    for (int ci = 0; ci < 3; ci++) {
        const float* inp = in + ci * 640000;
        const float* wp = w + (oc * 3 + ci) * 49;
#pragma unroll
        for (int ky = 0; ky < 7; ky++) {
            int iy = oy * 2 - 2 + ky;
            if (iy < 0 || iy >= 800) continue;
#pragma unroll
            for (int kx = 0; kx < 7; kx++) {
                int ix = ox * 2 - 2 + kx;
                if (ix < 0 || ix >= 800) continue;
                acc += inp[iy * 800 + ix] * wp[ky * 7 + kx];
            }
        }
    }
    out[idx] = fmaxf(acc, 0.f);
}

// ---------------------------------------------------------------------------
// Generic 3x3 conv, templated stride / pad_lo, smem-tiled
// Tile: 16x8 spatial, 8 output channels per block. 128 threads.
// ---------------------------------------------------------------------------
template <int S, int PADLO>
__global__ void conv3x3_kernel(const float* __restrict__ in, const float* __restrict__ w,
                               float* __restrict__ out, int Cin, int Hin, int Win,
                               int Hout, int Wout, int do_relu) {
    constexpr int TW = 16, TH = 8, OCB = 8;
    constexpr int IW = (TW - 1) * S + 3;
    constexpr int IH = (TH - 1) * S + 3;
    __shared__ float sIn[IH][IW + 1];
    __shared__ float sW[OCB][9];

    const int tid = threadIdx.x;
    const int tx = tid & 15, ty = tid >> 4;
    const int ox0 = blockIdx.x * TW, oy0 = blockIdx.y * TH;
    const int oc0 = blockIdx.z * OCB;
    const int ix0 = ox0 * S - PADLO, iy0 = oy0 * S - PADLO;

    float acc[OCB];
#pragma unroll
    for (int j = 0; j < OCB; j++) acc[j] = 0.f;

    for (int ci = 0; ci < Cin; ci++) {
        const float* inp = in + (size_t)ci * Hin * Win;
        for (int idx = tid; idx < IH * IW; idx += 128) {
            int r = idx / IW, c = idx % IW;
            int gy = iy0 + r, gx = ix0 + c;
            float v = 0.f;
            if (gy >= 0 && gy < Hin && gx >= 0 && gx < Win) v = inp[gy * Win + gx];
            sIn[r][c] = v;
        }
        if (tid < OCB * 9) {
            int j = tid / 9, t = tid % 9;
            sW[j][t] = w[((size_t)(oc0 + j) * Cin + ci) * 9 + t];
        }
        __syncthreads();
#pragma unroll
        for (int ky = 0; ky < 3; ky++) {
#pragma unroll
            for (int kx = 0; kx < 3; kx++) {
                float v = sIn[ty * S + ky][tx * S + kx];
#pragma unroll
                for (int j = 0; j < OCB; j++) acc[j] += v * sW[j][ky * 3 + kx];
            }
        }
        __syncthreads();
    }
    int ox = ox0 + tx, oy = oy0 + ty;
    if (ox < Wout && oy < Hout) {
#pragma unroll
        for (int j = 0; j < OCB; j++) {
            float v = acc[j];
            if (do_relu) v = fmaxf(v, 0.f);
            out[((size_t)(oc0 + j) * Hout + oy) * Wout + ox] = v;
        }
    }
}

// ---------------------------------------------------------------------------
// 1x1 conv (no bias, no relu)
// ---------------------------------------------------------------------------
__global__ void conv1x1_kernel(const float* __restrict__ in, const float* __restrict__ w,
                               float* __restrict__ out, int Cin, int Cout, int HW) {
    int idx = blockIdx.x * blockDim.x + threadIdx.x;
    if (idx >= Cout * HW) return;
    int p = idx % HW;
    int oc = idx / HW;
    float acc = 0.f;
    const float* wp = w + (size_t)oc * Cin;
    for (int ci = 0; ci < Cin; ci++) acc += in[(size_t)ci * HW + p] * wp[ci];
    out[idx] = acc;
}

// ---------------------------------------------------------------------------
// Anchor decode: per anchor (y,x,a), read cls + box deltas, produce box+score
// ---------------------------------------------------------------------------
__global__ void decode_kernel(const float* __restrict__ cls, const float* __restrict__ box,
                              int fh, int fw, float stride, float size,
                              float* __restrict__ dec_boxes, float* __restrict__ dec_scores) {
    int n = fh * fw * 3;
    int i = blockIdx.x * blockDim.x + threadIdx.x;
    if (i >= n) return;
    int a = i % 3;
    int rest = i / 3;
    int x = rest % fw;
    int y = rest / fw;

    // ws = size / sqrt(r), hs = size * sqrt(r); r in {0.5, 1, 2}
    const double wm[3] = {1.4142135623730951, 1.0, 0.7071067811865476};
    const double hm[3] = {0.7071067811865476, 1.0, 1.4142135623730951};
    float aw = (float)(size * wm[a]);
    float ah = (float)(size * hm[a]);
    float acx = (x + 0.5f) * stride;
    float acy = (y + 0.5f) * stride;

    int HW = fh * fw;
    int p = y * fw + x;
    float d0 = box[(a * 4 + 0) * HW + p];
    float d1 = box[(a * 4 + 1) * HW + p];
    float d2 = box[(a * 4 + 2) * HW + p];
    float d3 = box[(a * 4 + 3) * HW + p];
    float dw = fminf(fmaxf(d2, -4.f), 4.f);
    float dh = fminf(fmaxf(d3, -4.f), 4.f);
    float cx = acx + d0 * aw;
    float cy = acy + d1 * ah;
    float w = aw * expf(dw);
    float h = ah * expf(dh);
    float x1 = fminf(fmaxf(cx - w * 0.5f, 0.f), 800.f);
    float y1 = fminf(fmaxf(cy - h * 0.5f, 0.f), 800.f);
    float x2 = fminf(fmaxf(cx + w * 0.5f, 0.f), 800.f);
    float y2 = fminf(fmaxf(cy + h * 0.5f, 0.f), 800.f);
    dec_boxes[i * 4 + 0] = x1;
    dec_boxes[i * 4 + 1] = y1;
    dec_boxes[i * 4 + 2] = x2;
    dec_boxes[i * 4 + 3] = y2;
    dec_scores[i] = cls[a * HW + p];
}

// ---------------------------------------------------------------------------
// Top-k (k = 1000) per level via 4-pass radix select. One block.
// ---------------------------------------------------------------------------
__device__ __forceinline__ unsigned keyof(float f) {
    unsigned u = __float_as_uint(f);
    return (u & 0x80000000u) ? ~u : (u | 0x80000000u);
}

__global__ void topk_kernel(const float* __restrict__ scores, const float* __restrict__ boxes,
                            int n, int k,
                            float* __restrict__ out_scores, float* __restrict__ out_boxes) {
    __shared__ unsigned hist[256];
    __shared__ unsigned sh_prefix, sh_kk, sh_cgt, sh_ceq;
    int tid = threadIdx.x;
    int NT = blockDim.x;
    if (tid == 0) { sh_prefix = 0; sh_kk = (unsigned)k; }
    unsigned mask = 0;
    __syncthreads();
    for (int shift = 24; shift >= 0; shift -= 8) {
        for (int b = tid; b < 256; b += NT) hist[b] = 0;
        __syncthreads();
        unsigned prefix = sh_prefix;
        for (int i = tid; i < n; i += NT) {
            unsigned key = keyof(scores[i]);
            if ((key & mask) == prefix) atomicAdd(&hist[(key >> shift) & 255], 1u);
        }
        __syncthreads();
        if (tid == 0) {
            unsigned kk = sh_kk, cum = 0;
            int b = 255;
            for (; b > 0; b--) {
                if (cum + hist[b] >= kk) break;
                cum += hist[b];
            }
            sh_prefix = prefix | ((unsigned)b << shift);
            sh_kk = kk - cum;
        }
        mask |= (0xFFu << shift);
        __syncthreads();
    }
    unsigned T = sh_prefix;
    unsigned kk = sh_kk;  // number needed among == T
    if (tid == 0) { sh_cgt = 0; sh_ceq = 0; }
    __syncthreads();
    int gtcount = k - (int)kk;
    for (int i = tid; i < n; i += NT) {
        unsigned key = keyof(scores[i]);
        int slot = -1;
        if (key > T) {
            slot = (int)atomicAdd(&sh_cgt, 1u);
        } else if (key == T) {
            unsigned e = atomicAdd(&sh_ceq, 1u);
            if (e < kk) slot = gtcount + (int)e;
        }
        if (slot >= 0) {
            out_scores[slot] = scores[i];
            out_boxes[slot * 4 + 0] = boxes[i * 4 + 0];
            out_boxes[slot * 4 + 1] = boxes[i * 4 + 1];
            out_boxes[slot * 4 + 2] = boxes[i * 4 + 2];
            out_boxes[slot * 4 + 3] = boxes[i * 4 + 3];
        }
    }
}

// ---------------------------------------------------------------------------
// NMS: one block, 512 threads, 512 sequential selections over 4000 candidates.
// All state in dynamic smem (96 KB).
// ---------------------------------------------------------------------------
__global__ void nms_kernel(const float* __restrict__ boxes, const float* __restrict__ scores,
                           float* __restrict__ props, float* __restrict__ out_props,
                           float* __restrict__ out_scores) {
    constexpr int N = 4000, NT = 512, POST = 512;
    extern __shared__ float sm[];
    float* sx1 = sm;
    float* sy1 = sm + N;
    float* sx2 = sm + 2 * N;
    float* sy2 = sm + 3 * N;
    float* sar = sm + 4 * N;
    float* ss  = sm + 5 * N;
    __shared__ float rv[NT / 32];
    __shared__ int ri[NT / 32];
    __shared__ int s_best;

    int tid = threadIdx.x;
    for (int i = tid; i < N; i += NT) {
        float a = boxes[i * 4 + 0], b = boxes[i * 4 + 1];
        float c = boxes[i * 4 + 2], d = boxes[i * 4 + 3];
        sx1[i] = a; sy1[i] = b; sx2[i] = c; sy2[i] = d;
        sar[i] = (c - a) * (d - b);
        ss[i] = scores[i];
    }
    __syncthreads();

    for (int it = 0; it < POST; it++) {
        float bv = -INFINITY;
        int bi = 0x7FFFFFFF;
        for (int i = tid; i < N; i += NT) {
            float v = ss[i];
            if (v > bv || (v == bv && i < bi)) { bv = v; bi = i; }
        }
#pragma unroll
        for (int off = 16; off; off >>= 1) {
            float ov = __shfl_down_sync(0xFFFFFFFFu, bv, off);
            int oi = __shfl_down_sync(0xFFFFFFFFu, bi, off);
            if (ov > bv || (ov == bv && oi < bi)) { bv = ov; bi = oi; }
        }
        if ((tid & 31) == 0) { rv[tid >> 5] = bv; ri[tid >> 5] = bi; }
        __syncthreads();
        if (tid == 0) {
            float fbv = rv[0]; int fbi = ri[0];
            for (int wz = 1; wz < NT / 32; wz++) {
                float ov = rv[wz]; int oi = ri[wz];
                if (ov > fbv || (ov == fbv && oi < fbi)) { fbv = ov; fbi = oi; }
            }
            s_best = fbi;
        }
        __syncthreads();
        int idx = s_best;
        if (tid == 0) {
            float a = sx1[idx], b = sy1[idx], c = sx2[idx], d = sy2[idx];
            props[it * 4 + 0] = a; props[it * 4 + 1] = b;
            props[it * 4 + 2] = c; props[it * 4 + 3] = d;
            out_props[it * 4 + 0] = a; out_props[it * 4 + 1] = b;
            out_props[it * 4 + 2] = c; out_props[it * 4 + 3] = d;
            out_scores[it] = scores[idx];  // ORIGINAL scores, like scores[keep]
        }
        float X1 = sx1[idx], Y1 = sy1[idx], X2 = sx2[idx], Y2 = sy2[idx], AR = sar[idx];
        for (int i = tid; i < N; i += NT) {
            float ix1 = fmaxf(sx1[i], X1), iy1 = fmaxf(sy1[i], Y1);
            float ix2 = fminf(sx2[i], X2), iy2 = fminf(sy2[i], Y2);
            float inter = fmaxf(ix2 - ix1, 0.f) * fmaxf(iy2 - iy1, 0.f);
            float iou = inter / (sar[i] + AR - inter + 1e-6f);
            if (iou > 0.7f) ss[i] = -INFINITY;
        }
        __syncthreads();
    }
}

// ---------------------------------------------------------------------------
// ROI Align on feats[0] (256, 200, 200), scale 0.25, POOL 7.
// One block per roi (512 blocks), 256 threads = channels, loop over 49 bins.
// ---------------------------------------------------------------------------
__global__ void roi_align_kernel(const float* __restrict__ feat, const float* __restrict__ rois,
                                 float* __restrict__ out) {
    __shared__ int six0[49], siy0[49], six1[49], siy1[49];
    __shared__ float swx[49], swy[49];
    int roi = blockIdx.x;
    int c = threadIdx.x;
    if (threadIdx.x < 49) {
        int p = threadIdx.x;
        int py = p / 7, px = p % 7;
        float r0 = rois[roi * 4 + 0] * 0.25f;
        float r1 = rois[roi * 4 + 1] * 0.25f;
        float bw = (rois[roi * 4 + 2] - rois[roi * 4 + 0]) * 0.25f / 7.0f;
        float bh = (rois[roi * 4 + 3] - rois[roi * 4 + 1]) * 0.25f / 7.0f;
        float gx = r0 + (px + 0.5f) * bw - 0.5f;
        float gy = r1 + (py + 0.5f) * bh - 0.5f;
        float fx = fminf(fmaxf(floorf(gx), 0.f), 199.f);
        float fy = fminf(fmaxf(floorf(gy), 0.f), 199.f);
        int x0 = (int)fx, y0 = (int)fy;
        six0[p] = x0; siy0[p] = y0;
        six1[p] = min(x0 + 1, 199);
        siy1[p] = min(y0 + 1, 199);
        swx[p] = fminf(fmaxf(gx - fx, 0.f), 1.f);
        swy[p] = fminf(fmaxf(gy - fy, 0.f), 1.f);
    }
    __syncthreads();
    const float* f = feat + (size_t)c * 40000;
    float* o = out + (size_t)roi * 12544 + (size_t)c * 49;
#pragma unroll 7
    for (int p = 0; p < 49; p++) {
        int x0 = six0[p], y0 = siy0[p], x1 = six1[p], y1 = siy1[p];
        float wx = swx[p], wy = swy[p];
        float v00 = f[y0 * 200 + x0];
        float v01 = f[y0 * 200 + x1];
        float v10 = f[y1 * 200 + x0];
        float v11 = f[y1 * 200 + x1];
        o[p] = v00 * (1.f - wy) * (1.f - wx) + v01 * (1.f - wy) * wx +
               v10 * wy * (1.f - wx) + v11 * wy * wx;
    }
}

// ---------------------------------------------------------------------------
// SGEMM: C = relu(A @ B + bias). A: MxK row-major, B: KxN row-major.
// BM=BN=64, BK=16, 256 threads, 4x4 per thread.
// ---------------------------------------------------------------------------
__global__ void sgemm_bias_relu(const float* __restrict__ A, const float* __restrict__ B,
                                const float* __restrict__ bias, float* __restrict__ C,
                                int M, int N, int K, int do_relu) {
    constexpr int BM = 64, BN = 64, BK = 16;
    __shared__ float sA[BK][BM + 1];
    __shared__ float sB[BK][BN + 1];
    int tid = threadIdx.x;
    int trow = tid / 16, tcol = tid % 16;
    int bm0 = blockIdx.y * BM, bn0 = blockIdx.x * BN;
    float acc[4][4];
#pragma unroll
    for (int i = 0; i < 4; i++)
#pragma unroll
        for (int j = 0; j < 4; j++) acc[i][j] = 0.f;

    for (int k0 = 0; k0 < K; k0 += BK) {
#pragma unroll
        for (int l = 0; l < 4; l++) {
            int e = tid + l * 256;
            int ar = e / BK, ac = e % BK;
            sA[ac][ar] = A[(size_t)(bm0 + ar) * K + k0 + ac];
        }
#pragma unroll
        for (int l = 0; l < 4; l++) {
            int e = tid + l * 256;
            int br = e / BN, bc = e % BN;
            sB[br][bc] = B[(size_t)(k0 + br) * N + bn0 + bc];
        }
        __syncthreads();
#pragma unroll
        for (int kk = 0; kk < BK; kk++) {
            float a[4], b[4];
#pragma unroll
            for (int i = 0; i < 4; i++) a[i] = sA[kk][trow * 4 + i];
#pragma unroll
            for (int j = 0; j < 4; j++) b[j] = sB[kk][tcol * 4 + j];
#pragma unroll
            for (int i = 0; i < 4; i++)
#pragma unroll
                for (int j = 0; j < 4; j++) acc[i][j] += a[i] * b[j];
        }
        __syncthreads();
    }
#pragma unroll
    for (int i = 0; i < 4; i++) {
#pragma unroll
        for (int j = 0; j < 4; j++) {
            int r = bm0 + trow * 4 + i, c = bn0 + tcol * 4 + j;
            float v = acc[i][j] + bias[c];
            if (do_relu) v = fmaxf(v, 0.f);
            C[(size_t)r * N + c] = v;
        }
    }
}

// ---------------------------------------------------------------------------
// Final heads: cls (1024->2) and breg (1024->8), write directly to d_out.
// Layout: [0,1024) cls, [1024,5120) breg, [5120,7168) props, [7168,7680) scores
// ---------------------------------------------------------------------------
__global__ void head_kernel(const float* __restrict__ A, const float* __restrict__ cw,
                            const float* __restrict__ cb, const float* __restrict__ bw,
                            const float* __restrict__ bb, float* __restrict__ out) {
    int m = blockIdx.x;
    int j = threadIdx.x;
    if (j >= 10) return;
    const float* a = A + (size_t)m * 1024;
    bool is_cls = (j < 2);
    const float* W = is_cls ? cw : bw;
    int n = is_cls ? j : j - 2;
    int N = is_cls ? 2 : 8;
    float acc = 0.f;
    for (int k = 0; k < 1024; k++) acc += a[k] * W[(size_t)k * N + n];
    acc += is_cls ? cb[n] : bb[n];
    if (is_cls) out[m * 2 + n] = acc;
    else out[1024 + m * 8 + n] = acc;
}

// ---------------------------------------------------------------------------
// Host: launch sequence
// ---------------------------------------------------------------------------
static inline void* symaddr(const void* sym) {
    void* p = nullptr;
    cudaGetSymbolAddress(&p, sym);
    return p;
}

extern "C" void kernel_launch(void* const* d_in, const int* in_sizes, int n_in,
                              void* d_out, int out_size) {
    const float* x       = (const float*)d_in[0];
    const float* stem_w  = (const float*)d_in[1];
    const float* c2_w    = (const float*)d_in[2];
    const float* c3_w    = (const float*)d_in[3];
    const float* c4_w    = (const float*)d_in[4];
    const float* c5_w    = (const float*)d_in[5];
    const float* fpn_w[4] = {(const float*)d_in[6], (const float*)d_in[7],
                             (const float*)d_in[8], (const float*)d_in[9]};
    const float* rpn_w     = (const float*)d_in[10];
    const float* rpn_cls_w = (const float*)d_in[11];
    const float* rpn_box_w = (const float*)d_in[12];
    const float* fc1_w = (const float*)d_in[13];
    const float* fc1_b = (const float*)d_in[14];
    const float* fc2_w = (const float*)d_in[15];
    const float* fc2_b = (const float*)d_in[16];
    const float* cls_w = (const float*)d_in[17];
    const float* cls_b = (const float*)d_in[18];
    const float* breg_w = (const float*)d_in[19];
    const float* breg_b = (const float*)d_in[20];
    float* out = (float*)d_out;

    float* p_xn   = (float*)symaddr(g_xn);
    float* p_stem = (float*)symaddr(g_stem);
    float* p_c2   = (float*)symaddr(g_c2);
    float* p_c3   = (float*)symaddr(g_c3);
    float* p_c4   = (float*)symaddr(g_c4);
    float* p_c5   = (float*)symaddr(g_c5);
    float* p_f[4] = {(float*)symaddr(g_f2), (float*)symaddr(g_f3),
                     (float*)symaddr(g_f4), (float*)symaddr(g_f5)};
    float* p_t    = (float*)symaddr(g_t);
    float* p_cls  = (float*)symaddr(g_cls);
    float* p_box  = (float*)symaddr(g_box);
    float* p_decb = (float*)symaddr(g_decb);
    float* p_decs = (float*)symaddr(g_decs);
    float* p_b4k  = (float*)symaddr(g_boxes4k);
    float* p_s4k  = (float*)symaddr(g_scores4k);
    float* p_props = (float*)symaddr(g_props);
    float* p_pool = (float*)symaddr(g_pooled);
    float* p_fc1  = (float*)symaddr(g_fc1);
    float* p_fc2  = (float*)symaddr(g_fc2);

    // 1. normalize
    normalize_kernel<<<(3 * 800 * 800 + 255) / 256, 256>>>(x, p_xn);
    // 2. stem 7x7 s2
    stem_conv_kernel<<<(64 * 400 * 400 + 255) / 256, 256>>>(p_xn, stem_w, p_stem);

    // 3. backbone strided 3x3 convs (relu)
    {
        dim3 g((200 + 15) / 16, (200 + 7) / 8, 32);
        conv3x3_kernel<2, 0><<<g, 128>>>(p_stem, c2_w, p_c2, 64, 400, 400, 200, 200, 1);
    }
    {
        dim3 g((100 + 15) / 16, (100 + 7) / 8, 32);
        conv3x3_kernel<2, 0><<<g, 128>>>(p_c2, c3_w, p_c3, 256, 200, 200, 100, 100, 1);
    }
    {
        dim3 g((50 + 15) / 16, (50 + 7) / 8, 32);
        conv3x3_kernel<2, 0><<<g, 128>>>(p_c3, c4_w, p_c4, 256, 100, 100, 50, 50, 1);
    }
    {
        dim3 g((25 + 15) / 16, (25 + 7) / 8, 32);
        conv3x3_kernel<2, 0><<<g, 128>>>(p_c4, c5_w, p_c5, 256, 50, 50, 25, 25, 1);
    }

    // 4. FPN lateral convs (no relu)
    const float* csrc[4] = {p_c2, p_c3, p_c4, p_c5};
    const int fh[4] = {200, 100, 50, 25};
    for (int l = 0; l < 4; l++) {
        dim3 g((fh[l] + 15) / 16, (fh[l] + 7) / 8, 32);
        conv3x3_kernel<1, 1><<<g, 128>>>(csrc[l], fpn_w[l], p_f[l], 256, fh[l], fh[l],
                                         fh[l], fh[l], 0);
    }

    // 5. RPN per level: conv-relu, 1x1 heads, decode, top-1000
    const float strides[4] = {4.f, 8.f, 16.f, 32.f};
    const float sizes[4] = {32.f, 64.f, 128.f, 256.f};
    for (int l = 0; l < 4; l++) {
        int H = fh[l], HW = H * H;
        dim3 g((H + 15) / 16, (H + 7) / 8, 32);
        conv3x3_kernel<1, 1><<<g, 128>>>(p_f[l], rpn_w, p_t, 256, H, H, H, H, 1);
        conv1x1_kernel<<<(3 * HW + 255) / 256, 256>>>(p_t, rpn_cls_w, p_cls, 256, 3, HW);
        conv1x1_kernel<<<(12 * HW + 255) / 256, 256>>>(p_t, rpn_box_w, p_box, 256, 12, HW);
        int n = 3 * HW;
        decode_kernel<<<(n + 255) / 256, 256>>>(p_cls, p_box, H, H, strides[l], sizes[l],
                                                p_decb, p_decs);
        topk_kernel<<<1, 1024>>>(p_decs, p_decb, n, 1000, p_s4k + l * 1000,
                                 p_b4k + l * 4000);
    }

    // 6. NMS (512 out of 4000)
    cudaFuncSetAttribute(nms_kernel, cudaFuncAttributeMaxDynamicSharedMemorySize, 96000);
    nms_kernel<<<1, 512, 96000>>>(p_b4k, p_s4k, p_props, out + 5120, out + 7168);

    // 7. ROI align on feats[0]
    roi_align_kernel<<<512, 256>>>(p_f[0], p_props, p_pool);

    // 8. FC head
    {
        dim3 g(1024 / 64, 512 / 64);
        sgemm_bias_relu<<<g, 256>>>(p_pool, fc1_w, fc1_b, p_fc1, 512, 1024, 12544, 1);
        sgemm_bias_relu<<<g, 256>>>(p_fc1, fc2_w, fc2_b, p_fc2, 512, 1024, 1024, 1);
    }
    head_kernel<<<512, 32>>>(p_fc2, cls_w, cls_b, breg_w, breg_b, out);
}

// round 7
// speedup vs baseline: 1.1912x; 1.1912x over previous
#include <cuda_runtime.h>
#include <cuda_bf16.h>
#include <math.h>

// ---------------------------------------------------------------------------
// Static scratch (allocation-free rule: __device__ globals)
// ---------------------------------------------------------------------------
__device__ float g_stem[64 * 400 * 400];
__device__ float g_c2[256 * 200 * 200];
__device__ float g_c3[256 * 100 * 100];
__device__ float g_c4[256 * 50 * 50];
__device__ float g_c5[256 * 25 * 25];
__device__ float g_f2[256 * 200 * 200];
__device__ float g_f3[256 * 100 * 100];
__device__ float g_f4[256 * 50 * 50];
__device__ float g_f5[256 * 25 * 25];
__device__ float g_t[256 * 200 * 200];      // RPN hidden, reused per level
__device__ float g_cls[3 * 200 * 200];      // reused per level
__device__ float g_box[12 * 200 * 200];     // reused per level
__device__ float g_decb[120000 * 4];        // reused per level
__device__ float g_decs[120000];            // reused per level
__device__ float g_boxes4k[4000 * 4];
__device__ float g_scores4k[4000];
__device__ float g_props[512 * 4];
__device__ float g_pooled[512 * 12544];
__device__ float g_fc1[512 * 1024];
__device__ float g_fc2[512 * 1024];

__constant__ float c_mean[3] = {0.485f, 0.456f, 0.406f};
__constant__ float c_std[3]  = {0.229f, 0.224f, 0.225f};

// ---------------------------------------------------------------------------
// Packed f32x2 helpers (Blackwell FFMA2 — ptxas never auto-generates this)
// ---------------------------------------------------------------------------
__device__ __forceinline__ void ffma2(unsigned long long& d, unsigned long long a,
                                      unsigned long long b) {
    asm("fma.rn.f32x2 %0, %1, %2, %0;" : "+l"(d) : "l"(a), "l"(b));
}
__device__ __forceinline__ unsigned long long dup2(float v) {
    unsigned long long r;
    unsigned u = __float_as_uint(v);
    asm("mov.b64 %0, {%1, %1};" : "=l"(r) : "r"(u));
    return r;
}
__device__ __forceinline__ float2 unpack2(unsigned long long v) {
    unsigned lo, hi;
    asm("mov.b64 {%0, %1}, %2;" : "=r"(lo), "=r"(hi) : "l"(v));
    float2 f;
    f.x = __uint_as_float(lo);
    f.y = __uint_as_float(hi);
    return f;
}

// ---------------------------------------------------------------------------
// Stem conv 7x7 s2 (800->400, Cin=3, Cout=64) with fused normalize.
// Tile 32x8 out, 16 oc per block, f32x2 over oc pairs. 128 threads.
// ---------------------------------------------------------------------------
__global__ void stem_v2(const float* __restrict__ x, const float* __restrict__ w,
                        float* __restrict__ out) {
    constexpr int IH = 21, IW = 69;  // (8-1)*2+7, (32-1)*2+7
    __shared__ float sIn[3][IH][IW];
    __shared__ __align__(16) float sW[3][49][16];

    const int tid = threadIdx.x;
    const int tx = tid & 31, ty = tid >> 5;  // ty in 0..3, 2 rows each
    const int ox0 = blockIdx.x * 32, oy0 = blockIdx.y * 8, oc0 = blockIdx.z * 16;
    const int ix0 = ox0 * 2 - 2, iy0 = oy0 * 2 - 2;

    // load + normalize input tile
    for (int idx = tid; idx < 3 * IH * IW; idx += 128) {
        int ci = idx / (IH * IW);
        int rem = idx % (IH * IW);
        int r = rem / IW, c = rem % IW;
        int gy = iy0 + r, gx = ix0 + c;
        float v = 0.f;
        if (gy >= 0 && gy < 800 && gx >= 0 && gx < 800)
            v = (x[ci * 640000 + gy * 800 + gx] - c_mean[ci]) / c_std[ci];
        sIn[ci][r][c] = v;
    }
    // load weights [oc][ci][49] -> sW[ci][tap][oc]
    for (int idx = tid; idx < 3 * 49 * 16; idx += 128) {
        int j = idx & 15;
        int t = (idx >> 4) % 49;
        int ci = idx / (49 * 16);
        sW[ci][t][j] = w[(oc0 + j) * 147 + ci * 49 + t];
    }
    __syncthreads();

    unsigned long long acc[2][8];
#pragma unroll
    for (int r = 0; r < 2; r++)
#pragma unroll
        for (int jp = 0; jp < 8; jp++) acc[r][jp] = 0ull;

#pragma unroll 1
    for (int ci = 0; ci < 3; ci++) {
#pragma unroll 1
        for (int ky = 0; ky < 7; ky++) {
#pragma unroll
            for (int kx = 0; kx < 7; kx++) {
                int t = ky * 7 + kx;
                unsigned long long wv[8];
#pragma unroll
                for (int jp = 0; jp < 8; jp++)
                    wv[jp] = *(const unsigned long long*)&sW[ci][t][2 * jp];
#pragma unroll
                for (int r = 0; r < 2; r++) {
                    float v = sIn[ci][(ty * 2 + r) * 2 + ky][tx * 2 + kx];
                    unsigned long long vv = dup2(v);
#pragma unroll
                    for (int jp = 0; jp < 8; jp++) ffma2(acc[r][jp], vv, wv[jp]);
                }
            }
        }
    }

    int xo = ox0 + tx;
    if (xo < 400) {
#pragma unroll
        for (int r = 0; r < 2; r++) {
            int yo = oy0 + ty * 2 + r;
#pragma unroll
            for (int jp = 0; jp < 8; jp++) {
                float2 f = unpack2(acc[r][jp]);
                out[(size_t)(oc0 + 2 * jp) * 160000 + yo * 400 + xo] = fmaxf(f.x, 0.f);
                out[(size_t)(oc0 + 2 * jp + 1) * 160000 + yo * 400 + xo] = fmaxf(f.y, 0.f);
            }
        }
    }
}

// ---------------------------------------------------------------------------
// 3x3 conv v2: tile 32x16 out, 8 oc/block, 4 px/thread, f32x2 over oc pairs.
// 128 threads.
// ---------------------------------------------------------------------------
template <int S, int PADLO>
__global__ void conv3x3_v2(const float* __restrict__ in, const float* __restrict__ w,
                           float* __restrict__ out, int Cin, int Hin, int Win,
                           int Hout, int Wout, int do_relu) {
    constexpr int TW = 32, TH = 16, OCB = 8;
    constexpr int IW = (TW - 1) * S + 3;
    constexpr int IH = (TH - 1) * S + 3;
    __shared__ float sIn[IH][IW];
    __shared__ __align__(16) float sW[9][OCB];

    const int tid = threadIdx.x;
    const int tx = tid & 31, ty = tid >> 5;  // ty 0..3, 4 rows each
    const int ox0 = blockIdx.x * TW, oy0 = blockIdx.y * TH, oc0 = blockIdx.z * OCB;
    const int ix0 = ox0 * S - PADLO, iy0 = oy0 * S - PADLO;
    const bool interior =
        (ix0 >= 0) && (iy0 >= 0) && (ix0 + IW <= Win) && (iy0 + IH <= Hin);

    unsigned long long acc[4][4];
#pragma unroll
    for (int r = 0; r < 4; r++)
#pragma unroll
        for (int jp = 0; jp < 4; jp++) acc[r][jp] = 0ull;

    for (int ci = 0; ci < Cin; ci++) {
        const float* inp = in + (size_t)ci * Hin * Win;
        if (interior) {
            for (int idx = tid; idx < IH * IW; idx += 128) {
                int r = idx / IW, c = idx % IW;
                sIn[r][c] = __ldg(&inp[(iy0 + r) * Win + ix0 + c]);
            }
        } else {
            for (int idx = tid; idx < IH * IW; idx += 128) {
                int r = idx / IW, c = idx % IW;
                int gy = iy0 + r, gx = ix0 + c;
                float v = 0.f;
                if (gy >= 0 && gy < Hin && gx >= 0 && gx < Win) v = inp[gy * Win + gx];
                sIn[r][c] = v;
            }
        }
        if (tid < 72)
            sW[tid >> 3][tid & 7] =
                w[((size_t)(oc0 + (tid & 7)) * Cin + ci) * 9 + (tid >> 3)];
        __syncthreads();

#pragma unroll
        for (int ky = 0; ky < 3; ky++) {
#pragma unroll
            for (int kx = 0; kx < 3; kx++) {
                const int t = ky * 3 + kx;
                unsigned long long wv0 = *(const unsigned long long*)&sW[t][0];
                unsigned long long wv1 = *(const unsigned long long*)&sW[t][2];
                unsigned long long wv2 = *(const unsigned long long*)&sW[t][4];
                unsigned long long wv3 = *(const unsigned long long*)&sW[t][6];
#pragma unroll
                for (int r = 0; r < 4; r++) {
                    float v = sIn[(ty * 4 + r) * S + ky][tx * S + kx];
                    unsigned long long vv = dup2(v);
                    ffma2(acc[r][0], vv, wv0);
                    ffma2(acc[r][1], vv, wv1);
                    ffma2(acc[r][2], vv, wv2);
                    ffma2(acc[r][3], vv, wv3);
                }
            }
        }
        __syncthreads();
    }

    int xo = ox0 + tx;
    if (xo < Wout) {
#pragma unroll
        for (int r = 0; r < 4; r++) {
            int yo = oy0 + ty * 4 + r;
            if (yo < Hout) {
#pragma unroll
                for (int jp = 0; jp < 4; jp++) {
                    float2 f = unpack2(acc[r][jp]);
                    if (do_relu) {
                        f.x = fmaxf(f.x, 0.f);
                        f.y = fmaxf(f.y, 0.f);
                    }
                    out[((size_t)(oc0 + 2 * jp) * Hout + yo) * Wout + xo] = f.x;
                    out[((size_t)(oc0 + 2 * jp + 1) * Hout + yo) * Wout + xo] = f.y;
                }
            }
        }
    }
}

// ---------------------------------------------------------------------------
// 1x1 conv (no bias, no relu)
// ---------------------------------------------------------------------------
__global__ void conv1x1_kernel(const float* __restrict__ in, const float* __restrict__ w,
                               float* __restrict__ out, int Cin, int Cout, int HW) {
    int idx = blockIdx.x * blockDim.x + threadIdx.x;
    if (idx >= Cout * HW) return;
    int p = idx % HW;
    int oc = idx / HW;
    float acc = 0.f;
    const float* wp = w + (size_t)oc * Cin;
    for (int ci = 0; ci < Cin; ci++) acc += in[(size_t)ci * HW + p] * wp[ci];
    out[idx] = acc;
}

// ---------------------------------------------------------------------------
// Anchor decode
// ---------------------------------------------------------------------------
__global__ void decode_kernel(const float* __restrict__ cls, const float* __restrict__ box,
                              int fh, int fw, float stride, float size,
                              float* __restrict__ dec_boxes, float* __restrict__ dec_scores) {
    int n = fh * fw * 3;
    int i = blockIdx.x * blockDim.x + threadIdx.x;
    if (i >= n) return;
    int a = i % 3;
    int rest = i / 3;
    int x = rest % fw;
    int y = rest / fw;

    const double wm[3] = {1.4142135623730951, 1.0, 0.7071067811865476};
    const double hm[3] = {0.7071067811865476, 1.0, 1.4142135623730951};
    float aw = (float)(size * wm[a]);
    float ah = (float)(size * hm[a]);
    float acx = (x + 0.5f) * stride;
    float acy = (y + 0.5f) * stride;

    int HW = fh * fw;
    int p = y * fw + x;
    float d0 = box[(a * 4 + 0) * HW + p];
    float d1 = box[(a * 4 + 1) * HW + p];
    float d2 = box[(a * 4 + 2) * HW + p];
    float d3 = box[(a * 4 + 3) * HW + p];
    float dw = fminf(fmaxf(d2, -4.f), 4.f);
    float dh = fminf(fmaxf(d3, -4.f), 4.f);
    float cx = acx + d0 * aw;
    float cy = acy + d1 * ah;
    float w = aw * expf(dw);
    float h = ah * expf(dh);
    float x1 = fminf(fmaxf(cx - w * 0.5f, 0.f), 800.f);
    float y1 = fminf(fmaxf(cy - h * 0.5f, 0.f), 800.f);
    float x2 = fminf(fmaxf(cx + w * 0.5f, 0.f), 800.f);
    float y2 = fminf(fmaxf(cy + h * 0.5f, 0.f), 800.f);
    dec_boxes[i * 4 + 0] = x1;
    dec_boxes[i * 4 + 1] = y1;
    dec_boxes[i * 4 + 2] = x2;
    dec_boxes[i * 4 + 3] = y2;
    dec_scores[i] = cls[a * HW + p];
}

// ---------------------------------------------------------------------------
// Top-k (k = 1000) per level via 4-pass radix select. One block.
// ---------------------------------------------------------------------------
__device__ __forceinline__ unsigned keyof(float f) {
    unsigned u = __float_as_uint(f);
    return (u & 0x80000000u) ? ~u : (u | 0x80000000u);
}

__global__ void topk_kernel(const float* __restrict__ scores, const float* __restrict__ boxes,
                            int n, int k,
                            float* __restrict__ out_scores, float* __restrict__ out_boxes) {
    __shared__ unsigned hist[256];
    __shared__ unsigned sh_prefix, sh_kk, sh_cgt, sh_ceq;
    int tid = threadIdx.x;
    int NT = blockDim.x;
    if (tid == 0) { sh_prefix = 0; sh_kk = (unsigned)k; }
    unsigned mask = 0;
    __syncthreads();
    for (int shift = 24; shift >= 0; shift -= 8) {
        for (int b = tid; b < 256; b += NT) hist[b] = 0;
        __syncthreads();
        unsigned prefix = sh_prefix;
        for (int i = tid; i < n; i += NT) {
            unsigned key = keyof(scores[i]);
            if ((key & mask) == prefix) atomicAdd(&hist[(key >> shift) & 255], 1u);
        }
        __syncthreads();
        if (tid == 0) {
            unsigned kk = sh_kk, cum = 0;
            int b = 255;
            for (; b > 0; b--) {
                if (cum + hist[b] >= kk) break;
                cum += hist[b];
            }
            sh_prefix = prefix | ((unsigned)b << shift);
            sh_kk = kk - cum;
        }
        mask |= (0xFFu << shift);
        __syncthreads();
    }
    unsigned T = sh_prefix;
    unsigned kk = sh_kk;
    if (tid == 0) { sh_cgt = 0; sh_ceq = 0; }
    __syncthreads();
    int gtcount = k - (int)kk;
    for (int i = tid; i < n; i += NT) {
        unsigned key = keyof(scores[i]);
        int slot = -1;
        if (key > T) {
            slot = (int)atomicAdd(&sh_cgt, 1u);
        } else if (key == T) {
            unsigned e = atomicAdd(&sh_ceq, 1u);
            if (e < kk) slot = gtcount + (int)e;
        }
        if (slot >= 0) {
            out_scores[slot] = scores[i];
            out_boxes[slot * 4 + 0] = boxes[i * 4 + 0];
            out_boxes[slot * 4 + 1] = boxes[i * 4 + 1];
            out_boxes[slot * 4 + 2] = boxes[i * 4 + 2];
            out_boxes[slot * 4 + 3] = boxes[i * 4 + 3];
        }
    }
}

// ---------------------------------------------------------------------------
// NMS: one block, 512 threads, 512 sequential selections over 4000 candidates.
// ---------------------------------------------------------------------------
__global__ void nms_kernel(const float* __restrict__ boxes, const float* __restrict__ scores,
                           float* __restrict__ props, float* __restrict__ out_props,
                           float* __restrict__ out_scores) {
    constexpr int N = 4000, NT = 512, POST = 512;
    extern __shared__ float sm[];
    float* sx1 = sm;
    float* sy1 = sm + N;
    float* sx2 = sm + 2 * N;
    float* sy2 = sm + 3 * N;
    float* sar = sm + 4 * N;
    float* ss  = sm + 5 * N;
    __shared__ float rv[NT / 32];
    __shared__ int ri[NT / 32];
    __shared__ int s_best;

    int tid = threadIdx.x;
    for (int i = tid; i < N; i += NT) {
        float a = boxes[i * 4 + 0], b = boxes[i * 4 + 1];
        float c = boxes[i * 4 + 2], d = boxes[i * 4 + 3];
        sx1[i] = a; sy1[i] = b; sx2[i] = c; sy2[i] = d;
        sar[i] = (c - a) * (d - b);
        ss[i] = scores[i];
    }
    __syncthreads();

    for (int it = 0; it < POST; it++) {
        float bv = -INFINITY;
        int bi = 0x7FFFFFFF;
        for (int i = tid; i < N; i += NT) {
            float v = ss[i];
            if (v > bv || (v == bv && i < bi)) { bv = v; bi = i; }
        }
#pragma unroll
        for (int off = 16; off; off >>= 1) {
            float ov = __shfl_down_sync(0xFFFFFFFFu, bv, off);
            int oi = __shfl_down_sync(0xFFFFFFFFu, bi, off);
            if (ov > bv || (ov == bv && oi < bi)) { bv = ov; bi = oi; }
        }
        if ((tid & 31) == 0) { rv[tid >> 5] = bv; ri[tid >> 5] = bi; }
        __syncthreads();
        if (tid == 0) {
            float fbv = rv[0]; int fbi = ri[0];
            for (int wz = 1; wz < NT / 32; wz++) {
                float ov = rv[wz]; int oi = ri[wz];
                if (ov > fbv || (ov == fbv && oi < fbi)) { fbv = ov; fbi = oi; }
            }
            s_best = fbi;
        }
        __syncthreads();
        int idx = s_best;
        if (tid == 0) {
            float a = sx1[idx], b = sy1[idx], c = sx2[idx], d = sy2[idx];
            props[it * 4 + 0] = a; props[it * 4 + 1] = b;
            props[it * 4 + 2] = c; props[it * 4 + 3] = d;
            out_props[it * 4 + 0] = a; out_props[it * 4 + 1] = b;
            out_props[it * 4 + 2] = c; out_props[it * 4 + 3] = d;
            out_scores[it] = scores[idx];
        }
        float X1 = sx1[idx], Y1 = sy1[idx], X2 = sx2[idx], Y2 = sy2[idx], AR = sar[idx];
        for (int i = tid; i < N; i += NT) {
            float ix1 = fmaxf(sx1[i], X1), iy1 = fmaxf(sy1[i], Y1);
            float ix2 = fminf(sx2[i], X2), iy2 = fminf(sy2[i], Y2);
            float inter = fmaxf(ix2 - ix1, 0.f) * fmaxf(iy2 - iy1, 0.f);
            float iou = inter / (sar[i] + AR - inter + 1e-6f);
            if (iou > 0.7f) ss[i] = -INFINITY;
        }
        __syncthreads();
    }
}

// ---------------------------------------------------------------------------
// ROI Align on feats[0] (256, 200, 200), scale 0.25, POOL 7.
// ---------------------------------------------------------------------------
__global__ void roi_align_kernel(const float* __restrict__ feat, const float* __restrict__ rois,
                                 float* __restrict__ out) {
    __shared__ int six0[49], siy0[49], six1[49], siy1[49];
    __shared__ float swx[49], swy[49];
    int roi = blockIdx.x;
    int c = threadIdx.x;
    if (threadIdx.x < 49) {
        int p = threadIdx.x;
        int py = p / 7, px = p % 7;
        float r0 = rois[roi * 4 + 0] * 0.25f;
        float r1 = rois[roi * 4 + 1] * 0.25f;
        float bw = (rois[roi * 4 + 2] - rois[roi * 4 + 0]) * 0.25f / 7.0f;
        float bh = (rois[roi * 4 + 3] - rois[roi * 4 + 1]) * 0.25f / 7.0f;
        float gx = r0 + (px + 0.5f) * bw - 0.5f;
        float gy = r1 + (py + 0.5f) * bh - 0.5f;
        float fx = fminf(fmaxf(floorf(gx), 0.f), 199.f);
        float fy = fminf(fmaxf(floorf(gy), 0.f), 199.f);
        int x0 = (int)fx, y0 = (int)fy;
        six0[p] = x0; siy0[p] = y0;
        six1[p] = min(x0 + 1, 199);
        siy1[p] = min(y0 + 1, 199);
        swx[p] = fminf(fmaxf(gx - fx, 0.f), 1.f);
        swy[p] = fminf(fmaxf(gy - fy, 0.f), 1.f);
    }
    __syncthreads();
    const float* f = feat + (size_t)c * 40000;
    float* o = out + (size_t)roi * 12544 + (size_t)c * 49;
#pragma unroll 7
    for (int p = 0; p < 49; p++) {
        int x0 = six0[p], y0 = siy0[p], x1 = six1[p], y1 = siy1[p];
        float wx = swx[p], wy = swy[p];
        float v00 = f[y0 * 200 + x0];
        float v01 = f[y0 * 200 + x1];
        float v10 = f[y1 * 200 + x0];
        float v11 = f[y1 * 200 + x1];
        o[p] = v00 * (1.f - wy) * (1.f - wx) + v01 * (1.f - wy) * wx +
               v10 * wy * (1.f - wx) + v11 * wy * wx;
    }
}

// ---------------------------------------------------------------------------
// SGEMM v2: C = relu(A @ B + bias). f32x2 over N-column pairs.
// BM=BN=64, BK=16, 256 threads, 4 rows x 4 cols (2 pairs) per thread.
// ---------------------------------------------------------------------------
__global__ void sgemm_bias_relu(const float* __restrict__ A, const float* __restrict__ B,
                                const float* __restrict__ bias, float* __restrict__ C,
                                int M, int N, int K, int do_relu) {
    constexpr int BM = 64, BN = 64, BK = 16;
    __shared__ float sA[BK][BM + 1];
    __shared__ __align__(16) float sB[BK][BN + 2];
    int tid = threadIdx.x;
    int trow = tid / 16, tcol = tid % 16;
    int bm0 = blockIdx.y * BM, bn0 = blockIdx.x * BN;
    unsigned long long acc2[4][2];
#pragma unroll
    for (int i = 0; i < 4; i++) { acc2[i][0] = 0ull; acc2[i][1] = 0ull; }

    for (int k0 = 0; k0 < K; k0 += BK) {
#pragma unroll
        for (int l = 0; l < 4; l++) {
            int e = tid + l * 256;
            int ar = e / BK, ac = e % BK;
            sA[ac][ar] = A[(size_t)(bm0 + ar) * K + k0 + ac];
        }
#pragma unroll
        for (int l = 0; l < 4; l++) {
            int e = tid + l * 256;
            int br = e >> 6, bc = e & 63;
            sB[br][bc] = B[(size_t)(k0 + br) * N + bn0 + bc];
        }
        __syncthreads();
#pragma unroll
        for (int kk = 0; kk < BK; kk++) {
            unsigned long long b0 = *(const unsigned long long*)&sB[kk][tcol * 4];
            unsigned long long b1 = *(const unsigned long long*)&sB[kk][tcol * 4 + 2];
#pragma unroll
            for (int i = 0; i < 4; i++) {
                unsigned long long vv = dup2(sA[kk][trow * 4 + i]);
                ffma2(acc2[i][0], vv, b0);
                ffma2(acc2[i][1], vv, b1);
            }
        }
        __syncthreads();
    }
#pragma unroll
    for (int i = 0; i < 4; i++) {
        int r = bm0 + trow * 4 + i;
#pragma unroll
        for (int jp = 0; jp < 2; jp++) {
            int cidx = bn0 + tcol * 4 + 2 * jp;
            float2 f = unpack2(acc2[i][jp]);
            f.x += bias[cidx];
            f.y += bias[cidx + 1];
            if (do_relu) { f.x = fmaxf(f.x, 0.f); f.y = fmaxf(f.y, 0.f); }
            C[(size_t)r * N + cidx] = f.x;
            C[(size_t)r * N + cidx + 1] = f.y;
        }
    }
}

// ---------------------------------------------------------------------------
// Final heads: cls (1024->2) and breg (1024->8), write directly to d_out.
// ---------------------------------------------------------------------------
__global__ void head_kernel(const float* __restrict__ A, const float* __restrict__ cw,
                            const float* __restrict__ cb, const float* __restrict__ bw,
                            const float* __restrict__ bb, float* __restrict__ out) {
    int m = blockIdx.x;
    int j = threadIdx.x;
    if (j >= 10) return;
    const float* a = A + (size_t)m * 1024;
    bool is_cls = (j < 2);
    const float* W = is_cls ? cw : bw;
    int n = is_cls ? j : j - 2;
    int N = is_cls ? 2 : 8;
    float acc = 0.f;
    for (int k = 0; k < 1024; k++) acc += a[k] * W[(size_t)k * N + n];
    acc += is_cls ? cb[n] : bb[n];
    if (is_cls) out[m * 2 + n] = acc;
    else out[1024 + m * 8 + n] = acc;
}

// ---------------------------------------------------------------------------
// Host: launch sequence
// ---------------------------------------------------------------------------
static inline void* symaddr(const void* sym) {
    void* p = nullptr;
    cudaGetSymbolAddress(&p, sym);
    return p;
}

static inline int ceil_div(int a, int b) { return (a + b - 1) / b; }

extern "C" void kernel_launch(void* const* d_in, const int* in_sizes, int n_in,
                              void* d_out, int out_size) {
    const float* x       = (const float*)d_in[0];
    const float* stem_w  = (const float*)d_in[1];
    const float* c2_w    = (const float*)d_in[2];
    const float* c3_w    = (const float*)d_in[3];
    const float* c4_w    = (const float*)d_in[4];
    const float* c5_w    = (const float*)d_in[5];
    const float* fpn_w[4] = {(const float*)d_in[6], (const float*)d_in[7],
                             (const float*)d_in[8], (const float*)d_in[9]};
    const float* rpn_w     = (const float*)d_in[10];
    const float* rpn_cls_w = (const float*)d_in[11];
    const float* rpn_box_w = (const float*)d_in[12];
    const float* fc1_w = (const float*)d_in[13];
    const float* fc1_b = (const float*)d_in[14];
    const float* fc2_w = (const float*)d_in[15];
    const float* fc2_b = (const float*)d_in[16];
    const float* cls_w = (const float*)d_in[17];
    const float* cls_b = (const float*)d_in[18];
    const float* breg_w = (const float*)d_in[19];
    const float* breg_b = (const float*)d_in[20];
    float* out = (float*)d_out;

    float* p_stem = (float*)symaddr(g_stem);
    float* p_c2   = (float*)symaddr(g_c2);
    float* p_c3   = (float*)symaddr(g_c3);
    float* p_c4   = (float*)symaddr(g_c4);
    float* p_c5   = (float*)symaddr(g_c5);
    float* p_f[4] = {(float*)symaddr(g_f2), (float*)symaddr(g_f3),
                     (float*)symaddr(g_f4), (float*)symaddr(g_f5)};
    float* p_t    = (float*)symaddr(g_t);
    float* p_cls  = (float*)symaddr(g_cls);
    float* p_box  = (float*)symaddr(g_box);
    float* p_decb = (float*)symaddr(g_decb);
    float* p_decs = (float*)symaddr(g_decs);
    float* p_b4k  = (float*)symaddr(g_boxes4k);
    float* p_s4k  = (float*)symaddr(g_scores4k);
    float* p_props = (float*)symaddr(g_props);
    float* p_pool = (float*)symaddr(g_pooled);
    float* p_fc1  = (float*)symaddr(g_fc1);
    float* p_fc2  = (float*)symaddr(g_fc2);

    // 1. stem 7x7 s2 with fused normalize
    stem_v2<<<dim3(13, 50, 4), 128>>>(x, stem_w, p_stem);

    // 2. backbone strided 3x3 convs (relu)
    conv3x3_v2<2, 0><<<dim3(ceil_div(200, 32), ceil_div(200, 16), 32), 128>>>(
        p_stem, c2_w, p_c2, 64, 400, 400, 200, 200, 1);
    conv3x3_v2<2, 0><<<dim3(ceil_div(100, 32), ceil_div(100, 16), 32), 128>>>(
        p_c2, c3_w, p_c3, 256, 200, 200, 100, 100, 1);
    conv3x3_v2<2, 0><<<dim3(ceil_div(50, 32), ceil_div(50, 16), 32), 128>>>(
        p_c3, c4_w, p_c4, 256, 100, 100, 50, 50, 1);
    conv3x3_v2<2, 0><<<dim3(ceil_div(25, 32), ceil_div(25, 16), 32), 128>>>(
        p_c4, c5_w, p_c5, 256, 50, 50, 25, 25, 1);

    // 3. FPN lateral convs (no relu)
    const float* csrc[4] = {p_c2, p_c3, p_c4, p_c5};
    const int fh[4] = {200, 100, 50, 25};
    for (int l = 0; l < 4; l++) {
        conv3x3_v2<1, 1><<<dim3(ceil_div(fh[l], 32), ceil_div(fh[l], 16), 32), 128>>>(
            csrc[l], fpn_w[l], p_f[l], 256, fh[l], fh[l], fh[l], fh[l], 0);
    }

    // 4. RPN per level: conv-relu, 1x1 heads, decode, top-1000
    const float strides[4] = {4.f, 8.f, 16.f, 32.f};
    const float sizes[4] = {32.f, 64.f, 128.f, 256.f};
    for (int l = 0; l < 4; l++) {
        int H = fh[l], HW = H * H;
        conv3x3_v2<1, 1><<<dim3(ceil_div(H, 32), ceil_div(H, 16), 32), 128>>>(
            p_f[l], rpn_w, p_t, 256, H, H, H, H, 1);
        conv1x1_kernel<<<(3 * HW + 255) / 256, 256>>>(p_t, rpn_cls_w, p_cls, 256, 3, HW);
        conv1x1_kernel<<<(12 * HW + 255) / 256, 256>>>(p_t, rpn_box_w, p_box, 256, 12, HW);
        int n = 3 * HW;
        decode_kernel<<<(n + 255) / 256, 256>>>(p_cls, p_box, H, H, strides[l], sizes[l],
                                                p_decb, p_decs);
        topk_kernel<<<1, 1024>>>(p_decs, p_decb, n, 1000, p_s4k + l * 1000,
                                 p_b4k + l * 4000);
    }

    // 5. NMS (512 out of 4000)
    cudaFuncSetAttribute(nms_kernel, cudaFuncAttributeMaxDynamicSharedMemorySize, 96000);
    nms_kernel<<<1, 512, 96000>>>(p_b4k, p_s4k, p_props, out + 5120, out + 7168);

    // 6. ROI align on feats[0]
    roi_align_kernel<<<512, 256>>>(p_f[0], p_props, p_pool);

    // 7. FC head
    sgemm_bias_relu<<<dim3(1024 / 64, 512 / 64), 256>>>(p_pool, fc1_w, fc1_b, p_fc1,
                                                        512, 1024, 12544, 1);
    sgemm_bias_relu<<<dim3(1024 / 64, 512 / 64), 256>>>(p_fc1, fc2_w, fc2_b, p_fc2,
                                                        512, 1024, 1024, 1);
    head_kernel<<<512, 32>>>(p_fc2, cls_w, cls_b, breg_w, breg_b, out);
}

// round 8
// speedup vs baseline: 1.8989x; 1.5940x over previous
#include <cuda_runtime.h>
#include <cuda_bf16.h>
#include <math.h>

// ---------------------------------------------------------------------------
// Static scratch (allocation-free rule: __device__ globals)
// ---------------------------------------------------------------------------
__device__ float g_stem[64 * 400 * 400];
__device__ float g_c2[256 * 200 * 200];
__device__ float g_c3[256 * 100 * 100];
__device__ float g_c4[256 * 50 * 50];
__device__ float g_c5[256 * 25 * 25];
__device__ float g_f2[256 * 200 * 200];
__device__ float g_f3[256 * 100 * 100];
__device__ float g_f4[256 * 50 * 50];
__device__ float g_f5[256 * 25 * 25];
__device__ float g_t[256 * 200 * 200];      // RPN hidden, reused per level
__device__ float g_part[4 * 256 * 100 * 100]; // k-split partials (reused per conv)
__device__ float g_cls[3 * 200 * 200];      // reused per level
__device__ float g_box[12 * 200 * 200];     // reused per level
__device__ float g_decb[120000 * 4];        // reused per level
__device__ float g_decs[120000];            // reused per level
__device__ float g_boxes4k[4000 * 4];
__device__ float g_scores4k[4000];
__device__ float g_props[512 * 4];
__device__ float g_pooled[512 * 12544];
__device__ float g_fc1[512 * 1024];
__device__ float g_fc2[512 * 1024];

__constant__ float c_mean[3] = {0.485f, 0.456f, 0.406f};
__constant__ float c_std[3]  = {0.229f, 0.224f, 0.225f};

// ---------------------------------------------------------------------------
// Packed f32x2 helpers (Blackwell FFMA2 — ptxas never auto-generates this)
// ---------------------------------------------------------------------------
__device__ __forceinline__ void ffma2(unsigned long long& d, unsigned long long a,
                                      unsigned long long b) {
    asm("fma.rn.f32x2 %0, %1, %2, %0;" : "+l"(d) : "l"(a), "l"(b));
}
__device__ __forceinline__ unsigned long long dup2(float v) {
    unsigned long long r;
    unsigned u = __float_as_uint(v);
    asm("mov.b64 %0, {%1, %1};" : "=l"(r) : "r"(u));
    return r;
}
__device__ __forceinline__ float2 unpack2(unsigned long long v) {
    unsigned lo, hi;
    asm("mov.b64 {%0, %1}, %2;" : "=r"(lo), "=r"(hi) : "l"(v));
    float2 f;
    f.x = __uint_as_float(lo);
    f.y = __uint_as_float(hi);
    return f;
}

// ---------------------------------------------------------------------------
// Stem conv 7x7 s2 (800->400, Cin=3, Cout=64) with fused normalize.
// Tile 32x8 out, 16 oc per block, f32x2 over oc pairs. 128 threads.
// ---------------------------------------------------------------------------
__global__ void stem_v2(const float* __restrict__ x, const float* __restrict__ w,
                        float* __restrict__ out) {
    constexpr int IH = 21, IW = 69;  // (8-1)*2+7, (32-1)*2+7
    __shared__ float sIn[3][IH][IW];
    __shared__ __align__(16) float sW[3][49][16];

    const int tid = threadIdx.x;
    const int tx = tid & 31, ty = tid >> 5;  // ty in 0..3, 2 rows each
    const int ox0 = blockIdx.x * 32, oy0 = blockIdx.y * 8, oc0 = blockIdx.z * 16;
    const int ix0 = ox0 * 2 - 2, iy0 = oy0 * 2 - 2;

    // load + normalize input tile
    for (int idx = tid; idx < 3 * IH * IW; idx += 128) {
        int ci = idx / (IH * IW);
        int rem = idx % (IH * IW);
        int r = rem / IW, c = rem % IW;
        int gy = iy0 + r, gx = ix0 + c;
        float v = 0.f;
        if (gy >= 0 && gy < 800 && gx >= 0 && gx < 800)
            v = (x[ci * 640000 + gy * 800 + gx] - c_mean[ci]) / c_std[ci];
        sIn[ci][r][c] = v;
    }
    // load weights [oc][ci][49] -> sW[ci][tap][oc]
    for (int idx = tid; idx < 3 * 49 * 16; idx += 128) {
        int j = idx & 15;
        int t = (idx >> 4) % 49;
        int ci = idx / (49 * 16);
        sW[ci][t][j] = w[(oc0 + j) * 147 + ci * 49 + t];
    }
    __syncthreads();

    unsigned long long acc[2][8];
#pragma unroll
    for (int r = 0; r < 2; r++)
#pragma unroll
        for (int jp = 0; jp < 8; jp++) acc[r][jp] = 0ull;

#pragma unroll 1
    for (int ci = 0; ci < 3; ci++) {
#pragma unroll 1
        for (int ky = 0; ky < 7; ky++) {
#pragma unroll
            for (int kx = 0; kx < 7; kx++) {
                int t = ky * 7 + kx;
                unsigned long long wv[8];
#pragma unroll
                for (int jp = 0; jp < 8; jp++)
                    wv[jp] = *(const unsigned long long*)&sW[ci][t][2 * jp];
#pragma unroll
                for (int r = 0; r < 2; r++) {
                    float v = sIn[ci][(ty * 2 + r) * 2 + ky][tx * 2 + kx];
                    unsigned long long vv = dup2(v);
#pragma unroll
                    for (int jp = 0; jp < 8; jp++) ffma2(acc[r][jp], vv, wv[jp]);
                }
            }
        }
    }

    int xo = ox0 + tx;
    if (xo < 400) {
#pragma unroll
        for (int r = 0; r < 2; r++) {
            int yo = oy0 + ty * 2 + r;
#pragma unroll
            for (int jp = 0; jp < 8; jp++) {
                float2 f = unpack2(acc[r][jp]);
                out[(size_t)(oc0 + 2 * jp) * 160000 + yo * 400 + xo] = fmaxf(f.x, 0.f);
                out[(size_t)(oc0 + 2 * jp + 1) * 160000 + yo * 400 + xo] = fmaxf(f.y, 0.f);
            }
        }
    }
}

// ---------------------------------------------------------------------------
// 3x3 conv v3: tile 32x16 out, 16 oc/block, 256 threads, 2 px x 16 oc per
// thread (f32x2 over oc pairs). 2-stage smem pipeline (prefetch next Cin to
// regs during compute). Optional Cin-split: split s writes partials to
// out[s*Cout*HW + ...]; a deterministic reduce kernel sums them.
// ---------------------------------------------------------------------------
template <int S, int PADLO>
__global__ void __launch_bounds__(256, 2)
conv3x3_v3(const float* __restrict__ in, const float* __restrict__ w,
           float* __restrict__ out, int Cin, int Hin, int Win,
           int Hout, int Wout, int do_relu, int nsplit, int nOcG, int Cout) {
    constexpr int TW = 32, TH = 16, OCB = 16;
    constexpr int IW = (TW - 1) * S + 3;
    constexpr int IH = (TH - 1) * S + 3;
    constexpr int NPIX = IH * IW;
    constexpr int NLD = (NPIX + 255) / 256;
    __shared__ float sIn[2][NPIX];
    __shared__ __align__(16) float sW[2][9][OCB];

    const int tid = threadIdx.x;
    const int tx = tid & 31, ty = tid >> 5;  // ty 0..7, 2 rows each
    const int ocg = blockIdx.z % nOcG, split = blockIdx.z / nOcG;
    const int oc0 = ocg * OCB;
    const int cs = Cin / nsplit;
    const int ci0 = split * cs;
    const int ox0 = blockIdx.x * TW, oy0 = blockIdx.y * TH;
    const int ix0 = ox0 * S - PADLO, iy0 = oy0 * S - PADLO;
    const bool interior =
        (ix0 >= 0) && (iy0 >= 0) && (ix0 + IW <= Win) && (iy0 + IH <= Hin);

    float rbuf[NLD];
    float wreg = 0.f;
    const int wj = tid & 15, wt = tid >> 4;  // valid when tid < 144

    auto fetch = [&](int ci) {
        const float* inp = in + (size_t)ci * Hin * Win;
        if (interior) {
#pragma unroll
            for (int l = 0; l < NLD; l++) {
                int idx = tid + l * 256;
                if (idx < NPIX) {
                    int r = idx / IW, c = idx % IW;
                    rbuf[l] = __ldg(&inp[(iy0 + r) * Win + ix0 + c]);
                }
            }
        } else {
#pragma unroll
            for (int l = 0; l < NLD; l++) {
                int idx = tid + l * 256;
                if (idx < NPIX) {
                    int r = idx / IW, c = idx % IW;
                    int gy = iy0 + r, gx = ix0 + c;
                    float v = 0.f;
                    if (gy >= 0 && gy < Hin && gx >= 0 && gx < Win)
                        v = inp[gy * Win + gx];
                    rbuf[l] = v;
                }
            }
        }
        if (tid < 144) wreg = w[((size_t)(oc0 + wj) * Cin + ci) * 9 + wt];
    };
    auto sts = [&](int b) {
#pragma unroll
        for (int l = 0; l < NLD; l++) {
            int idx = tid + l * 256;
            if (idx < NPIX) sIn[b][idx] = rbuf[l];
        }
        if (tid < 144) sW[b][wt][wj] = wreg;
    };

    unsigned long long acc[2][8];
#pragma unroll
    for (int r = 0; r < 2; r++)
#pragma unroll
        for (int jp = 0; jp < 8; jp++) acc[r][jp] = 0ull;

    fetch(ci0);
    sts(0);
    __syncthreads();

    for (int i = 0; i < cs; i++) {
        const int b = i & 1;
        const bool more = (i + 1 < cs);
        if (more) fetch(ci0 + i + 1);

#pragma unroll
        for (int ky = 0; ky < 3; ky++) {
#pragma unroll
            for (int kx = 0; kx < 3; kx++) {
                const int t = ky * 3 + kx;
                const unsigned long long* wp =
                    (const unsigned long long*)&sW[b][t][0];
                unsigned long long wv0 = wp[0], wv1 = wp[1], wv2 = wp[2],
                                  wv3 = wp[3], wv4 = wp[4], wv5 = wp[5],
                                  wv6 = wp[6], wv7 = wp[7];
#pragma unroll
                for (int rr = 0; rr < 2; rr++) {
                    float v = sIn[b][((ty * 2 + rr) * S + ky) * IW + tx * S + kx];
                    unsigned long long vv = dup2(v);
                    ffma2(acc[rr][0], vv, wv0);
                    ffma2(acc[rr][1], vv, wv1);
                    ffma2(acc[rr][2], vv, wv2);
                    ffma2(acc[rr][3], vv, wv3);
                    ffma2(acc[rr][4], vv, wv4);
                    ffma2(acc[rr][5], vv, wv5);
                    ffma2(acc[rr][6], vv, wv6);
                    ffma2(acc[rr][7], vv, wv7);
                }
            }
        }
        if (more) {
            sts(b ^ 1);
            __syncthreads();
        }
    }

    const int xo = ox0 + tx;
    if (xo < Wout) {
#pragma unroll
        for (int rr = 0; rr < 2; rr++) {
            int yo = oy0 + ty * 2 + rr;
            if (yo < Hout) {
#pragma unroll
                for (int jp = 0; jp < 8; jp++) {
                    float2 f = unpack2(acc[rr][jp]);
                    if (nsplit == 1) {
                        if (do_relu) {
                            f.x = fmaxf(f.x, 0.f);
                            f.y = fmaxf(f.y, 0.f);
                        }
                        out[((size_t)(oc0 + 2 * jp) * Hout + yo) * Wout + xo] = f.x;
                        out[((size_t)(oc0 + 2 * jp + 1) * Hout + yo) * Wout + xo] = f.y;
                    } else {
                        size_t base = (size_t)split * Cout;
                        out[((base + oc0 + 2 * jp) * Hout + yo) * Wout + xo] = f.x;
                        out[((base + oc0 + 2 * jp + 1) * Hout + yo) * Wout + xo] = f.y;
                    }
                }
            }
        }
    }
}

// Deterministic fixed-order reduction over Cin-splits (+ optional relu).
__global__ void reduce_split_kernel(const float* __restrict__ part,
                                    float* __restrict__ out, int n, int nsplit,
                                    int do_relu) {
    int i = blockIdx.x * blockDim.x + threadIdx.x;
    if (i >= n) return;
    float acc = 0.f;
    for (int s = 0; s < nsplit; s++) acc += part[(size_t)s * n + i];
    if (do_relu) acc = fmaxf(acc, 0.f);
    out[i] = acc;
}

// ---------------------------------------------------------------------------
// 1x1 conv (no bias, no relu)
// ---------------------------------------------------------------------------
__global__ void conv1x1_kernel(const float* __restrict__ in, const float* __restrict__ w,
                               float* __restrict__ out, int Cin, int Cout, int HW) {
    int idx = blockIdx.x * blockDim.x + threadIdx.x;
    if (idx >= Cout * HW) return;
    int p = idx % HW;
    int oc = idx / HW;
    float acc = 0.f;
    const float* wp = w + (size_t)oc * Cin;
    for (int ci = 0; ci < Cin; ci++) acc += in[(size_t)ci * HW + p] * wp[ci];
    out[idx] = acc;
}

// ---------------------------------------------------------------------------
// Anchor decode
// ---------------------------------------------------------------------------
__global__ void decode_kernel(const float* __restrict__ cls, const float* __restrict__ box,
                              int fh, int fw, float stride, float size,
                              float* __restrict__ dec_boxes, float* __restrict__ dec_scores) {
    int n = fh * fw * 3;
    int i = blockIdx.x * blockDim.x + threadIdx.x;
    if (i >= n) return;
    int a = i % 3;
    int rest = i / 3;
    int x = rest % fw;
    int y = rest / fw;

    const double wm[3] = {1.4142135623730951, 1.0, 0.7071067811865476};
    const double hm[3] = {0.7071067811865476, 1.0, 1.4142135623730951};
    float aw = (float)(size * wm[a]);
    float ah = (float)(size * hm[a]);
    float acx = (x + 0.5f) * stride;
    float acy = (y + 0.5f) * stride;

    int HW = fh * fw;
    int p = y * fw + x;
    float d0 = box[(a * 4 + 0) * HW + p];
    float d1 = box[(a * 4 + 1) * HW + p];
    float d2 = box[(a * 4 + 2) * HW + p];
    float d3 = box[(a * 4 + 3) * HW + p];
    float dw = fminf(fmaxf(d2, -4.f), 4.f);
    float dh = fminf(fmaxf(d3, -4.f), 4.f);
    float cx = acx + d0 * aw;
    float cy = acy + d1 * ah;
    float w = aw * expf(dw);
    float h = ah * expf(dh);
    float x1 = fminf(fmaxf(cx - w * 0.5f, 0.f), 800.f);
    float y1 = fminf(fmaxf(cy - h * 0.5f, 0.f), 800.f);
    float x2 = fminf(fmaxf(cx + w * 0.5f, 0.f), 800.f);
    float y2 = fminf(fmaxf(cy + h * 0.5f, 0.f), 800.f);
    dec_boxes[i * 4 + 0] = x1;
    dec_boxes[i * 4 + 1] = y1;
    dec_boxes[i * 4 + 2] = x2;
    dec_boxes[i * 4 + 3] = y2;
    dec_scores[i] = cls[a * HW + p];
}

// ---------------------------------------------------------------------------
// Top-k (k = 1000) per level via 4-pass radix select. One block.
// ---------------------------------------------------------------------------
__device__ __forceinline__ unsigned keyof(float f) {
    unsigned u = __float_as_uint(f);
    return (u & 0x80000000u) ? ~u : (u | 0x80000000u);
}

__global__ void topk_kernel(const float* __restrict__ scores, const float* __restrict__ boxes,
                            int n, int k,
                            float* __restrict__ out_scores, float* __restrict__ out_boxes) {
    __shared__ unsigned hist[256];
    __shared__ unsigned sh_prefix, sh_kk, sh_cgt, sh_ceq;
    int tid = threadIdx.x;
    int NT = blockDim.x;
    if (tid == 0) { sh_prefix = 0; sh_kk = (unsigned)k; }
    unsigned mask = 0;
    __syncthreads();
    for (int shift = 24; shift >= 0; shift -= 8) {
        for (int b = tid; b < 256; b += NT) hist[b] = 0;
        __syncthreads();
        unsigned prefix = sh_prefix;
        for (int i = tid; i < n; i += NT) {
            unsigned key = keyof(scores[i]);
            if ((key & mask) == prefix) atomicAdd(&hist[(key >> shift) & 255], 1u);
        }
        __syncthreads();
        if (tid == 0) {
            unsigned kk = sh_kk, cum = 0;
            int b = 255;
            for (; b > 0; b--) {
                if (cum + hist[b] >= kk) break;
                cum += hist[b];
            }
            sh_prefix = prefix | ((unsigned)b << shift);
            sh_kk = kk - cum;
        }
        mask |= (0xFFu << shift);
        __syncthreads();
    }
    unsigned T = sh_prefix;
    unsigned kk = sh_kk;
    if (tid == 0) { sh_cgt = 0; sh_ceq = 0; }
    __syncthreads();
    int gtcount = k - (int)kk;
    for (int i = tid; i < n; i += NT) {
        unsigned key = keyof(scores[i]);
        int slot = -1;
        if (key > T) {
            slot = (int)atomicAdd(&sh_cgt, 1u);
        } else if (key == T) {
            unsigned e = atomicAdd(&sh_ceq, 1u);
            if (e < kk) slot = gtcount + (int)e;
        }
        if (slot >= 0) {
            out_scores[slot] = scores[i];
            out_boxes[slot * 4 + 0] = boxes[i * 4 + 0];
            out_boxes[slot * 4 + 1] = boxes[i * 4 + 1];
            out_boxes[slot * 4 + 2] = boxes[i * 4 + 2];
            out_boxes[slot * 4 + 3] = boxes[i * 4 + 3];
        }
    }
}

// ---------------------------------------------------------------------------
// NMS: one block, 512 threads, 512 sequential selections over 4000 candidates.
// ---------------------------------------------------------------------------
__global__ void nms_kernel(const float* __restrict__ boxes, const float* __restrict__ scores,
                           float* __restrict__ props, float* __restrict__ out_props,
                           float* __restrict__ out_scores) {
    constexpr int N = 4000, NT = 512, POST = 512;
    extern __shared__ float sm[];
    float* sx1 = sm;
    float* sy1 = sm + N;
    float* sx2 = sm + 2 * N;
    float* sy2 = sm + 3 * N;
    float* sar = sm + 4 * N;
    float* ss  = sm + 5 * N;
    __shared__ float rv[NT / 32];
    __shared__ int ri[NT / 32];
    __shared__ int s_best;

    int tid = threadIdx.x;
    for (int i = tid; i < N; i += NT) {
        float a = boxes[i * 4 + 0], b = boxes[i * 4 + 1];
        float c = boxes[i * 4 + 2], d = boxes[i * 4 + 3];
        sx1[i] = a; sy1[i] = b; sx2[i] = c; sy2[i] = d;
        sar[i] = (c - a) * (d - b);
        ss[i] = scores[i];
    }
    __syncthreads();

    for (int it = 0; it < POST; it++) {
        float bv = -INFINITY;
        int bi = 0x7FFFFFFF;
        for (int i = tid; i < N; i += NT) {
            float v = ss[i];
            if (v > bv || (v == bv && i < bi)) { bv = v; bi = i; }
        }
#pragma unroll
        for (int off = 16; off; off >>= 1) {
            float ov = __shfl_down_sync(0xFFFFFFFFu, bv, off);
            int oi = __shfl_down_sync(0xFFFFFFFFu, bi, off);
            if (ov > bv || (ov == bv && oi < bi)) { bv = ov; bi = oi; }
        }
        if ((tid & 31) == 0) { rv[tid >> 5] = bv; ri[tid >> 5] = bi; }
        __syncthreads();
        if (tid == 0) {
            float fbv = rv[0]; int fbi = ri[0];
            for (int wz = 1; wz < NT / 32; wz++) {
                float ov = rv[wz]; int oi = ri[wz];
                if (ov > fbv || (ov == fbv && oi < fbi)) { fbv = ov; fbi = oi; }
            }
            s_best = fbi;
        }
        __syncthreads();
        int idx = s_best;
        if (tid == 0) {
            float a = sx1[idx], b = sy1[idx], c = sx2[idx], d = sy2[idx];
            props[it * 4 + 0] = a; props[it * 4 + 1] = b;
            props[it * 4 + 2] = c; props[it * 4 + 3] = d;
            out_props[it * 4 + 0] = a; out_props[it * 4 + 1] = b;
            out_props[it * 4 + 2] = c; out_props[it * 4 + 3] = d;
            out_scores[it] = scores[idx];
        }
        float X1 = sx1[idx], Y1 = sy1[idx], X2 = sx2[idx], Y2 = sy2[idx], AR = sar[idx];
        for (int i = tid; i < N; i += NT) {
            float ix1 = fmaxf(sx1[i], X1), iy1 = fmaxf(sy1[i], Y1);
            float ix2 = fminf(sx2[i], X2), iy2 = fminf(sy2[i], Y2);
            float inter = fmaxf(ix2 - ix1, 0.f) * fmaxf(iy2 - iy1, 0.f);
            float iou = inter / (sar[i] + AR - inter + 1e-6f);
            if (iou > 0.7f) ss[i] = -INFINITY;
        }
        __syncthreads();
    }
}

// ---------------------------------------------------------------------------
// ROI Align on feats[0] (256, 200, 200), scale 0.25, POOL 7.
// ---------------------------------------------------------------------------
__global__ void roi_align_kernel(const float* __restrict__ feat, const float* __restrict__ rois,
                                 float* __restrict__ out) {
    __shared__ int six0[49], siy0[49], six1[49], siy1[49];
    __shared__ float swx[49], swy[49];
    int roi = blockIdx.x;
    int c = threadIdx.x;
    if (threadIdx.x < 49) {
        int p = threadIdx.x;
        int py = p / 7, px = p % 7;
        float r0 = rois[roi * 4 + 0] * 0.25f;
        float r1 = rois[roi * 4 + 1] * 0.25f;
        float bw = (rois[roi * 4 + 2] - rois[roi * 4 + 0]) * 0.25f / 7.0f;
        float bh = (rois[roi * 4 + 3] - rois[roi * 4 + 1]) * 0.25f / 7.0f;
        float gx = r0 + (px + 0.5f) * bw - 0.5f;
        float gy = r1 + (py + 0.5f) * bh - 0.5f;
        float fx = fminf(fmaxf(floorf(gx), 0.f), 199.f);
        float fy = fminf(fmaxf(floorf(gy), 0.f), 199.f);
        int x0 = (int)fx, y0 = (int)fy;
        six0[p] = x0; siy0[p] = y0;
        six1[p] = min(x0 + 1, 199);
        siy1[p] = min(y0 + 1, 199);
        swx[p] = fminf(fmaxf(gx - fx, 0.f), 1.f);
        swy[p] = fminf(fmaxf(gy - fy, 0.f), 1.f);
    }
    __syncthreads();
    const float* f = feat + (size_t)c * 40000;
    float* o = out + (size_t)roi * 12544 + (size_t)c * 49;
#pragma unroll 7
    for (int p = 0; p < 49; p++) {
        int x0 = six0[p], y0 = siy0[p], x1 = six1[p], y1 = siy1[p];
        float wx = swx[p], wy = swy[p];
        float v00 = f[y0 * 200 + x0];
        float v01 = f[y0 * 200 + x1];
        float v10 = f[y1 * 200 + x0];
        float v11 = f[y1 * 200 + x1];
        o[p] = v00 * (1.f - wy) * (1.f - wx) + v01 * (1.f - wy) * wx +
               v10 * wy * (1.f - wx) + v11 * wy * wx;
    }
}

// ---------------------------------------------------------------------------
// SGEMM: C = relu(A @ B + bias). f32x2 over N-column pairs.
// BM=BN=64, BK=16, 256 threads, 4 rows x 4 cols (2 pairs) per thread.
// ---------------------------------------------------------------------------
__global__ void sgemm_bias_relu(const float* __restrict__ A, const float* __restrict__ B,
                                const float* __restrict__ bias, float* __restrict__ C,
                                int M, int N, int K, int do_relu) {
    constexpr int BM = 64, BN = 64, BK = 16;
    __shared__ float sA[BK][BM + 1];
    __shared__ __align__(16) float sB[BK][BN + 2];
    int tid = threadIdx.x;
    int trow = tid / 16, tcol = tid % 16;
    int bm0 = blockIdx.y * BM, bn0 = blockIdx.x * BN;
    unsigned long long acc2[4][2];
#pragma unroll
    for (int i = 0; i < 4; i++) { acc2[i][0] = 0ull; acc2[i][1] = 0ull; }

    for (int k0 = 0; k0 < K; k0 += BK) {
#pragma unroll
        for (int l = 0; l < 4; l++) {
            int e = tid + l * 256;
            int ar = e / BK, ac = e % BK;
            sA[ac][ar] = A[(size_t)(bm0 + ar) * K + k0 + ac];
        }
#pragma unroll
        for (int l = 0; l < 4; l++) {
            int e = tid + l * 256;
            int br = e >> 6, bc = e & 63;
            sB[br][bc] = B[(size_t)(k0 + br) * N + bn0 + bc];
        }
        __syncthreads();
#pragma unroll
        for (int kk = 0; kk < BK; kk++) {
            unsigned long long b0 = *(const unsigned long long*)&sB[kk][tcol * 4];
            unsigned long long b1 = *(const unsigned long long*)&sB[kk][tcol * 4 + 2];
#pragma unroll
            for (int i = 0; i < 4; i++) {
                unsigned long long vv = dup2(sA[kk][trow * 4 + i]);
                ffma2(acc2[i][0], vv, b0);
                ffma2(acc2[i][1], vv, b1);
            }
        }
        __syncthreads();
    }
#pragma unroll
    for (int i = 0; i < 4; i++) {
        int r = bm0 + trow * 4 + i;
#pragma unroll
        for (int jp = 0; jp < 2; jp++) {
            int cidx = bn0 + tcol * 4 + 2 * jp;
            float2 f = unpack2(acc2[i][jp]);
            f.x += bias[cidx];
            f.y += bias[cidx + 1];
            if (do_relu) { f.x = fmaxf(f.x, 0.f); f.y = fmaxf(f.y, 0.f); }
            C[(size_t)r * N + cidx] = f.x;
            C[(size_t)r * N + cidx + 1] = f.y;
        }
    }
}

// ---------------------------------------------------------------------------
// Final heads: cls (1024->2) and breg (1024->8), write directly to d_out.
// ---------------------------------------------------------------------------
__global__ void head_kernel(const float* __restrict__ A, const float* __restrict__ cw,
                            const float* __restrict__ cb, const float* __restrict__ bw,
                            const float* __restrict__ bb, float* __restrict__ out) {
    int m = blockIdx.x;
    int j = threadIdx.x;
    if (j >= 10) return;
    const float* a = A + (size_t)m * 1024;
    bool is_cls = (j < 2);
    const float* W = is_cls ? cw : bw;
    int n = is_cls ? j : j - 2;
    int N = is_cls ? 2 : 8;
    float acc = 0.f;
    for (int k = 0; k < 1024; k++) acc += a[k] * W[(size_t)k * N + n];
    acc += is_cls ? cb[n] : bb[n];
    if (is_cls) out[m * 2 + n] = acc;
    else out[1024 + m * 8 + n] = acc;
}

// ---------------------------------------------------------------------------
// Host: launch sequence
// ---------------------------------------------------------------------------
static inline void* symaddr(const void* sym) {
    void* p = nullptr;
    cudaGetSymbolAddress(&p, sym);
    return p;
}

static inline int ceil_div(int a, int b) { return (a + b - 1) / b; }

extern "C" void kernel_launch(void* const* d_in, const int* in_sizes, int n_in,
                              void* d_out, int out_size) {
    const float* x       = (const float*)d_in[0];
    const float* stem_w  = (const float*)d_in[1];
    const float* c2_w    = (const float*)d_in[2];
    const float* c3_w    = (const float*)d_in[3];
    const float* c4_w    = (const float*)d_in[4];
    const float* c5_w    = (const float*)d_in[5];
    const float* fpn_w[4] = {(const float*)d_in[6], (const float*)d_in[7],
                             (const float*)d_in[8], (const float*)d_in[9]};
    const float* rpn_w     = (const float*)d_in[10];
    const float* rpn_cls_w = (const float*)d_in[11];
    const float* rpn_box_w = (const float*)d_in[12];
    const float* fc1_w = (const float*)d_in[13];
    const float* fc1_b = (const float*)d_in[14];
    const float* fc2_w = (const float*)d_in[15];
    const float* fc2_b = (const float*)d_in[16];
    const float* cls_w = (const float*)d_in[17];
    const float* cls_b = (const float*)d_in[18];
    const float* breg_w = (const float*)d_in[19];
    const float* breg_b = (const float*)d_in[20];
    float* out = (float*)d_out;

    float* p_stem = (float*)symaddr(g_stem);
    float* p_c2   = (float*)symaddr(g_c2);
    float* p_c3   = (float*)symaddr(g_c3);
    float* p_c4   = (float*)symaddr(g_c4);
    float* p_c5   = (float*)symaddr(g_c5);
    float* p_f[4] = {(float*)symaddr(g_f2), (float*)symaddr(g_f3),
                     (float*)symaddr(g_f4), (float*)symaddr(g_f5)};
    float* p_t    = (float*)symaddr(g_t);
    float* p_part = (float*)symaddr(g_part);
    float* p_cls  = (float*)symaddr(g_cls);
    float* p_box  = (float*)symaddr(g_box);
    float* p_decb = (float*)symaddr(g_decb);
    float* p_decs = (float*)symaddr(g_decs);
    float* p_b4k  = (float*)symaddr(g_boxes4k);
    float* p_s4k  = (float*)symaddr(g_scores4k);
    float* p_props = (float*)symaddr(g_props);
    float* p_pool = (float*)symaddr(g_pooled);
    float* p_fc1  = (float*)symaddr(g_fc1);
    float* p_fc2  = (float*)symaddr(g_fc2);

    const int fh[4] = {200, 100, 50, 25};
    const int ks[4] = {1, 4, 8, 16};  // Cin-splits per level size

    // 1. stem 7x7 s2 with fused normalize
    stem_v2<<<dim3(13, 50, 4), 128>>>(x, stem_w, p_stem);

    // 2. backbone strided 3x3 convs (relu)
    // c2: 400->200, Cin=64, no split (grid 7x13x16 = 1456 blocks)
    conv3x3_v3<2, 0><<<dim3(7, 13, 16), 256>>>(p_stem, c2_w, p_c2, 64, 400, 400,
                                               200, 200, 1, 1, 16, 256);
    // c3: 200->100, split 4
    conv3x3_v3<2, 0><<<dim3(4, 7, 16 * 4), 256>>>(p_c2, c3_w, p_part, 256, 200, 200,
                                                  100, 100, 1, 4, 16, 256);
    reduce_split_kernel<<<ceil_div(256 * 10000, 256), 256>>>(p_part, p_c3,
                                                             256 * 10000, 4, 1);
    // c4: 100->50, split 8
    conv3x3_v3<2, 0><<<dim3(2, 4, 16 * 8), 256>>>(p_c3, c4_w, p_part, 256, 100, 100,
                                                  50, 50, 1, 8, 16, 256);
    reduce_split_kernel<<<ceil_div(256 * 2500, 256), 256>>>(p_part, p_c4,
                                                            256 * 2500, 8, 1);
    // c5: 50->25, split 16
    conv3x3_v3<2, 0><<<dim3(1, 2, 16 * 16), 256>>>(p_c4, c5_w, p_part, 256, 50, 50,
                                                   25, 25, 1, 16, 16, 256);
    reduce_split_kernel<<<ceil_div(256 * 625, 256), 256>>>(p_part, p_c5,
                                                           256 * 625, 16, 1);

    // 3. FPN lateral convs (no relu)
    const float* csrc[4] = {p_c2, p_c3, p_c4, p_c5};
    for (int l = 0; l < 4; l++) {
        int H = fh[l], HW = H * H;
        int k = ks[l];
        dim3 g(ceil_div(H, 32), ceil_div(H, 16), 16 * k);
        if (k == 1) {
            conv3x3_v3<1, 1><<<g, 256>>>(csrc[l], fpn_w[l], p_f[l], 256, H, H, H, H,
                                         0, 1, 16, 256);
        } else {
            conv3x3_v3<1, 1><<<g, 256>>>(csrc[l], fpn_w[l], p_part, 256, H, H, H, H,
                                         0, k, 16, 256);
            reduce_split_kernel<<<ceil_div(256 * HW, 256), 256>>>(p_part, p_f[l],
                                                                  256 * HW, k, 0);
        }
    }

    // 4. RPN per level: conv-relu, 1x1 heads, decode, top-1000
    const float strides[4] = {4.f, 8.f, 16.f, 32.f};
    const float sizes[4] = {32.f, 64.f, 128.f, 256.f};
    for (int l = 0; l < 4; l++) {
        int H = fh[l], HW = H * H;
        int k = ks[l];
        dim3 g(ceil_div(H, 32), ceil_div(H, 16), 16 * k);
        if (k == 1) {
            conv3x3_v3<1, 1><<<g, 256>>>(p_f[l], rpn_w, p_t, 256, H, H, H, H,
                                         1, 1, 16, 256);
        } else {
            conv3x3_v3<1, 1><<<g, 256>>>(p_f[l], rpn_w, p_part, 256, H, H, H, H,
                                         1, k, 16, 256);
            reduce_split_kernel<<<ceil_div(256 * HW, 256), 256>>>(p_part, p_t,
                                                                  256 * HW, k, 1);
        }
        conv1x1_kernel<<<(3 * HW + 255) / 256, 256>>>(p_t, rpn_cls_w, p_cls, 256, 3, HW);
        conv1x1_kernel<<<(12 * HW + 255) / 256, 256>>>(p_t, rpn_box_w, p_box, 256, 12, HW);
        int n = 3 * HW;
        decode_kernel<<<(n + 255) / 256, 256>>>(p_cls, p_box, H, H, strides[l], sizes[l],
                                                p_decb, p_decs);
        topk_kernel<<<1, 1024>>>(p_decs, p_decb, n, 1000, p_s4k + l * 1000,
                                 p_b4k + l * 4000);
    }

    // 5. NMS (512 out of 4000)
    cudaFuncSetAttribute(nms_kernel, cudaFuncAttributeMaxDynamicSharedMemorySize, 96000);
    nms_kernel<<<1, 512, 96000>>>(p_b4k, p_s4k, p_props, out + 5120, out + 7168);

    // 6. ROI align on feats[0]
    roi_align_kernel<<<512, 256>>>(p_f[0], p_props, p_pool);

    // 7. FC head
    sgemm_bias_relu<<<dim3(1024 / 64, 512 / 64), 256>>>(p_pool, fc1_w, fc1_b, p_fc1,
                                                        512, 1024, 12544, 1);
    sgemm_bias_relu<<<dim3(1024 / 64, 512 / 64), 256>>>(p_fc1, fc2_w, fc2_b, p_fc2,
                                                        512, 1024, 1024, 1);
    head_kernel<<<512, 32>>>(p_fc2, cls_w, cls_b, breg_w, breg_b, out);
}

// round 9
// speedup vs baseline: 1.9266x; 1.0146x over previous
#include <cuda_runtime.h>
#include <cuda_bf16.h>
#include <math.h>

// ---------------------------------------------------------------------------
// Static scratch (allocation-free rule: __device__ globals)
// ---------------------------------------------------------------------------
__device__ float g_stem[64 * 400 * 400];
__device__ float g_c2[256 * 200 * 200];
__device__ float g_c3[256 * 100 * 100];
__device__ float g_c4[256 * 50 * 50];
__device__ float g_c5[256 * 25 * 25];
__device__ float g_f2[256 * 200 * 200];
__device__ float g_f3[256 * 100 * 100];
__device__ float g_f4[256 * 50 * 50];
__device__ float g_f5[256 * 25 * 25];
__device__ float g_t[256 * 200 * 200];        // RPN hidden, reused per level
__device__ float g_part[4 * 256 * 100 * 100]; // k-split partials (reused)
__device__ float g_decb[120000 * 4];          // reused per level
__device__ float g_decs[120000];              // reused per level
__device__ float g_boxes4k[4000 * 4];
__device__ float g_scores4k[4000];
__device__ float g_props[512 * 4];
__device__ float g_pooled[512 * 12544];
__device__ float g_fc1[512 * 1024];
__device__ float g_fc2[512 * 1024];

__constant__ float c_mean[3] = {0.485f, 0.456f, 0.406f};
__constant__ float c_std[3]  = {0.229f, 0.224f, 0.225f};

// ---------------------------------------------------------------------------
// Packed f32x2 helpers (Blackwell FFMA2 — ptxas never auto-generates this)
// ---------------------------------------------------------------------------
__device__ __forceinline__ void ffma2(unsigned long long& d, unsigned long long a,
                                      unsigned long long b) {
    asm("fma.rn.f32x2 %0, %1, %2, %0;" : "+l"(d) : "l"(a), "l"(b));
}
__device__ __forceinline__ unsigned long long dup2(float v) {
    unsigned long long r;
    unsigned u = __float_as_uint(v);
    asm("mov.b64 %0, {%1, %1};" : "=l"(r) : "r"(u));
    return r;
}
__device__ __forceinline__ float2 unpack2(unsigned long long v) {
    unsigned lo, hi;
    asm("mov.b64 {%0, %1}, %2;" : "=r"(lo), "=r"(hi) : "l"(v));
    float2 f;
    f.x = __uint_as_float(lo);
    f.y = __uint_as_float(hi);
    return f;
}

// ---------------------------------------------------------------------------
// Stem conv 7x7 s2 (800->400, Cin=3, Cout=64) with fused normalize.
// ---------------------------------------------------------------------------
__global__ void stem_v2(const float* __restrict__ x, const float* __restrict__ w,
                        float* __restrict__ out) {
    constexpr int IH = 21, IW = 69;
    __shared__ float sIn[3][IH][IW];
    __shared__ __align__(16) float sW[3][49][16];

    const int tid = threadIdx.x;
    const int tx = tid & 31, ty = tid >> 5;
    const int ox0 = blockIdx.x * 32, oy0 = blockIdx.y * 8, oc0 = blockIdx.z * 16;
    const int ix0 = ox0 * 2 - 2, iy0 = oy0 * 2 - 2;

    for (int idx = tid; idx < 3 * IH * IW; idx += 128) {
        int ci = idx / (IH * IW);
        int rem = idx % (IH * IW);
        int r = rem / IW, c = rem % IW;
        int gy = iy0 + r, gx = ix0 + c;
        float v = 0.f;
        if (gy >= 0 && gy < 800 && gx >= 0 && gx < 800)
            v = (x[ci * 640000 + gy * 800 + gx] - c_mean[ci]) / c_std[ci];
        sIn[ci][r][c] = v;
    }
    for (int idx = tid; idx < 3 * 49 * 16; idx += 128) {
        int j = idx & 15;
        int t = (idx >> 4) % 49;
        int ci = idx / (49 * 16);
        sW[ci][t][j] = w[(oc0 + j) * 147 + ci * 49 + t];
    }
    __syncthreads();

    unsigned long long acc[2][8];
#pragma unroll
    for (int r = 0; r < 2; r++)
#pragma unroll
        for (int jp = 0; jp < 8; jp++) acc[r][jp] = 0ull;

#pragma unroll 1
    for (int ci = 0; ci < 3; ci++) {
#pragma unroll 1
        for (int ky = 0; ky < 7; ky++) {
#pragma unroll
            for (int kx = 0; kx < 7; kx++) {
                int t = ky * 7 + kx;
                unsigned long long wv[8];
#pragma unroll
                for (int jp = 0; jp < 8; jp++)
                    wv[jp] = *(const unsigned long long*)&sW[ci][t][2 * jp];
#pragma unroll
                for (int r = 0; r < 2; r++) {
                    float v = sIn[ci][(ty * 2 + r) * 2 + ky][tx * 2 + kx];
                    unsigned long long vv = dup2(v);
#pragma unroll
                    for (int jp = 0; jp < 8; jp++) ffma2(acc[r][jp], vv, wv[jp]);
                }
            }
        }
    }

    int xo = ox0 + tx;
    if (xo < 400) {
#pragma unroll
        for (int r = 0; r < 2; r++) {
            int yo = oy0 + ty * 2 + r;
#pragma unroll
            for (int jp = 0; jp < 8; jp++) {
                float2 f = unpack2(acc[r][jp]);
                out[(size_t)(oc0 + 2 * jp) * 160000 + yo * 400 + xo] = fmaxf(f.x, 0.f);
                out[(size_t)(oc0 + 2 * jp + 1) * 160000 + yo * 400 + xo] = fmaxf(f.y, 0.f);
            }
        }
    }
}

// ---------------------------------------------------------------------------
// 3x3 conv v3 (stride-2 path): tile 32x16 out, 16 oc/block, 256 threads,
// 2 px x 16 oc per thread, 2-stage smem pipeline, optional Cin-split.
// ---------------------------------------------------------------------------
template <int S, int PADLO>
__global__ void __launch_bounds__(256, 2)
conv3x3_v3(const float* __restrict__ in, const float* __restrict__ w,
           float* __restrict__ out, int Cin, int Hin, int Win,
           int Hout, int Wout, int do_relu, int nsplit, int nOcG, int Cout) {
    constexpr int TW = 32, TH = 16, OCB = 16;
    constexpr int IW = (TW - 1) * S + 3;
    constexpr int IH = (TH - 1) * S + 3;
    constexpr int NPIX = IH * IW;
    constexpr int NLD = (NPIX + 255) / 256;
    __shared__ float sIn[2][NPIX];
    __shared__ __align__(16) float sW[2][9][OCB];

    const int tid = threadIdx.x;
    const int tx = tid & 31, ty = tid >> 5;
    const int ocg = blockIdx.z % nOcG, split = blockIdx.z / nOcG;
    const int oc0 = ocg * OCB;
    const int cs = Cin / nsplit;
    const int ci0 = split * cs;
    const int ox0 = blockIdx.x * TW, oy0 = blockIdx.y * TH;
    const int ix0 = ox0 * S - PADLO, iy0 = oy0 * S - PADLO;
    const bool interior =
        (ix0 >= 0) && (iy0 >= 0) && (ix0 + IW <= Win) && (iy0 + IH <= Hin);

    float rbuf[NLD];
    float wreg = 0.f;
    const int wj = tid & 15, wt = tid >> 4;

    auto fetch = [&](int ci) {
        const float* inp = in + (size_t)ci * Hin * Win;
        if (interior) {
#pragma unroll
            for (int l = 0; l < NLD; l++) {
                int idx = tid + l * 256;
                if (idx < NPIX) {
                    int r = idx / IW, c = idx % IW;
                    rbuf[l] = __ldg(&inp[(iy0 + r) * Win + ix0 + c]);
                }
            }
        } else {
#pragma unroll
            for (int l = 0; l < NLD; l++) {
                int idx = tid + l * 256;
                if (idx < NPIX) {
                    int r = idx / IW, c = idx % IW;
                    int gy = iy0 + r, gx = ix0 + c;
                    float v = 0.f;
                    if (gy >= 0 && gy < Hin && gx >= 0 && gx < Win)
                        v = inp[gy * Win + gx];
                    rbuf[l] = v;
                }
            }
        }
        if (tid < 144) wreg = w[((size_t)(oc0 + wj) * Cin + ci) * 9 + wt];
    };
    auto sts = [&](int b) {
#pragma unroll
        for (int l = 0; l < NLD; l++) {
            int idx = tid + l * 256;
            if (idx < NPIX) sIn[b][idx] = rbuf[l];
        }
        if (tid < 144) sW[b][wt][wj] = wreg;
    };

    unsigned long long acc[2][8];
#pragma unroll
    for (int r = 0; r < 2; r++)
#pragma unroll
        for (int jp = 0; jp < 8; jp++) acc[r][jp] = 0ull;

    fetch(ci0);
    sts(0);
    __syncthreads();

    for (int i = 0; i < cs; i++) {
        const int b = i & 1;
        const bool more = (i + 1 < cs);
        if (more) fetch(ci0 + i + 1);

#pragma unroll
        for (int ky = 0; ky < 3; ky++) {
#pragma unroll
            for (int kx = 0; kx < 3; kx++) {
                const int t = ky * 3 + kx;
                const unsigned long long* wp =
                    (const unsigned long long*)&sW[b][t][0];
                unsigned long long wv0 = wp[0], wv1 = wp[1], wv2 = wp[2],
                                  wv3 = wp[3], wv4 = wp[4], wv5 = wp[5],
                                  wv6 = wp[6], wv7 = wp[7];
#pragma unroll
                for (int rr = 0; rr < 2; rr++) {
                    float v = sIn[b][((ty * 2 + rr) * S + ky) * IW + tx * S + kx];
                    unsigned long long vv = dup2(v);
                    ffma2(acc[rr][0], vv, wv0);
                    ffma2(acc[rr][1], vv, wv1);
                    ffma2(acc[rr][2], vv, wv2);
                    ffma2(acc[rr][3], vv, wv3);
                    ffma2(acc[rr][4], vv, wv4);
                    ffma2(acc[rr][5], vv, wv5);
                    ffma2(acc[rr][6], vv, wv6);
                    ffma2(acc[rr][7], vv, wv7);
                }
            }
        }
        if (more) {
            sts(b ^ 1);
            __syncthreads();
        }
    }

    const int xo = ox0 + tx;
    if (xo < Wout) {
#pragma unroll
        for (int rr = 0; rr < 2; rr++) {
            int yo = oy0 + ty * 2 + rr;
            if (yo < Hout) {
#pragma unroll
                for (int jp = 0; jp < 8; jp++) {
                    float2 f = unpack2(acc[rr][jp]);
                    if (nsplit == 1) {
                        if (do_relu) {
                            f.x = fmaxf(f.x, 0.f);
                            f.y = fmaxf(f.y, 0.f);
                        }
                        out[((size_t)(oc0 + 2 * jp) * Hout + yo) * Wout + xo] = f.x;
                        out[((size_t)(oc0 + 2 * jp + 1) * Hout + yo) * Wout + xo] = f.y;
                    } else {
                        size_t base = (size_t)split * Cout;
                        out[((base + oc0 + 2 * jp) * Hout + yo) * Wout + xo] = f.x;
                        out[((base + oc0 + 2 * jp + 1) * Hout + yo) * Wout + xo] = f.y;
                    }
                }
            }
        }
    }
}

// ---------------------------------------------------------------------------
// 3x3 conv v4 (stride-1): tile 32x32 out, 16 oc/block, 256 threads,
// 4 px x 16 oc per thread -> 288 FFMA2 per ci vs ~100 non-fma issues:
// fma-pipe-bound. 2-stage smem pipeline, optional Cin-split.
// ---------------------------------------------------------------------------
__global__ void __launch_bounds__(256, 2)
conv3x3_v4(const float* __restrict__ in, const float* __restrict__ w,
           float* __restrict__ out, int Cin, int Hin, int Win,
           int Hout, int Wout, int do_relu, int nsplit, int nOcG, int Cout) {
    constexpr int TW = 32, TH = 32, OCB = 16;
    constexpr int IW = TW + 2, IH = TH + 2;      // stride 1, pad 1
    constexpr int NPIX = IH * IW;                // 34*34 = 1156
    constexpr int NLD = (NPIX + 255) / 256;      // 5
    __shared__ float sIn[2][NPIX];
    __shared__ __align__(16) float sW[2][9][OCB];

    const int tid = threadIdx.x;
    const int tx = tid & 31, ty = tid >> 5;      // ty 0..7, 4 rows each
    const int ocg = blockIdx.z % nOcG, split = blockIdx.z / nOcG;
    const int oc0 = ocg * OCB;
    const int cs = Cin / nsplit;
    const int ci0 = split * cs;
    const int ox0 = blockIdx.x * TW, oy0 = blockIdx.y * TH;
    const int ix0 = ox0 - 1, iy0 = oy0 - 1;
    const bool interior =
        (ix0 >= 0) && (iy0 >= 0) && (ix0 + IW <= Win) && (iy0 + IH <= Hin);

    float rbuf[NLD];
    float wreg = 0.f;
    const int wj = tid & 15, wt = tid >> 4;

    auto fetch = [&](int ci) {
        const float* inp = in + (size_t)ci * Hin * Win;
        if (interior) {
#pragma unroll
            for (int l = 0; l < NLD; l++) {
                int idx = tid + l * 256;
                if (idx < NPIX) {
                    int r = idx / IW, c = idx % IW;
                    rbuf[l] = __ldg(&inp[(iy0 + r) * Win + ix0 + c]);
                }
            }
        } else {
#pragma unroll
            for (int l = 0; l < NLD; l++) {
                int idx = tid + l * 256;
                if (idx < NPIX) {
                    int r = idx / IW, c = idx % IW;
                    int gy = iy0 + r, gx = ix0 + c;
                    float v = 0.f;
                    if (gy >= 0 && gy < Hin && gx >= 0 && gx < Win)
                        v = inp[gy * Win + gx];
                    rbuf[l] = v;
                }
            }
        }
        if (tid < 144) wreg = w[((size_t)(oc0 + wj) * Cin + ci) * 9 + wt];
    };
    auto sts = [&](int b) {
#pragma unroll
        for (int l = 0; l < NLD; l++) {
            int idx = tid + l * 256;
            if (idx < NPIX) sIn[b][idx] = rbuf[l];
        }
        if (tid < 144) sW[b][wt][wj] = wreg;
    };

    unsigned long long acc[4][8];
#pragma unroll
    for (int r = 0; r < 4; r++)
#pragma unroll
        for (int jp = 0; jp < 8; jp++) acc[r][jp] = 0ull;

    fetch(ci0);
    sts(0);
    __syncthreads();

    for (int i = 0; i < cs; i++) {
        const int b = i & 1;
        const bool more = (i + 1 < cs);
        if (more) fetch(ci0 + i + 1);

#pragma unroll
        for (int ky = 0; ky < 3; ky++) {
#pragma unroll
            for (int kx = 0; kx < 3; kx++) {
                const int t = ky * 3 + kx;
                const unsigned long long* wp =
                    (const unsigned long long*)&sW[b][t][0];
                unsigned long long wv0 = wp[0], wv1 = wp[1], wv2 = wp[2],
                                  wv3 = wp[3], wv4 = wp[4], wv5 = wp[5],
                                  wv6 = wp[6], wv7 = wp[7];
#pragma unroll
                for (int rr = 0; rr < 4; rr++) {
                    float v = sIn[b][(ty * 4 + rr + ky) * IW + tx + kx];
                    unsigned long long vv = dup2(v);
                    ffma2(acc[rr][0], vv, wv0);
                    ffma2(acc[rr][1], vv, wv1);
                    ffma2(acc[rr][2], vv, wv2);
                    ffma2(acc[rr][3], vv, wv3);
                    ffma2(acc[rr][4], vv, wv4);
                    ffma2(acc[rr][5], vv, wv5);
                    ffma2(acc[rr][6], vv, wv6);
                    ffma2(acc[rr][7], vv, wv7);
                }
            }
        }
        if (more) {
            sts(b ^ 1);
            __syncthreads();
        }
    }

    const int xo = ox0 + tx;
    if (xo < Wout) {
#pragma unroll
        for (int rr = 0; rr < 4; rr++) {
            int yo = oy0 + ty * 4 + rr;
            if (yo < Hout) {
#pragma unroll
                for (int jp = 0; jp < 8; jp++) {
                    float2 f = unpack2(acc[rr][jp]);
                    if (nsplit == 1) {
                        if (do_relu) {
                            f.x = fmaxf(f.x, 0.f);
                            f.y = fmaxf(f.y, 0.f);
                        }
                        out[((size_t)(oc0 + 2 * jp) * Hout + yo) * Wout + xo] = f.x;
                        out[((size_t)(oc0 + 2 * jp + 1) * Hout + yo) * Wout + xo] = f.y;
                    } else {
                        size_t base = (size_t)split * Cout;
                        out[((base + oc0 + 2 * jp) * Hout + yo) * Wout + xo] = f.x;
                        out[((base + oc0 + 2 * jp + 1) * Hout + yo) * Wout + xo] = f.y;
                    }
                }
            }
        }
    }
}

// Deterministic fixed-order reduction over Cin-splits (+ optional relu).
__global__ void reduce_split_kernel(const float* __restrict__ part,
                                    float* __restrict__ out, int n, int nsplit,
                                    int do_relu) {
    int i = blockIdx.x * blockDim.x + threadIdx.x;
    if (i >= n) return;
    float acc = 0.f;
    for (int s = 0; s < nsplit; s++) acc += part[(size_t)s * n + i];
    if (do_relu) acc = fmaxf(acc, 0.f);
    out[i] = acc;
}

// ---------------------------------------------------------------------------
// Fused RPN head: 1x1 cls (3) + 1x1 box (12) + anchor decode, one thread per
// spatial position. Weights staged in smem; input read once (coalesced).
// FFMA order per output identical to the old conv1x1 (ci ascending).
// ---------------------------------------------------------------------------
__global__ void rpn_head_kernel(const float* __restrict__ t,
                                const float* __restrict__ cls_w,
                                const float* __restrict__ box_w,
                                int HW, int fw, float stride, float size,
                                float* __restrict__ dec_boxes,
                                float* __restrict__ dec_scores) {
    __shared__ float sCW[3][256];
    __shared__ float sBW[12][256];
    const int tid = threadIdx.x;
    for (int idx = tid; idx < 3 * 256; idx += 256) sCW[idx >> 8][idx & 255] = cls_w[idx];
    for (int idx = tid; idx < 12 * 256; idx += 256) sBW[idx >> 8][idx & 255] = box_w[idx];
    __syncthreads();

    const int p = blockIdx.x * 256 + tid;
    if (p >= HW) return;

    float accC[3] = {0.f, 0.f, 0.f};
    float accB[12];
#pragma unroll
    for (int j = 0; j < 12; j++) accB[j] = 0.f;

    for (int ci = 0; ci < 256; ci++) {
        float v = t[(size_t)ci * HW + p];
#pragma unroll
        for (int j = 0; j < 3; j++) accC[j] += v * sCW[j][ci];
#pragma unroll
        for (int j = 0; j < 12; j++) accB[j] += v * sBW[j][ci];
    }

    const int x = p % fw, y = p / fw;
    const double wm[3] = {1.4142135623730951, 1.0, 0.7071067811865476};
    const double hm[3] = {0.7071067811865476, 1.0, 1.4142135623730951};
    float acx = (x + 0.5f) * stride;
    float acy = (y + 0.5f) * stride;

#pragma unroll
    for (int a = 0; a < 3; a++) {
        float aw = (float)(size * wm[a]);
        float ah = (float)(size * hm[a]);
        float d0 = accB[a * 4 + 0];
        float d1 = accB[a * 4 + 1];
        float dw = fminf(fmaxf(accB[a * 4 + 2], -4.f), 4.f);
        float dh = fminf(fmaxf(accB[a * 4 + 3], -4.f), 4.f);
        float cx = acx + d0 * aw;
        float cy = acy + d1 * ah;
        float w = aw * expf(dw);
        float h = ah * expf(dh);
        int i = p * 3 + a;
        dec_boxes[i * 4 + 0] = fminf(fmaxf(cx - w * 0.5f, 0.f), 800.f);
        dec_boxes[i * 4 + 1] = fminf(fmaxf(cy - h * 0.5f, 0.f), 800.f);
        dec_boxes[i * 4 + 2] = fminf(fmaxf(cx + w * 0.5f, 0.f), 800.f);
        dec_boxes[i * 4 + 3] = fminf(fmaxf(cy + h * 0.5f, 0.f), 800.f);
        dec_scores[i] = accC[a];
    }
}

// ---------------------------------------------------------------------------
// Top-k (k = 1000) per level via 4-pass radix select. One block.
// ---------------------------------------------------------------------------
__device__ __forceinline__ unsigned keyof(float f) {
    unsigned u = __float_as_uint(f);
    return (u & 0x80000000u) ? ~u : (u | 0x80000000u);
}

__global__ void topk_kernel(const float* __restrict__ scores, const float* __restrict__ boxes,
                            int n, int k,
                            float* __restrict__ out_scores, float* __restrict__ out_boxes) {
    __shared__ unsigned hist[256];
    __shared__ unsigned sh_prefix, sh_kk, sh_cgt, sh_ceq;
    int tid = threadIdx.x;
    int NT = blockDim.x;
    if (tid == 0) { sh_prefix = 0; sh_kk = (unsigned)k; }
    unsigned mask = 0;
    __syncthreads();
    for (int shift = 24; shift >= 0; shift -= 8) {
        for (int b = tid; b < 256; b += NT) hist[b] = 0;
        __syncthreads();
        unsigned prefix = sh_prefix;
        for (int i = tid; i < n; i += NT) {
            unsigned key = keyof(scores[i]);
            if ((key & mask) == prefix) atomicAdd(&hist[(key >> shift) & 255], 1u);
        }
        __syncthreads();
        if (tid == 0) {
            unsigned kk = sh_kk, cum = 0;
            int b = 255;
            for (; b > 0; b--) {
                if (cum + hist[b] >= kk) break;
                cum += hist[b];
            }
            sh_prefix = prefix | ((unsigned)b << shift);
            sh_kk = kk - cum;
        }
        mask |= (0xFFu << shift);
        __syncthreads();
    }
    unsigned T = sh_prefix;
    unsigned kk = sh_kk;
    if (tid == 0) { sh_cgt = 0; sh_ceq = 0; }
    __syncthreads();
    int gtcount = k - (int)kk;
    for (int i = tid; i < n; i += NT) {
        unsigned key = keyof(scores[i]);
        int slot = -1;
        if (key > T) {
            slot = (int)atomicAdd(&sh_cgt, 1u);
        } else if (key == T) {
            unsigned e = atomicAdd(&sh_ceq, 1u);
            if (e < kk) slot = gtcount + (int)e;
        }
        if (slot >= 0) {
            out_scores[slot] = scores[i];
            out_boxes[slot * 4 + 0] = boxes[i * 4 + 0];
            out_boxes[slot * 4 + 1] = boxes[i * 4 + 1];
            out_boxes[slot * 4 + 2] = boxes[i * 4 + 2];
            out_boxes[slot * 4 + 3] = boxes[i * 4 + 3];
        }
    }
}

// ---------------------------------------------------------------------------
// NMS: one block, 512 threads, 512 sequential selections over 4000 candidates.
// ---------------------------------------------------------------------------
__global__ void nms_kernel(const float* __restrict__ boxes, const float* __restrict__ scores,
                           float* __restrict__ props, float* __restrict__ out_props,
                           float* __restrict__ out_scores) {
    constexpr int N = 4000, NT = 512, POST = 512;
    extern __shared__ float sm[];
    float* sx1 = sm;
    float* sy1 = sm + N;
    float* sx2 = sm + 2 * N;
    float* sy2 = sm + 3 * N;
    float* sar = sm + 4 * N;
    float* ss  = sm + 5 * N;
    __shared__ float rv[NT / 32];
    __shared__ int ri[NT / 32];
    __shared__ int s_best;

    int tid = threadIdx.x;
    for (int i = tid; i < N; i += NT) {
        float a = boxes[i * 4 + 0], b = boxes[i * 4 + 1];
        float c = boxes[i * 4 + 2], d = boxes[i * 4 + 3];
        sx1[i] = a; sy1[i] = b; sx2[i] = c; sy2[i] = d;
        sar[i] = (c - a) * (d - b);
        ss[i] = scores[i];
    }
    __syncthreads();

    for (int it = 0; it < POST; it++) {
        float bv = -INFINITY;
        int bi = 0x7FFFFFFF;
        for (int i = tid; i < N; i += NT) {
            float v = ss[i];
            if (v > bv || (v == bv && i < bi)) { bv = v; bi = i; }
        }
#pragma unroll
        for (int off = 16; off; off >>= 1) {
            float ov = __shfl_down_sync(0xFFFFFFFFu, bv, off);
            int oi = __shfl_down_sync(0xFFFFFFFFu, bi, off);
            if (ov > bv || (ov == bv && oi < bi)) { bv = ov; bi = oi; }
        }
        if ((tid & 31) == 0) { rv[tid >> 5] = bv; ri[tid >> 5] = bi; }
        __syncthreads();
        if (tid == 0) {
            float fbv = rv[0]; int fbi = ri[0];
            for (int wz = 1; wz < NT / 32; wz++) {
                float ov = rv[wz]; int oi = ri[wz];
                if (ov > fbv || (ov == fbv && oi < fbi)) { fbv = ov; fbi = oi; }
            }
            s_best = fbi;
        }
        __syncthreads();
        int idx = s_best;
        if (tid == 0) {
            float a = sx1[idx], b = sy1[idx], c = sx2[idx], d = sy2[idx];
            props[it * 4 + 0] = a; props[it * 4 + 1] = b;
            props[it * 4 + 2] = c; props[it * 4 + 3] = d;
            out_props[it * 4 + 0] = a; out_props[it * 4 + 1] = b;
            out_props[it * 4 + 2] = c; out_props[it * 4 + 3] = d;
            out_scores[it] = scores[idx];
        }
        float X1 = sx1[idx], Y1 = sy1[idx], X2 = sx2[idx], Y2 = sy2[idx], AR = sar[idx];
        for (int i = tid; i < N; i += NT) {
            float ix1 = fmaxf(sx1[i], X1), iy1 = fmaxf(sy1[i], Y1);
            float ix2 = fminf(sx2[i], X2), iy2 = fminf(sy2[i], Y2);
            float inter = fmaxf(ix2 - ix1, 0.f) * fmaxf(iy2 - iy1, 0.f);
            float iou = inter / (sar[i] + AR - inter + 1e-6f);
            if (iou > 0.7f) ss[i] = -INFINITY;
        }
        __syncthreads();
    }
}

// ---------------------------------------------------------------------------
// ROI Align on feats[0] (256, 200, 200), scale 0.25, POOL 7.
// ---------------------------------------------------------------------------
__global__ void roi_align_kernel(const float* __restrict__ feat, const float* __restrict__ rois,
                                 float* __restrict__ out) {
    __shared__ int six0[49], siy0[49], six1[49], siy1[49];
    __shared__ float swx[49], swy[49];
    int roi = blockIdx.x;
    int c = threadIdx.x;
    if (threadIdx.x < 49) {
        int p = threadIdx.x;
        int py = p / 7, px = p % 7;
        float r0 = rois[roi * 4 + 0] * 0.25f;
        float r1 = rois[roi * 4 + 1] * 0.25f;
        float bw = (rois[roi * 4 + 2] - rois[roi * 4 + 0]) * 0.25f / 7.0f;
        float bh = (rois[roi * 4 + 3] - rois[roi * 4 + 1]) * 0.25f / 7.0f;
        float gx = r0 + (px + 0.5f) * bw - 0.5f;
        float gy = r1 + (py + 0.5f) * bh - 0.5f;
        float fx = fminf(fmaxf(floorf(gx), 0.f), 199.f);
        float fy = fminf(fmaxf(floorf(gy), 0.f), 199.f);
        int x0 = (int)fx, y0 = (int)fy;
        six0[p] = x0; siy0[p] = y0;
        six1[p] = min(x0 + 1, 199);
        siy1[p] = min(y0 + 1, 199);
        swx[p] = fminf(fmaxf(gx - fx, 0.f), 1.f);
        swy[p] = fminf(fmaxf(gy - fy, 0.f), 1.f);
    }
    __syncthreads();
    const float* f = feat + (size_t)c * 40000;
    float* o = out + (size_t)roi * 12544 + (size_t)c * 49;
#pragma unroll 7
    for (int p = 0; p < 49; p++) {
        int x0 = six0[p], y0 = siy0[p], x1 = six1[p], y1 = siy1[p];
        float wx = swx[p], wy = swy[p];
        float v00 = f[y0 * 200 + x0];
        float v01 = f[y0 * 200 + x1];
        float v10 = f[y1 * 200 + x0];
        float v11 = f[y1 * 200 + x1];
        o[p] = v00 * (1.f - wy) * (1.f - wx) + v01 * (1.f - wy) * wx +
               v10 * wy * (1.f - wx) + v11 * wy * wx;
    }
}

// ---------------------------------------------------------------------------
// SGEMM: C = relu(A @ B + bias). f32x2 over N-column pairs.
// ---------------------------------------------------------------------------
__global__ void sgemm_bias_relu(const float* __restrict__ A, const float* __restrict__ B,
                                const float* __restrict__ bias, float* __restrict__ C,
                                int M, int N, int K, int do_relu) {
    constexpr int BM = 64, BN = 64, BK = 16;
    __shared__ float sA[BK][BM + 1];
    __shared__ __align__(16) float sB[BK][BN + 2];
    int tid = threadIdx.x;
    int trow = tid / 16, tcol = tid % 16;
    int bm0 = blockIdx.y * BM, bn0 = blockIdx.x * BN;
    unsigned long long acc2[4][2];
#pragma unroll
    for (int i = 0; i < 4; i++) { acc2[i][0] = 0ull; acc2[i][1] = 0ull; }

    for (int k0 = 0; k0 < K; k0 += BK) {
#pragma unroll
        for (int l = 0; l < 4; l++) {
            int e = tid + l * 256;
            int ar = e / BK, ac = e % BK;
            sA[ac][ar] = A[(size_t)(bm0 + ar) * K + k0 + ac];
        }
#pragma unroll
        for (int l = 0; l < 4; l++) {
            int e = tid + l * 256;
            int br = e >> 6, bc = e & 63;
            sB[br][bc] = B[(size_t)(k0 + br) * N + bn0 + bc];
        }
        __syncthreads();
#pragma unroll
        for (int kk = 0; kk < BK; kk++) {
            unsigned long long b0 = *(const unsigned long long*)&sB[kk][tcol * 4];
            unsigned long long b1 = *(const unsigned long long*)&sB[kk][tcol * 4 + 2];
#pragma unroll
            for (int i = 0; i < 4; i++) {
                unsigned long long vv = dup2(sA[kk][trow * 4 + i]);
                ffma2(acc2[i][0], vv, b0);
                ffma2(acc2[i][1], vv, b1);
            }
        }
        __syncthreads();
    }
#pragma unroll
    for (int i = 0; i < 4; i++) {
        int r = bm0 + trow * 4 + i;
#pragma unroll
        for (int jp = 0; jp < 2; jp++) {
            int cidx = bn0 + tcol * 4 + 2 * jp;
            float2 f = unpack2(acc2[i][jp]);
            f.x += bias[cidx];
            f.y += bias[cidx + 1];
            if (do_relu) { f.x = fmaxf(f.x, 0.f); f.y = fmaxf(f.y, 0.f); }
            C[(size_t)r * N + cidx] = f.x;
            C[(size_t)r * N + cidx + 1] = f.y;
        }
    }
}

// ---------------------------------------------------------------------------
// Final heads: cls (1024->2) and breg (1024->8), write directly to d_out.
// ---------------------------------------------------------------------------
__global__ void head_kernel(const float* __restrict__ A, const float* __restrict__ cw,
                            const float* __restrict__ cb, const float* __restrict__ bw,
                            const float* __restrict__ bb, float* __restrict__ out) {
    int m = blockIdx.x;
    int j = threadIdx.x;
    if (j >= 10) return;
    const float* a = A + (size_t)m * 1024;
    bool is_cls = (j < 2);
    const float* W = is_cls ? cw : bw;
    int n = is_cls ? j : j - 2;
    int N = is_cls ? 2 : 8;
    float acc = 0.f;
    for (int k = 0; k < 1024; k++) acc += a[k] * W[(size_t)k * N + n];
    acc += is_cls ? cb[n] : bb[n];
    if (is_cls) out[m * 2 + n] = acc;
    else out[1024 + m * 8 + n] = acc;
}

// ---------------------------------------------------------------------------
// Host: launch sequence
// ---------------------------------------------------------------------------
static inline void* symaddr(const void* sym) {
    void* p = nullptr;
    cudaGetSymbolAddress(&p, sym);
    return p;
}

static inline int ceil_div(int a, int b) { return (a + b - 1) / b; }

extern "C" void kernel_launch(void* const* d_in, const int* in_sizes, int n_in,
                              void* d_out, int out_size) {
    const float* x       = (const float*)d_in[0];
    const float* stem_w  = (const float*)d_in[1];
    const float* c2_w    = (const float*)d_in[2];
    const float* c3_w    = (const float*)d_in[3];
    const float* c4_w    = (const float*)d_in[4];
    const float* c5_w    = (const float*)d_in[5];
    const float* fpn_w[4] = {(const float*)d_in[6], (const float*)d_in[7],
                             (const float*)d_in[8], (const float*)d_in[9]};
    const float* rpn_w     = (const float*)d_in[10];
    const float* rpn_cls_w = (const float*)d_in[11];
    const float* rpn_box_w = (const float*)d_in[12];
    const float* fc1_w = (const float*)d_in[13];
    const float* fc1_b = (const float*)d_in[14];
    const float* fc2_w = (const float*)d_in[15];
    const float* fc2_b = (const float*)d_in[16];
    const float* cls_w = (const float*)d_in[17];
    const float* cls_b = (const float*)d_in[18];
    const float* breg_w = (const float*)d_in[19];
    const float* breg_b = (const float*)d_in[20];
    float* out = (float*)d_out;

    float* p_stem = (float*)symaddr(g_stem);
    float* p_c2   = (float*)symaddr(g_c2);
    float* p_c3   = (float*)symaddr(g_c3);
    float* p_c4   = (float*)symaddr(g_c4);
    float* p_c5   = (float*)symaddr(g_c5);
    float* p_f[4] = {(float*)symaddr(g_f2), (float*)symaddr(g_f3),
                     (float*)symaddr(g_f4), (float*)symaddr(g_f5)};
    float* p_t    = (float*)symaddr(g_t);
    float* p_part = (float*)symaddr(g_part);
    float* p_decb = (float*)symaddr(g_decb);
    float* p_decs = (float*)symaddr(g_decs);
    float* p_b4k  = (float*)symaddr(g_boxes4k);
    float* p_s4k  = (float*)symaddr(g_scores4k);
    float* p_props = (float*)symaddr(g_props);
    float* p_pool = (float*)symaddr(g_pooled);
    float* p_fc1  = (float*)symaddr(g_fc1);
    float* p_fc2  = (float*)symaddr(g_fc2);

    const int fh[4] = {200, 100, 50, 25};
    const int ksv4[4] = {1, 2, 8, 16};  // Cin-splits for stride-1 convs (v4)

    // 1. stem 7x7 s2 with fused normalize
    stem_v2<<<dim3(13, 50, 4), 128>>>(x, stem_w, p_stem);

    // 2. backbone strided 3x3 convs (relu) — v3 path
    conv3x3_v3<2, 0><<<dim3(7, 13, 16), 256>>>(p_stem, c2_w, p_c2, 64, 400, 400,
                                               200, 200, 1, 1, 16, 256);
    conv3x3_v3<2, 0><<<dim3(4, 7, 16 * 4), 256>>>(p_c2, c3_w, p_part, 256, 200, 200,
                                                  100, 100, 1, 4, 16, 256);
    reduce_split_kernel<<<ceil_div(256 * 10000, 256), 256>>>(p_part, p_c3,
                                                             256 * 10000, 4, 1);
    conv3x3_v3<2, 0><<<dim3(2, 4, 16 * 8), 256>>>(p_c3, c4_w, p_part, 256, 100, 100,
                                                  50, 50, 1, 8, 16, 256);
    reduce_split_kernel<<<ceil_div(256 * 2500, 256), 256>>>(p_part, p_c4,
                                                            256 * 2500, 8, 1);
    conv3x3_v3<2, 0><<<dim3(1, 2, 16 * 16), 256>>>(p_c4, c5_w, p_part, 256, 50, 50,
                                                   25, 25, 1, 16, 16, 256);
    reduce_split_kernel<<<ceil_div(256 * 625, 256), 256>>>(p_part, p_c5,
                                                           256 * 625, 16, 1);

    // 3. FPN lateral convs (no relu) — v4 path (stride 1)
    const float* csrc[4] = {p_c2, p_c3, p_c4, p_c5};
    for (int l = 0; l < 4; l++) {
        int H = fh[l], HW = H * H;
        int k = ksv4[l];
        dim3 g(ceil_div(H, 32), ceil_div(H, 32), 16 * k);
        if (k == 1) {
            conv3x3_v4<<<g, 256>>>(csrc[l], fpn_w[l], p_f[l], 256, H, H, H, H,
                                   0, 1, 16, 256);
        } else {
            conv3x3_v4<<<g, 256>>>(csrc[l], fpn_w[l], p_part, 256, H, H, H, H,
                                   0, k, 16, 256);
            reduce_split_kernel<<<ceil_div(256 * HW, 256), 256>>>(p_part, p_f[l],
                                                                  256 * HW, k, 0);
        }
    }

    // 4. RPN per level: conv-relu (v4), fused head+decode, top-1000
    const float strides[4] = {4.f, 8.f, 16.f, 32.f};
    const float sizes[4] = {32.f, 64.f, 128.f, 256.f};
    for (int l = 0; l < 4; l++) {
        int H = fh[l], HW = H * H;
        int k = ksv4[l];
        dim3 g(ceil_div(H, 32), ceil_div(H, 32), 16 * k);
        if (k == 1) {
            conv3x3_v4<<<g, 256>>>(p_f[l], rpn_w, p_t, 256, H, H, H, H,
                                   1, 1, 16, 256);
        } else {
            conv3x3_v4<<<g, 256>>>(p_f[l], rpn_w, p_part, 256, H, H, H, H,
                                   1, k, 16, 256);
            reduce_split_kernel<<<ceil_div(256 * HW, 256), 256>>>(p_part, p_t,
                                                                  256 * HW, k, 1);
        }
        rpn_head_kernel<<<ceil_div(HW, 256), 256>>>(p_t, rpn_cls_w, rpn_box_w,
                                                    HW, H, strides[l], sizes[l],
                                                    p_decb, p_decs);
        topk_kernel<<<1, 1024>>>(p_decs, p_decb, 3 * HW, 1000, p_s4k + l * 1000,
                                 p_b4k + l * 4000);
    }

    // 5. NMS (512 out of 4000)
    cudaFuncSetAttribute(nms_kernel, cudaFuncAttributeMaxDynamicSharedMemorySize, 96000);
    nms_kernel<<<1, 512, 96000>>>(p_b4k, p_s4k, p_props, out + 5120, out + 7168);

    // 6. ROI align on feats[0]
    roi_align_kernel<<<512, 256>>>(p_f[0], p_props, p_pool);

    // 7. FC head
    sgemm_bias_relu<<<dim3(1024 / 64, 512 / 64), 256>>>(p_pool, fc1_w, fc1_b, p_fc1,
                                                        512, 1024, 12544, 1);
    sgemm_bias_relu<<<dim3(1024 / 64, 512 / 64), 256>>>(p_fc1, fc2_w, fc2_b, p_fc2,
                                                        512, 1024, 1024, 1);
    head_kernel<<<512, 32>>>(p_fc2, cls_w, cls_b, breg_w, breg_b, out);
}

// round 10
// speedup vs baseline: 1.9666x; 1.0208x over previous
#include <cuda_runtime.h>
#include <cuda_bf16.h>
#include <math.h>

// ---------------------------------------------------------------------------
// Static scratch (allocation-free rule: __device__ globals)
// ---------------------------------------------------------------------------
__device__ float g_stem[64 * 400 * 400];
__device__ float g_c2[256 * 200 * 200];
__device__ float g_c3[256 * 100 * 100];
__device__ float g_c4[256 * 50 * 50];
__device__ float g_c5[256 * 25 * 25];
__device__ float g_f2[256 * 200 * 200];
__device__ float g_f3[256 * 100 * 100];
__device__ float g_f4[256 * 50 * 50];
__device__ float g_f5[256 * 25 * 25];
__device__ float g_t[256 * 200 * 200];          // RPN hidden, reused per level
__device__ float g_part[2 * 256 * 200 * 200];   // k-split partials (reused)
__device__ float g_decb[159375 * 4];            // all levels' decoded boxes
__device__ float g_decs[159375];                // all levels' scores
__device__ float g_boxes4k[4000 * 4];
__device__ float g_scores4k[4000];
__device__ float g_props[512 * 4];
__device__ float g_pooled[512 * 12544];
__device__ float g_fc1[512 * 1024];
__device__ float g_fc2[512 * 1024];

__constant__ float c_mean[3] = {0.485f, 0.456f, 0.406f};
__constant__ float c_std[3]  = {0.229f, 0.224f, 0.225f};

// ---------------------------------------------------------------------------
// Packed f32x2 helpers (Blackwell FFMA2 — ptxas never auto-generates this)
// ---------------------------------------------------------------------------
__device__ __forceinline__ void ffma2(unsigned long long& d, unsigned long long a,
                                      unsigned long long b) {
    asm("fma.rn.f32x2 %0, %1, %2, %0;" : "+l"(d) : "l"(a), "l"(b));
}
__device__ __forceinline__ unsigned long long dup2(float v) {
    unsigned long long r;
    unsigned u = __float_as_uint(v);
    asm("mov.b64 %0, {%1, %1};" : "=l"(r) : "r"(u));
    return r;
}
__device__ __forceinline__ float2 unpack2(unsigned long long v) {
    unsigned lo, hi;
    asm("mov.b64 {%0, %1}, %2;" : "=r"(lo), "=r"(hi) : "l"(v));
    float2 f;
    f.x = __uint_as_float(lo);
    f.y = __uint_as_float(hi);
    return f;
}

// ---------------------------------------------------------------------------
// Stem conv 7x7 s2 (800->400, Cin=3, Cout=64) with fused normalize.
// ---------------------------------------------------------------------------
__global__ void stem_v2(const float* __restrict__ x, const float* __restrict__ w,
                        float* __restrict__ out) {
    constexpr int IH = 21, IW = 69;
    __shared__ float sIn[3][IH][IW];
    __shared__ __align__(16) float sW[3][49][16];

    const int tid = threadIdx.x;
    const int tx = tid & 31, ty = tid >> 5;
    const int ox0 = blockIdx.x * 32, oy0 = blockIdx.y * 8, oc0 = blockIdx.z * 16;
    const int ix0 = ox0 * 2 - 2, iy0 = oy0 * 2 - 2;

    for (int idx = tid; idx < 3 * IH * IW; idx += 128) {
        int ci = idx / (IH * IW);
        int rem = idx % (IH * IW);
        int r = rem / IW, c = rem % IW;
        int gy = iy0 + r, gx = ix0 + c;
        float v = 0.f;
        if (gy >= 0 && gy < 800 && gx >= 0 && gx < 800)
            v = (x[ci * 640000 + gy * 800 + gx] - c_mean[ci]) / c_std[ci];
        sIn[ci][r][c] = v;
    }
    for (int idx = tid; idx < 3 * 49 * 16; idx += 128) {
        int j = idx & 15;
        int t = (idx >> 4) % 49;
        int ci = idx / (49 * 16);
        sW[ci][t][j] = w[(oc0 + j) * 147 + ci * 49 + t];
    }
    __syncthreads();

    unsigned long long acc[2][8];
#pragma unroll
    for (int r = 0; r < 2; r++)
#pragma unroll
        for (int jp = 0; jp < 8; jp++) acc[r][jp] = 0ull;

#pragma unroll 1
    for (int ci = 0; ci < 3; ci++) {
#pragma unroll 1
        for (int ky = 0; ky < 7; ky++) {
#pragma unroll
            for (int kx = 0; kx < 7; kx++) {
                int t = ky * 7 + kx;
                const longlong2* wp2 = (const longlong2*)&sW[ci][t][0];
                longlong2 q0 = wp2[0], q1 = wp2[1], q2 = wp2[2], q3 = wp2[3];
                unsigned long long wv[8] = {
                    (unsigned long long)q0.x, (unsigned long long)q0.y,
                    (unsigned long long)q1.x, (unsigned long long)q1.y,
                    (unsigned long long)q2.x, (unsigned long long)q2.y,
                    (unsigned long long)q3.x, (unsigned long long)q3.y};
#pragma unroll
                for (int r = 0; r < 2; r++) {
                    float v = sIn[ci][(ty * 2 + r) * 2 + ky][tx * 2 + kx];
                    unsigned long long vv = dup2(v);
#pragma unroll
                    for (int jp = 0; jp < 8; jp++) ffma2(acc[r][jp], vv, wv[jp]);
                }
            }
        }
    }

    int xo = ox0 + tx;
    if (xo < 400) {
#pragma unroll
        for (int r = 0; r < 2; r++) {
            int yo = oy0 + ty * 2 + r;
#pragma unroll
            for (int jp = 0; jp < 8; jp++) {
                float2 f = unpack2(acc[r][jp]);
                out[(size_t)(oc0 + 2 * jp) * 160000 + yo * 400 + xo] = fmaxf(f.x, 0.f);
                out[(size_t)(oc0 + 2 * jp + 1) * 160000 + yo * 400 + xo] = fmaxf(f.y, 0.f);
            }
        }
    }
}

// ---------------------------------------------------------------------------
// 3x3 conv v3 (stride-2 path): tile 32x16 out, 16 oc/block, 256 threads,
// 2 px x 16 oc per thread, 2-stage smem pipeline, optional Cin-split.
// ---------------------------------------------------------------------------
template <int S, int PADLO>
__global__ void __launch_bounds__(256, 2)
conv3x3_v3(const float* __restrict__ in, const float* __restrict__ w,
           float* __restrict__ out, int Cin, int Hin, int Win,
           int Hout, int Wout, int do_relu, int nsplit, int nOcG, int Cout) {
    constexpr int TW = 32, TH = 16, OCB = 16;
    constexpr int IW = (TW - 1) * S + 3;
    constexpr int IH = (TH - 1) * S + 3;
    constexpr int NPIX = IH * IW;
    constexpr int NLD = (NPIX + 255) / 256;
    __shared__ float sIn[2][NPIX];
    __shared__ __align__(16) float sW[2][9][OCB];

    const int tid = threadIdx.x;
    const int tx = tid & 31, ty = tid >> 5;
    const int ocg = blockIdx.z % nOcG, split = blockIdx.z / nOcG;
    const int oc0 = ocg * OCB;
    const int cs = Cin / nsplit;
    const int ci0 = split * cs;
    const int ox0 = blockIdx.x * TW, oy0 = blockIdx.y * TH;
    const int ix0 = ox0 * S - PADLO, iy0 = oy0 * S - PADLO;
    const bool interior =
        (ix0 >= 0) && (iy0 >= 0) && (ix0 + IW <= Win) && (iy0 + IH <= Hin);

    float rbuf[NLD];
    float wreg = 0.f;
    const int wj = tid & 15, wt = tid >> 4;

    auto fetch = [&](int ci) {
        const float* inp = in + (size_t)ci * Hin * Win;
        if (interior) {
#pragma unroll
            for (int l = 0; l < NLD; l++) {
                int idx = tid + l * 256;
                if (idx < NPIX) {
                    int r = idx / IW, c = idx % IW;
                    rbuf[l] = __ldg(&inp[(iy0 + r) * Win + ix0 + c]);
                }
            }
        } else {
#pragma unroll
            for (int l = 0; l < NLD; l++) {
                int idx = tid + l * 256;
                if (idx < NPIX) {
                    int r = idx / IW, c = idx % IW;
                    int gy = iy0 + r, gx = ix0 + c;
                    float v = 0.f;
                    if (gy >= 0 && gy < Hin && gx >= 0 && gx < Win)
                        v = inp[gy * Win + gx];
                    rbuf[l] = v;
                }
            }
        }
        if (tid < 144) wreg = w[((size_t)(oc0 + wj) * Cin + ci) * 9 + wt];
    };
    auto sts = [&](int b) {
#pragma unroll
        for (int l = 0; l < NLD; l++) {
            int idx = tid + l * 256;
            if (idx < NPIX) sIn[b][idx] = rbuf[l];
        }
        if (tid < 144) sW[b][wt][wj] = wreg;
    };

    unsigned long long acc[2][8];
#pragma unroll
    for (int r = 0; r < 2; r++)
#pragma unroll
        for (int jp = 0; jp < 8; jp++) acc[r][jp] = 0ull;

    fetch(ci0);
    sts(0);
    __syncthreads();

    for (int i = 0; i < cs; i++) {
        const int b = i & 1;
        const bool more = (i + 1 < cs);
        if (more) fetch(ci0 + i + 1);

#pragma unroll
        for (int ky = 0; ky < 3; ky++) {
#pragma unroll
            for (int kx = 0; kx < 3; kx++) {
                const int t = ky * 3 + kx;
                const longlong2* wp2 = (const longlong2*)&sW[b][t][0];
                longlong2 q0 = wp2[0], q1 = wp2[1], q2 = wp2[2], q3 = wp2[3];
                unsigned long long wv0 = (unsigned long long)q0.x,
                                  wv1 = (unsigned long long)q0.y,
                                  wv2 = (unsigned long long)q1.x,
                                  wv3 = (unsigned long long)q1.y,
                                  wv4 = (unsigned long long)q2.x,
                                  wv5 = (unsigned long long)q2.y,
                                  wv6 = (unsigned long long)q3.x,
                                  wv7 = (unsigned long long)q3.y;
#pragma unroll
                for (int rr = 0; rr < 2; rr++) {
                    float v = sIn[b][((ty * 2 + rr) * S + ky) * IW + tx * S + kx];
                    unsigned long long vv = dup2(v);
                    ffma2(acc[rr][0], vv, wv0);
                    ffma2(acc[rr][1], vv, wv1);
                    ffma2(acc[rr][2], vv, wv2);
                    ffma2(acc[rr][3], vv, wv3);
                    ffma2(acc[rr][4], vv, wv4);
                    ffma2(acc[rr][5], vv, wv5);
                    ffma2(acc[rr][6], vv, wv6);
                    ffma2(acc[rr][7], vv, wv7);
                }
            }
        }
        if (more) {
            sts(b ^ 1);
            __syncthreads();
        }
    }

    const int xo = ox0 + tx;
    if (xo < Wout) {
#pragma unroll
        for (int rr = 0; rr < 2; rr++) {
            int yo = oy0 + ty * 2 + rr;
            if (yo < Hout) {
#pragma unroll
                for (int jp = 0; jp < 8; jp++) {
                    float2 f = unpack2(acc[rr][jp]);
                    if (nsplit == 1) {
                        if (do_relu) {
                            f.x = fmaxf(f.x, 0.f);
                            f.y = fmaxf(f.y, 0.f);
                        }
                        out[((size_t)(oc0 + 2 * jp) * Hout + yo) * Wout + xo] = f.x;
                        out[((size_t)(oc0 + 2 * jp + 1) * Hout + yo) * Wout + xo] = f.y;
                    } else {
                        size_t base = (size_t)split * Cout;
                        out[((base + oc0 + 2 * jp) * Hout + yo) * Wout + xo] = f.x;
                        out[((base + oc0 + 2 * jp + 1) * Hout + yo) * Wout + xo] = f.y;
                    }
                }
            }
        }
    }
}

// ---------------------------------------------------------------------------
// 3x3 conv v4 (stride-1): tile 32x32 out, 16 oc/block, 256 threads,
// 4 px x 16 oc per thread. 2-stage smem pipeline, optional Cin-split.
// ---------------------------------------------------------------------------
__global__ void __launch_bounds__(256, 2)
conv3x3_v4(const float* __restrict__ in, const float* __restrict__ w,
           float* __restrict__ out, int Cin, int Hin, int Win,
           int Hout, int Wout, int do_relu, int nsplit, int nOcG, int Cout) {
    constexpr int TW = 32, TH = 32, OCB = 16;
    constexpr int IW = TW + 2, IH = TH + 2;
    constexpr int NPIX = IH * IW;
    constexpr int NLD = (NPIX + 255) / 256;
    __shared__ float sIn[2][NPIX];
    __shared__ __align__(16) float sW[2][9][OCB];

    const int tid = threadIdx.x;
    const int tx = tid & 31, ty = tid >> 5;
    const int ocg = blockIdx.z % nOcG, split = blockIdx.z / nOcG;
    const int oc0 = ocg * OCB;
    const int cs = Cin / nsplit;
    const int ci0 = split * cs;
    const int ox0 = blockIdx.x * TW, oy0 = blockIdx.y * TH;
    const int ix0 = ox0 - 1, iy0 = oy0 - 1;
    const bool interior =
        (ix0 >= 0) && (iy0 >= 0) && (ix0 + IW <= Win) && (iy0 + IH <= Hin);

    float rbuf[NLD];
    float wreg = 0.f;
    const int wj = tid & 15, wt = tid >> 4;

    auto fetch = [&](int ci) {
        const float* inp = in + (size_t)ci * Hin * Win;
        if (interior) {
#pragma unroll
            for (int l = 0; l < NLD; l++) {
                int idx = tid + l * 256;
                if (idx < NPIX) {
                    int r = idx / IW, c = idx % IW;
                    rbuf[l] = __ldg(&inp[(iy0 + r) * Win + ix0 + c]);
                }
            }
        } else {
#pragma unroll
            for (int l = 0; l < NLD; l++) {
                int idx = tid + l * 256;
                if (idx < NPIX) {
                    int r = idx / IW, c = idx % IW;
                    int gy = iy0 + r, gx = ix0 + c;
                    float v = 0.f;
                    if (gy >= 0 && gy < Hin && gx >= 0 && gx < Win)
                        v = inp[gy * Win + gx];
                    rbuf[l] = v;
                }
            }
        }
        if (tid < 144) wreg = w[((size_t)(oc0 + wj) * Cin + ci) * 9 + wt];
    };
    auto sts = [&](int b) {
#pragma unroll
        for (int l = 0; l < NLD; l++) {
            int idx = tid + l * 256;
            if (idx < NPIX) sIn[b][idx] = rbuf[l];
        }
        if (tid < 144) sW[b][wt][wj] = wreg;
    };

    unsigned long long acc[4][8];
#pragma unroll
    for (int r = 0; r < 4; r++)
#pragma unroll
        for (int jp = 0; jp < 8; jp++) acc[r][jp] = 0ull;

    fetch(ci0);
    sts(0);
    __syncthreads();

    for (int i = 0; i < cs; i++) {
        const int b = i & 1;
        const bool more = (i + 1 < cs);
        if (more) fetch(ci0 + i + 1);

#pragma unroll
        for (int ky = 0; ky < 3; ky++) {
#pragma unroll
            for (int kx = 0; kx < 3; kx++) {
                const int t = ky * 3 + kx;
                const longlong2* wp2 = (const longlong2*)&sW[b][t][0];
                longlong2 q0 = wp2[0], q1 = wp2[1], q2 = wp2[2], q3 = wp2[3];
                unsigned long long wv0 = (unsigned long long)q0.x,
                                  wv1 = (unsigned long long)q0.y,
                                  wv2 = (unsigned long long)q1.x,
                                  wv3 = (unsigned long long)q1.y,
                                  wv4 = (unsigned long long)q2.x,
                                  wv5 = (unsigned long long)q2.y,
                                  wv6 = (unsigned long long)q3.x,
                                  wv7 = (unsigned long long)q3.y;
#pragma unroll
                for (int rr = 0; rr < 4; rr++) {
                    float v = sIn[b][(ty * 4 + rr + ky) * IW + tx + kx];
                    unsigned long long vv = dup2(v);
                    ffma2(acc[rr][0], vv, wv0);
                    ffma2(acc[rr][1], vv, wv1);
                    ffma2(acc[rr][2], vv, wv2);
                    ffma2(acc[rr][3], vv, wv3);
                    ffma2(acc[rr][4], vv, wv4);
                    ffma2(acc[rr][5], vv, wv5);
                    ffma2(acc[rr][6], vv, wv6);
                    ffma2(acc[rr][7], vv, wv7);
                }
            }
        }
        if (more) {
            sts(b ^ 1);
            __syncthreads();
        }
    }

    const int xo = ox0 + tx;
    if (xo < Wout) {
#pragma unroll
        for (int rr = 0; rr < 4; rr++) {
            int yo = oy0 + ty * 4 + rr;
            if (yo < Hout) {
#pragma unroll
                for (int jp = 0; jp < 8; jp++) {
                    float2 f = unpack2(acc[rr][jp]);
                    if (nsplit == 1) {
                        if (do_relu) {
                            f.x = fmaxf(f.x, 0.f);
                            f.y = fmaxf(f.y, 0.f);
                        }
                        out[((size_t)(oc0 + 2 * jp) * Hout + yo) * Wout + xo] = f.x;
                        out[((size_t)(oc0 + 2 * jp + 1) * Hout + yo) * Wout + xo] = f.y;
                    } else {
                        size_t base = (size_t)split * Cout;
                        out[((base + oc0 + 2 * jp) * Hout + yo) * Wout + xo] = f.x;
                        out[((base + oc0 + 2 * jp + 1) * Hout + yo) * Wout + xo] = f.y;
                    }
                }
            }
        }
    }
}

// Deterministic fixed-order reduction over Cin-splits (+ optional relu).
__global__ void reduce_split_kernel(const float* __restrict__ part,
                                    float* __restrict__ out, int n, int nsplit,
                                    int do_relu) {
    int i = blockIdx.x * blockDim.x + threadIdx.x;
    if (i >= n) return;
    float acc = 0.f;
    for (int s = 0; s < nsplit; s++) acc += part[(size_t)s * n + i];
    if (do_relu) acc = fmaxf(acc, 0.f);
    out[i] = acc;
}

// ---------------------------------------------------------------------------
// Fused RPN head: 1x1 cls (3) + 1x1 box (12) + anchor decode.
// ---------------------------------------------------------------------------
__global__ void rpn_head_kernel(const float* __restrict__ t,
                                const float* __restrict__ cls_w,
                                const float* __restrict__ box_w,
                                int HW, int fw, float stride, float size,
                                float* __restrict__ dec_boxes,
                                float* __restrict__ dec_scores) {
    __shared__ float sCW[3][256];
    __shared__ float sBW[12][256];
    const int tid = threadIdx.x;
    for (int idx = tid; idx < 3 * 256; idx += 256) sCW[idx >> 8][idx & 255] = cls_w[idx];
    for (int idx = tid; idx < 12 * 256; idx += 256) sBW[idx >> 8][idx & 255] = box_w[idx];
    __syncthreads();

    const int p = blockIdx.x * 256 + tid;
    if (p >= HW) return;

    float accC[3] = {0.f, 0.f, 0.f};
    float accB[12];
#pragma unroll
    for (int j = 0; j < 12; j++) accB[j] = 0.f;

    for (int ci = 0; ci < 256; ci++) {
        float v = t[(size_t)ci * HW + p];
#pragma unroll
        for (int j = 0; j < 3; j++) accC[j] += v * sCW[j][ci];
#pragma unroll
        for (int j = 0; j < 12; j++) accB[j] += v * sBW[j][ci];
    }

    const int x = p % fw, y = p / fw;
    const double wm[3] = {1.4142135623730951, 1.0, 0.7071067811865476};
    const double hm[3] = {0.7071067811865476, 1.0, 1.4142135623730951};
    float acx = (x + 0.5f) * stride;
    float acy = (y + 0.5f) * stride;

#pragma unroll
    for (int a = 0; a < 3; a++) {
        float aw = (float)(size * wm[a]);
        float ah = (float)(size * hm[a]);
        float d0 = accB[a * 4 + 0];
        float d1 = accB[a * 4 + 1];
        float dw = fminf(fmaxf(accB[a * 4 + 2], -4.f), 4.f);
        float dh = fminf(fmaxf(accB[a * 4 + 3], -4.f), 4.f);
        float cx = acx + d0 * aw;
        float cy = acy + d1 * ah;
        float w = aw * expf(dw);
        float h = ah * expf(dh);
        int i = p * 3 + a;
        dec_boxes[i * 4 + 0] = fminf(fmaxf(cx - w * 0.5f, 0.f), 800.f);
        dec_boxes[i * 4 + 1] = fminf(fmaxf(cy - h * 0.5f, 0.f), 800.f);
        dec_boxes[i * 4 + 2] = fminf(fmaxf(cx + w * 0.5f, 0.f), 800.f);
        dec_boxes[i * 4 + 3] = fminf(fmaxf(cy + h * 0.5f, 0.f), 800.f);
        dec_scores[i] = accC[a];
    }
}

// ---------------------------------------------------------------------------
// Top-k (k = 1000): 4 levels in ONE launch, one block per level.
// ---------------------------------------------------------------------------
__device__ __forceinline__ unsigned keyof(float f) {
    unsigned u = __float_as_uint(f);
    return (u & 0x80000000u) ? ~u : (u | 0x80000000u);
}

__global__ void topk4_kernel(const float* __restrict__ all_scores,
                             const float* __restrict__ all_boxes,
                             const int4 offs, const int4 lens,
                             float* __restrict__ out_scores4k,
                             float* __restrict__ out_boxes4k) {
    const int lvl = blockIdx.x;
    const int off = (lvl == 0) ? offs.x : (lvl == 1) ? offs.y : (lvl == 2) ? offs.z : offs.w;
    const int n   = (lvl == 0) ? lens.x : (lvl == 1) ? lens.y : (lvl == 2) ? lens.z : lens.w;
    const int k = 1000;
    const float* scores = all_scores + off;
    const float* boxes = all_boxes + (size_t)off * 4;
    float* out_scores = out_scores4k + lvl * 1000;
    float* out_boxes = out_boxes4k + lvl * 4000;

    __shared__ unsigned hist[256];
    __shared__ unsigned sh_prefix, sh_kk, sh_cgt, sh_ceq;
    int tid = threadIdx.x;
    int NT = blockDim.x;
    if (tid == 0) { sh_prefix = 0; sh_kk = (unsigned)k; }
    unsigned mask = 0;
    __syncthreads();
    for (int shift = 24; shift >= 0; shift -= 8) {
        for (int b = tid; b < 256; b += NT) hist[b] = 0;
        __syncthreads();
        unsigned prefix = sh_prefix;
        for (int i = tid; i < n; i += NT) {
            unsigned key = keyof(scores[i]);
            if ((key & mask) == prefix) atomicAdd(&hist[(key >> shift) & 255], 1u);
        }
        __syncthreads();
        if (tid == 0) {
            unsigned kk = sh_kk, cum = 0;
            int b = 255;
            for (; b > 0; b--) {
                if (cum + hist[b] >= kk) break;
                cum += hist[b];
            }
            sh_prefix = prefix | ((unsigned)b << shift);
            sh_kk = kk - cum;
        }
        mask |= (0xFFu << shift);
        __syncthreads();
    }
    unsigned T = sh_prefix;
    unsigned kk = sh_kk;
    if (tid == 0) { sh_cgt = 0; sh_ceq = 0; }
    __syncthreads();
    int gtcount = k - (int)kk;
    for (int i = tid; i < n; i += NT) {
        unsigned key = keyof(scores[i]);
        int slot = -1;
        if (key > T) {
            slot = (int)atomicAdd(&sh_cgt, 1u);
        } else if (key == T) {
            unsigned e = atomicAdd(&sh_ceq, 1u);
            if (e < kk) slot = gtcount + (int)e;
        }
        if (slot >= 0) {
            out_scores[slot] = scores[i];
            out_boxes[slot * 4 + 0] = boxes[i * 4 + 0];
            out_boxes[slot * 4 + 1] = boxes[i * 4 + 1];
            out_boxes[slot * 4 + 2] = boxes[i * 4 + 2];
            out_boxes[slot * 4 + 3] = boxes[i * 4 + 3];
        }
    }
}

// ---------------------------------------------------------------------------
// NMS: one block, 512 threads, 512 sequential selections over 4000 candidates.
// ---------------------------------------------------------------------------
__global__ void nms_kernel(const float* __restrict__ boxes, const float* __restrict__ scores,
                           float* __restrict__ props, float* __restrict__ out_props,
                           float* __restrict__ out_scores) {
    constexpr int N = 4000, NT = 512, POST = 512;
    extern __shared__ float sm[];
    float* sx1 = sm;
    float* sy1 = sm + N;
    float* sx2 = sm + 2 * N;
    float* sy2 = sm + 3 * N;
    float* sar = sm + 4 * N;
    float* ss  = sm + 5 * N;
    __shared__ float rv[NT / 32];
    __shared__ int ri[NT / 32];
    __shared__ int s_best;

    int tid = threadIdx.x;
    for (int i = tid; i < N; i += NT) {
        float a = boxes[i * 4 + 0], b = boxes[i * 4 + 1];
        float c = boxes[i * 4 + 2], d = boxes[i * 4 + 3];
        sx1[i] = a; sy1[i] = b; sx2[i] = c; sy2[i] = d;
        sar[i] = (c - a) * (d - b);
        ss[i] = scores[i];
    }
    __syncthreads();

    for (int it = 0; it < POST; it++) {
        float bv = -INFINITY;
        int bi = 0x7FFFFFFF;
        for (int i = tid; i < N; i += NT) {
            float v = ss[i];
            if (v > bv || (v == bv && i < bi)) { bv = v; bi = i; }
        }
#pragma unroll
        for (int off = 16; off; off >>= 1) {
            float ov = __shfl_down_sync(0xFFFFFFFFu, bv, off);
            int oi = __shfl_down_sync(0xFFFFFFFFu, bi, off);
            if (ov > bv || (ov == bv && oi < bi)) { bv = ov; bi = oi; }
        }
        if ((tid & 31) == 0) { rv[tid >> 5] = bv; ri[tid >> 5] = bi; }
        __syncthreads();
        if (tid == 0) {
            float fbv = rv[0]; int fbi = ri[0];
            for (int wz = 1; wz < NT / 32; wz++) {
                float ov = rv[wz]; int oi = ri[wz];
                if (ov > fbv || (ov == fbv && oi < fbi)) { fbv = ov; fbi = oi; }
            }
            s_best = fbi;
        }
        __syncthreads();
        int idx = s_best;
        if (tid == 0) {
            float a = sx1[idx], b = sy1[idx], c = sx2[idx], d = sy2[idx];
            props[it * 4 + 0] = a; props[it * 4 + 1] = b;
            props[it * 4 + 2] = c; props[it * 4 + 3] = d;
            out_props[it * 4 + 0] = a; out_props[it * 4 + 1] = b;
            out_props[it * 4 + 2] = c; out_props[it * 4 + 3] = d;
            out_scores[it] = scores[idx];
        }
        float X1 = sx1[idx], Y1 = sy1[idx], X2 = sx2[idx], Y2 = sy2[idx], AR = sar[idx];
        for (int i = tid; i < N; i += NT) {
            float ix1 = fmaxf(sx1[i], X1), iy1 = fmaxf(sy1[i], Y1);
            float ix2 = fminf(sx2[i], X2), iy2 = fminf(sy2[i], Y2);
            float inter = fmaxf(ix2 - ix1, 0.f) * fmaxf(iy2 - iy1, 0.f);
            float iou = inter / (sar[i] + AR - inter + 1e-6f);
            if (iou > 0.7f) ss[i] = -INFINITY;
        }
        __syncthreads();
    }
}

// ---------------------------------------------------------------------------
// ROI Align on feats[0] (256, 200, 200), scale 0.25, POOL 7.
// ---------------------------------------------------------------------------
__global__ void roi_align_kernel(const float* __restrict__ feat, const float* __restrict__ rois,
                                 float* __restrict__ out) {
    __shared__ int six0[49], siy0[49], six1[49], siy1[49];
    __shared__ float swx[49], swy[49];
    int roi = blockIdx.x;
    int c = threadIdx.x;
    if (threadIdx.x < 49) {
        int p = threadIdx.x;
        int py = p / 7, px = p % 7;
        float r0 = rois[roi * 4 + 0] * 0.25f;
        float r1 = rois[roi * 4 + 1] * 0.25f;
        float bw = (rois[roi * 4 + 2] - rois[roi * 4 + 0]) * 0.25f / 7.0f;
        float bh = (rois[roi * 4 + 3] - rois[roi * 4 + 1]) * 0.25f / 7.0f;
        float gx = r0 + (px + 0.5f) * bw - 0.5f;
        float gy = r1 + (py + 0.5f) * bh - 0.5f;
        float fx = fminf(fmaxf(floorf(gx), 0.f), 199.f);
        float fy = fminf(fmaxf(floorf(gy), 0.f), 199.f);
        int x0 = (int)fx, y0 = (int)fy;
        six0[p] = x0; siy0[p] = y0;
        six1[p] = min(x0 + 1, 199);
        siy1[p] = min(y0 + 1, 199);
        swx[p] = fminf(fmaxf(gx - fx, 0.f), 1.f);
        swy[p] = fminf(fmaxf(gy - fy, 0.f), 1.f);
    }
    __syncthreads();
    const float* f = feat + (size_t)c * 40000;
    float* o = out + (size_t)roi * 12544 + (size_t)c * 49;
#pragma unroll 7
    for (int p = 0; p < 49; p++) {
        int x0 = six0[p], y0 = siy0[p], x1 = six1[p], y1 = siy1[p];
        float wx = swx[p], wy = swy[p];
        float v00 = f[y0 * 200 + x0];
        float v01 = f[y0 * 200 + x1];
        float v10 = f[y1 * 200 + x0];
        float v11 = f[y1 * 200 + x1];
        o[p] = v00 * (1.f - wy) * (1.f - wx) + v01 * (1.f - wy) * wx +
               v10 * wy * (1.f - wx) + v11 * wy * wx;
    }
}

// ---------------------------------------------------------------------------
// SGEMM: C = relu(A @ B + bias). f32x2 over N-column pairs.
// ---------------------------------------------------------------------------
__global__ void sgemm_bias_relu(const float* __restrict__ A, const float* __restrict__ B,
                                const float* __restrict__ bias, float* __restrict__ C,
                                int M, int N, int K, int do_relu) {
    constexpr int BM = 64, BN = 64, BK = 16;
    __shared__ float sA[BK][BM + 1];
    __shared__ __align__(16) float sB[BK][BN + 2];
    int tid = threadIdx.x;
    int trow = tid / 16, tcol = tid % 16;
    int bm0 = blockIdx.y * BM, bn0 = blockIdx.x * BN;
    unsigned long long acc2[4][2];
#pragma unroll
    for (int i = 0; i < 4; i++) { acc2[i][0] = 0ull; acc2[i][1] = 0ull; }

    for (int k0 = 0; k0 < K; k0 += BK) {
#pragma unroll
        for (int l = 0; l < 4; l++) {
            int e = tid + l * 256;
            int ar = e / BK, ac = e % BK;
            sA[ac][ar] = A[(size_t)(bm0 + ar) * K + k0 + ac];
        }
#pragma unroll
        for (int l = 0; l < 4; l++) {
            int e = tid + l * 256;
            int br = e >> 6, bc = e & 63;
            sB[br][bc] = B[(size_t)(k0 + br) * N + bn0 + bc];
        }
        __syncthreads();
#pragma unroll
        for (int kk = 0; kk < BK; kk++) {
            unsigned long long b0 = *(const unsigned long long*)&sB[kk][tcol * 4];
            unsigned long long b1 = *(const unsigned long long*)&sB[kk][tcol * 4 + 2];
#pragma unroll
            for (int i = 0; i < 4; i++) {
                unsigned long long vv = dup2(sA[kk][trow * 4 + i]);
                ffma2(acc2[i][0], vv, b0);
                ffma2(acc2[i][1], vv, b1);
            }
        }
        __syncthreads();
    }
#pragma unroll
    for (int i = 0; i < 4; i++) {
        int r = bm0 + trow * 4 + i;
#pragma unroll
        for (int jp = 0; jp < 2; jp++) {
            int cidx = bn0 + tcol * 4 + 2 * jp;
            float2 f = unpack2(acc2[i][jp]);
            f.x += bias[cidx];
            f.y += bias[cidx + 1];
            if (do_relu) { f.x = fmaxf(f.x, 0.f); f.y = fmaxf(f.y, 0.f); }
            C[(size_t)r * N + cidx] = f.x;
            C[(size_t)r * N + cidx + 1] = f.y;
        }
    }
}

// ---------------------------------------------------------------------------
// Final heads: cls (1024->2) and breg (1024->8), write directly to d_out.
// ---------------------------------------------------------------------------
__global__ void head_kernel(const float* __restrict__ A, const float* __restrict__ cw,
                            const float* __restrict__ cb, const float* __restrict__ bw,
                            const float* __restrict__ bb, float* __restrict__ out) {
    int m = blockIdx.x;
    int j = threadIdx.x;
    if (j >= 10) return;
    const float* a = A + (size_t)m * 1024;
    bool is_cls = (j < 2);
    const float* W = is_cls ? cw : bw;
    int n = is_cls ? j : j - 2;
    int N = is_cls ? 2 : 8;
    float acc = 0.f;
    for (int k = 0; k < 1024; k++) acc += a[k] * W[(size_t)k * N + n];
    acc += is_cls ? cb[n] : bb[n];
    if (is_cls) out[m * 2 + n] = acc;
    else out[1024 + m * 8 + n] = acc;
}

// ---------------------------------------------------------------------------
// Host: launch sequence
// ---------------------------------------------------------------------------
static inline void* symaddr(const void* sym) {
    void* p = nullptr;
    cudaGetSymbolAddress(&p, sym);
    return p;
}

static inline int ceil_div(int a, int b) { return (a + b - 1) / b; }

extern "C" void kernel_launch(void* const* d_in, const int* in_sizes, int n_in,
                              void* d_out, int out_size) {
    const float* x       = (const float*)d_in[0];
    const float* stem_w  = (const float*)d_in[1];
    const float* c2_w    = (const float*)d_in[2];
    const float* c3_w    = (const float*)d_in[3];
    const float* c4_w    = (const float*)d_in[4];
    const float* c5_w    = (const float*)d_in[5];
    const float* fpn_w[4] = {(const float*)d_in[6], (const float*)d_in[7],
                             (const float*)d_in[8], (const float*)d_in[9]};
    const float* rpn_w     = (const float*)d_in[10];
    const float* rpn_cls_w = (const float*)d_in[11];
    const float* rpn_box_w = (const float*)d_in[12];
    const float* fc1_w = (const float*)d_in[13];
    const float* fc1_b = (const float*)d_in[14];
    const float* fc2_w = (const float*)d_in[15];
    const float* fc2_b = (const float*)d_in[16];
    const float* cls_w = (const float*)d_in[17];
    const float* cls_b = (const float*)d_in[18];
    const float* breg_w = (const float*)d_in[19];
    const float* breg_b = (const float*)d_in[20];
    float* out = (float*)d_out;

    float* p_stem = (float*)symaddr(g_stem);
    float* p_c2   = (float*)symaddr(g_c2);
    float* p_c3   = (float*)symaddr(g_c3);
    float* p_c4   = (float*)symaddr(g_c4);
    float* p_c5   = (float*)symaddr(g_c5);
    float* p_f[4] = {(float*)symaddr(g_f2), (float*)symaddr(g_f3),
                     (float*)symaddr(g_f4), (float*)symaddr(g_f5)};
    float* p_t    = (float*)symaddr(g_t);
    float* p_part = (float*)symaddr(g_part);
    float* p_decb = (float*)symaddr(g_decb);
    float* p_decs = (float*)symaddr(g_decs);
    float* p_b4k  = (float*)symaddr(g_boxes4k);
    float* p_s4k  = (float*)symaddr(g_scores4k);
    float* p_props = (float*)symaddr(g_props);
    float* p_pool = (float*)symaddr(g_pooled);
    float* p_fc1  = (float*)symaddr(g_fc1);
    float* p_fc2  = (float*)symaddr(g_fc2);

    const int fh[4] = {200, 100, 50, 25};
    const int ksv4[4] = {2, 2, 8, 16};  // Cin-splits for stride-1 convs (v4)
    const int doff[4] = {0, 120000, 150000, 157500};  // decode region offsets

    // 1. stem 7x7 s2 with fused normalize
    stem_v2<<<dim3(13, 50, 4), 128>>>(x, stem_w, p_stem);

    // 2. backbone strided 3x3 convs (relu) — v3 path
    conv3x3_v3<2, 0><<<dim3(7, 13, 16), 256>>>(p_stem, c2_w, p_c2, 64, 400, 400,
                                               200, 200, 1, 1, 16, 256);
    conv3x3_v3<2, 0><<<dim3(4, 7, 16 * 4), 256>>>(p_c2, c3_w, p_part, 256, 200, 200,
                                                  100, 100, 1, 4, 16, 256);
    reduce_split_kernel<<<ceil_div(256 * 10000, 256), 256>>>(p_part, p_c3,
                                                             256 * 10000, 4, 1);
    conv3x3_v3<2, 0><<<dim3(2, 4, 16 * 8), 256>>>(p_c3, c4_w, p_part, 256, 100, 100,
                                                  50, 50, 1, 8, 16, 256);
    reduce_split_kernel<<<ceil_div(256 * 2500, 256), 256>>>(p_part, p_c4,
                                                            256 * 2500, 8, 1);
    conv3x3_v3<2, 0><<<dim3(1, 2, 16 * 16), 256>>>(p_c4, c5_w, p_part, 256, 50, 50,
                                                   25, 25, 1, 16, 16, 256);
    reduce_split_kernel<<<ceil_div(256 * 625, 256), 256>>>(p_part, p_c5,
                                                           256 * 625, 16, 1);

    // 3. FPN lateral convs (no relu) — v4 path (stride 1)
    const float* csrc[4] = {p_c2, p_c3, p_c4, p_c5};
    for (int l = 0; l < 4; l++) {
        int H = fh[l], HW = H * H;
        int k = ksv4[l];
        dim3 g(ceil_div(H, 32), ceil_div(H, 32), 16 * k);
        conv3x3_v4<<<g, 256>>>(csrc[l], fpn_w[l], p_part, 256, H, H, H, H,
                               0, k, 16, 256);
        reduce_split_kernel<<<ceil_div(256 * HW, 256), 256>>>(p_part, p_f[l],
                                                              256 * HW, k, 0);
    }

    // 4. RPN per level: conv-relu (v4), fused head+decode into level regions
    const float strides[4] = {4.f, 8.f, 16.f, 32.f};
    const float sizes[4] = {32.f, 64.f, 128.f, 256.f};
    for (int l = 0; l < 4; l++) {
        int H = fh[l], HW = H * H;
        int k = ksv4[l];
        dim3 g(ceil_div(H, 32), ceil_div(H, 32), 16 * k);
        conv3x3_v4<<<g, 256>>>(p_f[l], rpn_w, p_part, 256, H, H, H, H,
                               1, k, 16, 256);
        reduce_split_kernel<<<ceil_div(256 * HW, 256), 256>>>(p_part, p_t,
                                                              256 * HW, k, 1);
        rpn_head_kernel<<<ceil_div(HW, 256), 256>>>(p_t, rpn_cls_w, rpn_box_w,
                                                    HW, H, strides[l], sizes[l],
                                                    p_decb + (size_t)doff[l] * 4,
                                                    p_decs + doff[l]);
    }

    // 5. Combined top-1000 over 4 levels (one launch, 4 blocks)
    {
        int4 offs = make_int4(doff[0], doff[1], doff[2], doff[3]);
        int4 lens = make_int4(120000, 30000, 7500, 1875);
        topk4_kernel<<<4, 1024>>>(p_decs, p_decb, offs, lens, p_s4k, p_b4k);
    }

    // 6. NMS (512 out of 4000)
    cudaFuncSetAttribute(nms_kernel, cudaFuncAttributeMaxDynamicSharedMemorySize, 96000);
    nms_kernel<<<1, 512, 96000>>>(p_b4k, p_s4k, p_props, out + 5120, out + 7168);

    // 7. ROI align on feats[0]
    roi_align_kernel<<<512, 256>>>(p_f[0], p_props, p_pool);

    // 8. FC head
    sgemm_bias_relu<<<dim3(1024 / 64, 512 / 64), 256>>>(p_pool, fc1_w, fc1_b, p_fc1,
                                                        512, 1024, 12544, 1);
    sgemm_bias_relu<<<dim3(1024 / 64, 512 / 64), 256>>>(p_fc1, fc2_w, fc2_b, p_fc2,
                                                        512, 1024, 1024, 1);
    head_kernel<<<512, 32>>>(p_fc2, cls_w, cls_b, breg_w, breg_b, out);
}

// round 11
// speedup vs baseline: 2.2822x; 1.1605x over previous
#include <cuda_runtime.h>
#include <cuda_bf16.h>
#include <math.h>

// ---------------------------------------------------------------------------
// Static scratch (allocation-free rule: __device__ globals)
// ---------------------------------------------------------------------------
__device__ float g_stem[64 * 400 * 400];
__device__ float g_c2[256 * 200 * 200];
__device__ float g_c3[256 * 100 * 100];
__device__ float g_c4[256 * 50 * 50];
__device__ float g_c5[256 * 25 * 25];
__device__ float g_f2[256 * 200 * 200];
__device__ float g_f3[256 * 100 * 100];
__device__ float g_f4[256 * 50 * 50];
__device__ float g_f5[256 * 25 * 25];
__device__ float g_t[256 * 200 * 200];          // RPN hidden, reused per level
__device__ float g_part[2 * 256 * 200 * 200];   // k-split partials (reused)
__device__ float g_winoU[16 * 256 * 256];       // Winograd weight transform
__device__ float g_winoV[16 * 256 * 10000];     // Winograd input transform
__device__ float g_winoM[16 * 256 * 10000];     // Winograd GEMM output
__device__ float g_decb[159375 * 4];            // all levels' decoded boxes
__device__ float g_decs[159375];                // all levels' scores
__device__ float g_boxes4k[4000 * 4];
__device__ float g_scores4k[4000];
__device__ float g_props[512 * 4];
__device__ float g_pooled[512 * 12544];
__device__ float g_fc1[512 * 1024];
__device__ float g_fc2[512 * 1024];

__constant__ float c_mean[3] = {0.485f, 0.456f, 0.406f};
__constant__ float c_std[3]  = {0.229f, 0.224f, 0.225f};

// ---------------------------------------------------------------------------
// Packed f32x2 helpers (Blackwell FFMA2 — ptxas never auto-generates this)
// ---------------------------------------------------------------------------
__device__ __forceinline__ void ffma2(unsigned long long& d, unsigned long long a,
                                      unsigned long long b) {
    asm("fma.rn.f32x2 %0, %1, %2, %0;" : "+l"(d) : "l"(a), "l"(b));
}
__device__ __forceinline__ unsigned long long dup2(float v) {
    unsigned long long r;
    unsigned u = __float_as_uint(v);
    asm("mov.b64 %0, {%1, %1};" : "=l"(r) : "r"(u));
    return r;
}
__device__ __forceinline__ float2 unpack2(unsigned long long v) {
    unsigned lo, hi;
    asm("mov.b64 {%0, %1}, %2;" : "=r"(lo), "=r"(hi) : "l"(v));
    float2 f;
    f.x = __uint_as_float(lo);
    f.y = __uint_as_float(hi);
    return f;
}

// ---------------------------------------------------------------------------
// Stem conv 7x7 s2 (800->400, Cin=3, Cout=64) with fused normalize.
// ---------------------------------------------------------------------------
__global__ void stem_v2(const float* __restrict__ x, const float* __restrict__ w,
                        float* __restrict__ out) {
    constexpr int IH = 21, IW = 69;
    __shared__ float sIn[3][IH][IW];
    __shared__ __align__(16) float sW[3][49][16];

    const int tid = threadIdx.x;
    const int tx = tid & 31, ty = tid >> 5;
    const int ox0 = blockIdx.x * 32, oy0 = blockIdx.y * 8, oc0 = blockIdx.z * 16;
    const int ix0 = ox0 * 2 - 2, iy0 = oy0 * 2 - 2;

    for (int idx = tid; idx < 3 * IH * IW; idx += 128) {
        int ci = idx / (IH * IW);
        int rem = idx % (IH * IW);
        int r = rem / IW, c = rem % IW;
        int gy = iy0 + r, gx = ix0 + c;
        float v = 0.f;
        if (gy >= 0 && gy < 800 && gx >= 0 && gx < 800)
            v = (x[ci * 640000 + gy * 800 + gx] - c_mean[ci]) / c_std[ci];
        sIn[ci][r][c] = v;
    }
    for (int idx = tid; idx < 3 * 49 * 16; idx += 128) {
        int j = idx & 15;
        int t = (idx >> 4) % 49;
        int ci = idx / (49 * 16);
        sW[ci][t][j] = w[(oc0 + j) * 147 + ci * 49 + t];
    }
    __syncthreads();

    unsigned long long acc[2][8];
#pragma unroll
    for (int r = 0; r < 2; r++)
#pragma unroll
        for (int jp = 0; jp < 8; jp++) acc[r][jp] = 0ull;

#pragma unroll 1
    for (int ci = 0; ci < 3; ci++) {
#pragma unroll 1
        for (int ky = 0; ky < 7; ky++) {
#pragma unroll
            for (int kx = 0; kx < 7; kx++) {
                int t = ky * 7 + kx;
                const longlong2* wp2 = (const longlong2*)&sW[ci][t][0];
                longlong2 q0 = wp2[0], q1 = wp2[1], q2 = wp2[2], q3 = wp2[3];
                unsigned long long wv[8] = {
                    (unsigned long long)q0.x, (unsigned long long)q0.y,
                    (unsigned long long)q1.x, (unsigned long long)q1.y,
                    (unsigned long long)q2.x, (unsigned long long)q2.y,
                    (unsigned long long)q3.x, (unsigned long long)q3.y};
#pragma unroll
                for (int r = 0; r < 2; r++) {
                    float v = sIn[ci][(ty * 2 + r) * 2 + ky][tx * 2 + kx];
                    unsigned long long vv = dup2(v);
#pragma unroll
                    for (int jp = 0; jp < 8; jp++) ffma2(acc[r][jp], vv, wv[jp]);
                }
            }
        }
    }

    int xo = ox0 + tx;
    if (xo < 400) {
#pragma unroll
        for (int r = 0; r < 2; r++) {
            int yo = oy0 + ty * 2 + r;
#pragma unroll
            for (int jp = 0; jp < 8; jp++) {
                float2 f = unpack2(acc[r][jp]);
                out[(size_t)(oc0 + 2 * jp) * 160000 + yo * 400 + xo] = fmaxf(f.x, 0.f);
                out[(size_t)(oc0 + 2 * jp + 1) * 160000 + yo * 400 + xo] = fmaxf(f.y, 0.f);
            }
        }
    }
}

// ---------------------------------------------------------------------------
// 3x3 conv v3 (stride-2 path): tile 32x16 out, 16 oc/block, 256 threads,
// 2 px x 16 oc per thread, 2-stage smem pipeline, optional Cin-split.
// ---------------------------------------------------------------------------
template <int S, int PADLO>
__global__ void __launch_bounds__(256, 2)
conv3x3_v3(const float* __restrict__ in, const float* __restrict__ w,
           float* __restrict__ out, int Cin, int Hin, int Win,
           int Hout, int Wout, int do_relu, int nsplit, int nOcG, int Cout) {
    constexpr int TW = 32, TH = 16, OCB = 16;
    constexpr int IW = (TW - 1) * S + 3;
    constexpr int IH = (TH - 1) * S + 3;
    constexpr int NPIX = IH * IW;
    constexpr int NLD = (NPIX + 255) / 256;
    __shared__ float sIn[2][NPIX];
    __shared__ __align__(16) float sW[2][9][OCB];

    const int tid = threadIdx.x;
    const int tx = tid & 31, ty = tid >> 5;
    const int ocg = blockIdx.z % nOcG, split = blockIdx.z / nOcG;
    const int oc0 = ocg * OCB;
    const int cs = Cin / nsplit;
    const int ci0 = split * cs;
    const int ox0 = blockIdx.x * TW, oy0 = blockIdx.y * TH;
    const int ix0 = ox0 * S - PADLO, iy0 = oy0 * S - PADLO;
    const bool interior =
        (ix0 >= 0) && (iy0 >= 0) && (ix0 + IW <= Win) && (iy0 + IH <= Hin);

    float rbuf[NLD];
    float wreg = 0.f;
    const int wj = tid & 15, wt = tid >> 4;

    auto fetch = [&](int ci) {
        const float* inp = in + (size_t)ci * Hin * Win;
        if (interior) {
#pragma unroll
            for (int l = 0; l < NLD; l++) {
                int idx = tid + l * 256;
                if (idx < NPIX) {
                    int r = idx / IW, c = idx % IW;
                    rbuf[l] = __ldg(&inp[(iy0 + r) * Win + ix0 + c]);
                }
            }
        } else {
#pragma unroll
            for (int l = 0; l < NLD; l++) {
                int idx = tid + l * 256;
                if (idx < NPIX) {
                    int r = idx / IW, c = idx % IW;
                    int gy = iy0 + r, gx = ix0 + c;
                    float v = 0.f;
                    if (gy >= 0 && gy < Hin && gx >= 0 && gx < Win)
                        v = inp[gy * Win + gx];
                    rbuf[l] = v;
                }
            }
        }
        if (tid < 144) wreg = w[((size_t)(oc0 + wj) * Cin + ci) * 9 + wt];
    };
    auto sts = [&](int b) {
#pragma unroll
        for (int l = 0; l < NLD; l++) {
            int idx = tid + l * 256;
            if (idx < NPIX) sIn[b][idx] = rbuf[l];
        }
        if (tid < 144) sW[b][wt][wj] = wreg;
    };

    unsigned long long acc[2][8];
#pragma unroll
    for (int r = 0; r < 2; r++)
#pragma unroll
        for (int jp = 0; jp < 8; jp++) acc[r][jp] = 0ull;

    fetch(ci0);
    sts(0);
    __syncthreads();

    for (int i = 0; i < cs; i++) {
        const int b = i & 1;
        const bool more = (i + 1 < cs);
        if (more) fetch(ci0 + i + 1);

#pragma unroll
        for (int ky = 0; ky < 3; ky++) {
#pragma unroll
            for (int kx = 0; kx < 3; kx++) {
                const int t = ky * 3 + kx;
                const longlong2* wp2 = (const longlong2*)&sW[b][t][0];
                longlong2 q0 = wp2[0], q1 = wp2[1], q2 = wp2[2], q3 = wp2[3];
                unsigned long long wv0 = (unsigned long long)q0.x,
                                  wv1 = (unsigned long long)q0.y,
                                  wv2 = (unsigned long long)q1.x,
                                  wv3 = (unsigned long long)q1.y,
                                  wv4 = (unsigned long long)q2.x,
                                  wv5 = (unsigned long long)q2.y,
                                  wv6 = (unsigned long long)q3.x,
                                  wv7 = (unsigned long long)q3.y;
#pragma unroll
                for (int rr = 0; rr < 2; rr++) {
                    float v = sIn[b][((ty * 2 + rr) * S + ky) * IW + tx * S + kx];
                    unsigned long long vv = dup2(v);
                    ffma2(acc[rr][0], vv, wv0);
                    ffma2(acc[rr][1], vv, wv1);
                    ffma2(acc[rr][2], vv, wv2);
                    ffma2(acc[rr][3], vv, wv3);
                    ffma2(acc[rr][4], vv, wv4);
                    ffma2(acc[rr][5], vv, wv5);
                    ffma2(acc[rr][6], vv, wv6);
                    ffma2(acc[rr][7], vv, wv7);
                }
            }
        }
        if (more) {
            sts(b ^ 1);
            __syncthreads();
        }
    }

    const int xo = ox0 + tx;
    if (xo < Wout) {
#pragma unroll
        for (int rr = 0; rr < 2; rr++) {
            int yo = oy0 + ty * 2 + rr;
            if (yo < Hout) {
#pragma unroll
                for (int jp = 0; jp < 8; jp++) {
                    float2 f = unpack2(acc[rr][jp]);
                    if (nsplit == 1) {
                        if (do_relu) {
                            f.x = fmaxf(f.x, 0.f);
                            f.y = fmaxf(f.y, 0.f);
                        }
                        out[((size_t)(oc0 + 2 * jp) * Hout + yo) * Wout + xo] = f.x;
                        out[((size_t)(oc0 + 2 * jp + 1) * Hout + yo) * Wout + xo] = f.y;
                    } else {
                        size_t base = (size_t)split * Cout;
                        out[((base + oc0 + 2 * jp) * Hout + yo) * Wout + xo] = f.x;
                        out[((base + oc0 + 2 * jp + 1) * Hout + yo) * Wout + xo] = f.y;
                    }
                }
            }
        }
    }
}

// ---------------------------------------------------------------------------
// 3x3 conv v4 (stride-1, small levels): tile 32x32, 16 oc/block, Cin-split.
// ---------------------------------------------------------------------------
__global__ void __launch_bounds__(256, 2)
conv3x3_v4(const float* __restrict__ in, const float* __restrict__ w,
           float* __restrict__ out, int Cin, int Hin, int Win,
           int Hout, int Wout, int do_relu, int nsplit, int nOcG, int Cout) {
    constexpr int TW = 32, TH = 32, OCB = 16;
    constexpr int IW = TW + 2, IH = TH + 2;
    constexpr int NPIX = IH * IW;
    constexpr int NLD = (NPIX + 255) / 256;
    __shared__ float sIn[2][NPIX];
    __shared__ __align__(16) float sW[2][9][OCB];

    const int tid = threadIdx.x;
    const int tx = tid & 31, ty = tid >> 5;
    const int ocg = blockIdx.z % nOcG, split = blockIdx.z / nOcG;
    const int oc0 = ocg * OCB;
    const int cs = Cin / nsplit;
    const int ci0 = split * cs;
    const int ox0 = blockIdx.x * TW, oy0 = blockIdx.y * TH;
    const int ix0 = ox0 - 1, iy0 = oy0 - 1;
    const bool interior =
        (ix0 >= 0) && (iy0 >= 0) && (ix0 + IW <= Win) && (iy0 + IH <= Hin);

    float rbuf[NLD];
    float wreg = 0.f;
    const int wj = tid & 15, wt = tid >> 4;

    auto fetch = [&](int ci) {
        const float* inp = in + (size_t)ci * Hin * Win;
        if (interior) {
#pragma unroll
            for (int l = 0; l < NLD; l++) {
                int idx = tid + l * 256;
                if (idx < NPIX) {
                    int r = idx / IW, c = idx % IW;
                    rbuf[l] = __ldg(&inp[(iy0 + r) * Win + ix0 + c]);
                }
            }
        } else {
#pragma unroll
            for (int l = 0; l < NLD; l++) {
                int idx = tid + l * 256;
                if (idx < NPIX) {
                    int r = idx / IW, c = idx % IW;
                    int gy = iy0 + r, gx = ix0 + c;
                    float v = 0.f;
                    if (gy >= 0 && gy < Hin && gx >= 0 && gx < Win)
                        v = inp[gy * Win + gx];
                    rbuf[l] = v;
                }
            }
        }
        if (tid < 144) wreg = w[((size_t)(oc0 + wj) * Cin + ci) * 9 + wt];
    };
    auto sts = [&](int b) {
#pragma unroll
        for (int l = 0; l < NLD; l++) {
            int idx = tid + l * 256;
            if (idx < NPIX) sIn[b][idx] = rbuf[l];
        }
        if (tid < 144) sW[b][wt][wj] = wreg;
    };

    unsigned long long acc[4][8];
#pragma unroll
    for (int r = 0; r < 4; r++)
#pragma unroll
        for (int jp = 0; jp < 8; jp++) acc[r][jp] = 0ull;

    fetch(ci0);
    sts(0);
    __syncthreads();

    for (int i = 0; i < cs; i++) {
        const int b = i & 1;
        const bool more = (i + 1 < cs);
        if (more) fetch(ci0 + i + 1);

#pragma unroll
        for (int ky = 0; ky < 3; ky++) {
#pragma unroll
            for (int kx = 0; kx < 3; kx++) {
                const int t = ky * 3 + kx;
                const longlong2* wp2 = (const longlong2*)&sW[b][t][0];
                longlong2 q0 = wp2[0], q1 = wp2[1], q2 = wp2[2], q3 = wp2[3];
                unsigned long long wv0 = (unsigned long long)q0.x,
                                  wv1 = (unsigned long long)q0.y,
                                  wv2 = (unsigned long long)q1.x,
                                  wv3 = (unsigned long long)q1.y,
                                  wv4 = (unsigned long long)q2.x,
                                  wv5 = (unsigned long long)q2.y,
                                  wv6 = (unsigned long long)q3.x,
                                  wv7 = (unsigned long long)q3.y;
#pragma unroll
                for (int rr = 0; rr < 4; rr++) {
                    float v = sIn[b][(ty * 4 + rr + ky) * IW + tx + kx];
                    unsigned long long vv = dup2(v);
                    ffma2(acc[rr][0], vv, wv0);
                    ffma2(acc[rr][1], vv, wv1);
                    ffma2(acc[rr][2], vv, wv2);
                    ffma2(acc[rr][3], vv, wv3);
                    ffma2(acc[rr][4], vv, wv4);
                    ffma2(acc[rr][5], vv, wv5);
                    ffma2(acc[rr][6], vv, wv6);
                    ffma2(acc[rr][7], vv, wv7);
                }
            }
        }
        if (more) {
            sts(b ^ 1);
            __syncthreads();
        }
    }

    const int xo = ox0 + tx;
    if (xo < Wout) {
#pragma unroll
        for (int rr = 0; rr < 4; rr++) {
            int yo = oy0 + ty * 4 + rr;
            if (yo < Hout) {
#pragma unroll
                for (int jp = 0; jp < 8; jp++) {
                    float2 f = unpack2(acc[rr][jp]);
                    if (nsplit == 1) {
                        if (do_relu) {
                            f.x = fmaxf(f.x, 0.f);
                            f.y = fmaxf(f.y, 0.f);
                        }
                        out[((size_t)(oc0 + 2 * jp) * Hout + yo) * Wout + xo] = f.x;
                        out[((size_t)(oc0 + 2 * jp + 1) * Hout + yo) * Wout + xo] = f.y;
                    } else {
                        size_t base = (size_t)split * Cout;
                        out[((base + oc0 + 2 * jp) * Hout + yo) * Wout + xo] = f.x;
                        out[((base + oc0 + 2 * jp + 1) * Hout + yo) * Wout + xo] = f.y;
                    }
                }
            }
        }
    }
}

// Deterministic fixed-order reduction over Cin-splits (+ optional relu).
__global__ void reduce_split_kernel(const float* __restrict__ part,
                                    float* __restrict__ out, int n, int nsplit,
                                    int do_relu) {
    int i = blockIdx.x * blockDim.x + threadIdx.x;
    if (i >= n) return;
    float acc = 0.f;
    for (int s = 0; s < nsplit; s++) acc += part[(size_t)s * n + i];
    if (do_relu) acc = fmaxf(acc, 0.f);
    out[i] = acc;
}

// ---------------------------------------------------------------------------
// Winograd F(2x2,3x3) for big stride-1 convs (Cin=Cout=256, pad 1).
//   U = G g G^T  (4x4 per (oc,ci)), stored U[k][ci][oc]
//   V = B^T d B  (4x4 per (ci,tile)), stored V[k][ci][tile]
//   M[k] = U[k]^T-free GEMM: M[k][oc][tile] = sum_ci U[k][ci][oc]*V[k][ci][tile]
//   Y = A^T M A  (2x2 per (oc,tile))
// ---------------------------------------------------------------------------
__global__ void wino_weight_kernel(const float* __restrict__ w,
                                   float* __restrict__ U) {
    int idx = blockIdx.x * blockDim.x + threadIdx.x;
    if (idx >= 65536) return;
    int oc = idx & 255, ci = idx >> 8;
    const float* g = w + ((size_t)oc * 256 + ci) * 9;
    float g00 = g[0], g01 = g[1], g02 = g[2];
    float g10 = g[3], g11 = g[4], g12 = g[5];
    float g20 = g[6], g21 = g[7], g22 = g[8];
    // t = G g (4x3)
    float t0[3] = {g00, g01, g02};
    float t1[3] = {0.5f * (g00 + g10 + g20), 0.5f * (g01 + g11 + g21),
                   0.5f * (g02 + g12 + g22)};
    float t2[3] = {0.5f * (g00 - g10 + g20), 0.5f * (g01 - g11 + g21),
                   0.5f * (g02 - g12 + g22)};
    float t3[3] = {g20, g21, g22};
    float* rows[4] = {t0, t1, t2, t3};
    float u[16];
#pragma unroll
    for (int r = 0; r < 4; r++) {
        float* t = rows[r];
        u[r * 4 + 0] = t[0];
        u[r * 4 + 1] = 0.5f * (t[0] + t[1] + t[2]);
        u[r * 4 + 2] = 0.5f * (t[0] - t[1] + t[2]);
        u[r * 4 + 3] = t[2];
    }
#pragma unroll
    for (int k = 0; k < 16; k++)
        U[(size_t)k * 65536 + ci * 256 + oc] = u[k];
}

__global__ void wino_input_kernel(const float* __restrict__ in,
                                  float* __restrict__ V, int H, int tpr,
                                  int ntiles) {
    int idx = blockIdx.x * blockDim.x + threadIdx.x;
    if (idx >= 256 * ntiles) return;
    int tile = idx % ntiles, ci = idx / ntiles;
    int ty = tile / tpr, tx = tile % tpr;
    const float* inp = in + (size_t)ci * H * H;
    int iy0 = ty * 2 - 1, ix0 = tx * 2 - 1;
    float d[4][4];
#pragma unroll
    for (int r = 0; r < 4; r++) {
        int iy = iy0 + r;
#pragma unroll
        for (int c = 0; c < 4; c++) {
            int ix = ix0 + c;
            d[r][c] = (iy >= 0 && iy < H && ix >= 0 && ix < H) ? inp[iy * H + ix]
                                                               : 0.f;
        }
    }
    // e = B^T d
    float e[4][4];
#pragma unroll
    for (int c = 0; c < 4; c++) {
        e[0][c] = d[0][c] - d[2][c];
        e[1][c] = d[1][c] + d[2][c];
        e[2][c] = d[2][c] - d[1][c];
        e[3][c] = d[1][c] - d[3][c];
    }
    // v = e B
    float v[16];
#pragma unroll
    for (int r = 0; r < 4; r++) {
        v[r * 4 + 0] = e[r][0] - e[r][2];
        v[r * 4 + 1] = e[r][1] + e[r][2];
        v[r * 4 + 2] = e[r][2] - e[r][1];
        v[r * 4 + 3] = e[r][1] - e[r][3];
    }
    size_t base = (size_t)ci * ntiles + tile;
    size_t kstride = (size_t)256 * ntiles;
#pragma unroll
    for (int k = 0; k < 16; k++) V[base + (size_t)k * kstride] = v[k];
}

// Batched GEMM: M[k][oc][tile] = sum_ci U[k][ci][oc] * V[k][ci][tile].
__global__ void wino_gemm_kernel(const float* __restrict__ U,
                                 const float* __restrict__ V,
                                 float* __restrict__ M, int ntiles) {
    constexpr int BM = 64, BN = 64, BK = 16;
    __shared__ float sA[BK][BM + 1];
    __shared__ __align__(16) float sB[BK][BN + 2];
    const int tid = threadIdx.x;
    const int trow = tid / 16, tcol = tid % 16;
    const int bn0 = blockIdx.x * BN, bm0 = blockIdx.y * BM;
    const int k = blockIdx.z;
    const float* A = U + (size_t)k * 65536;
    const float* B = V + (size_t)k * 256 * ntiles;
    float* C = M + (size_t)k * 256 * ntiles;

    unsigned long long acc2[4][2];
#pragma unroll
    for (int i = 0; i < 4; i++) { acc2[i][0] = 0ull; acc2[i][1] = 0ull; }

    for (int k0 = 0; k0 < 256; k0 += BK) {
#pragma unroll
        for (int l = 0; l < 4; l++) {
            int e = tid + l * 256;
            int ar = e & 63, ac = e >> 6;
            sA[ac][ar] = A[(size_t)(k0 + ac) * 256 + bm0 + ar];
        }
#pragma unroll
        for (int l = 0; l < 4; l++) {
            int e = tid + l * 256;
            int bc = e & 63, br = e >> 6;
            int n = bn0 + bc;
            sB[br][bc] = (n < ntiles) ? B[(size_t)(k0 + br) * ntiles + n] : 0.f;
        }
        __syncthreads();
#pragma unroll
        for (int kk = 0; kk < BK; kk++) {
            unsigned long long b0 = *(const unsigned long long*)&sB[kk][tcol * 4];
            unsigned long long b1 = *(const unsigned long long*)&sB[kk][tcol * 4 + 2];
#pragma unroll
            for (int i = 0; i < 4; i++) {
                unsigned long long vv = dup2(sA[kk][trow * 4 + i]);
                ffma2(acc2[i][0], vv, b0);
                ffma2(acc2[i][1], vv, b1);
            }
        }
        __syncthreads();
    }
#pragma unroll
    for (int i = 0; i < 4; i++) {
        int r = bm0 + trow * 4 + i;
#pragma unroll
        for (int jp = 0; jp < 2; jp++) {
            int c = bn0 + tcol * 4 + 2 * jp;
            float2 f = unpack2(acc2[i][jp]);
            if (c < ntiles) C[(size_t)r * ntiles + c] = f.x;
            if (c + 1 < ntiles) C[(size_t)r * ntiles + c + 1] = f.y;
        }
    }
}

__global__ void wino_output_kernel(const float* __restrict__ M,
                                   float* __restrict__ out, int H, int tpr,
                                   int ntiles, int do_relu) {
    int idx = blockIdx.x * blockDim.x + threadIdx.x;
    if (idx >= 256 * ntiles) return;
    int tile = idx % ntiles, oc = idx / ntiles;
    size_t base = (size_t)oc * ntiles + tile;
    size_t kstride = (size_t)256 * ntiles;
    float m[16];
#pragma unroll
    for (int k = 0; k < 16; k++) m[k] = M[base + (size_t)k * kstride];
    // f = A^T m  (2x4)
    float f0[4], f1[4];
#pragma unroll
    for (int c = 0; c < 4; c++) {
        f0[c] = m[0 * 4 + c] + m[1 * 4 + c] + m[2 * 4 + c];
        f1[c] = m[1 * 4 + c] - m[2 * 4 + c] - m[3 * 4 + c];
    }
    float y00 = f0[0] + f0[1] + f0[2];
    float y01 = f0[1] - f0[2] - f0[3];
    float y10 = f1[0] + f1[1] + f1[2];
    float y11 = f1[1] - f1[2] - f1[3];
    if (do_relu) {
        y00 = fmaxf(y00, 0.f);
        y01 = fmaxf(y01, 0.f);
        y10 = fmaxf(y10, 0.f);
        y11 = fmaxf(y11, 0.f);
    }
    int ty = tile / tpr, tx = tile % tpr;
    float* o = out + (size_t)oc * H * H + (ty * 2) * H + tx * 2;
    o[0] = y00;
    o[1] = y01;
    o[H] = y10;
    o[H + 1] = y11;
}

// ---------------------------------------------------------------------------
// Fused RPN head: 1x1 cls (3) + 1x1 box (12) + anchor decode.
// ---------------------------------------------------------------------------
__global__ void rpn_head_kernel(const float* __restrict__ t,
                                const float* __restrict__ cls_w,
                                const float* __restrict__ box_w,
                                int HW, int fw, float stride, float size,
                                float* __restrict__ dec_boxes,
                                float* __restrict__ dec_scores) {
    __shared__ float sCW[3][256];
    __shared__ float sBW[12][256];
    const int tid = threadIdx.x;
    for (int idx = tid; idx < 3 * 256; idx += 256) sCW[idx >> 8][idx & 255] = cls_w[idx];
    for (int idx = tid; idx < 12 * 256; idx += 256) sBW[idx >> 8][idx & 255] = box_w[idx];
    __syncthreads();

    const int p = blockIdx.x * 256 + tid;
    if (p >= HW) return;

    float accC[3] = {0.f, 0.f, 0.f};
    float accB[12];
#pragma unroll
    for (int j = 0; j < 12; j++) accB[j] = 0.f;

    for (int ci = 0; ci < 256; ci++) {
        float v = t[(size_t)ci * HW + p];
#pragma unroll
        for (int j = 0; j < 3; j++) accC[j] += v * sCW[j][ci];
#pragma unroll
        for (int j = 0; j < 12; j++) accB[j] += v * sBW[j][ci];
    }

    const int x = p % fw, y = p / fw;
    const double wm[3] = {1.4142135623730951, 1.0, 0.7071067811865476};
    const double hm[3] = {0.7071067811865476, 1.0, 1.4142135623730951};
    float acx = (x + 0.5f) * stride;
    float acy = (y + 0.5f) * stride;

#pragma unroll
    for (int a = 0; a < 3; a++) {
        float aw = (float)(size * wm[a]);
        float ah = (float)(size * hm[a]);
        float d0 = accB[a * 4 + 0];
        float d1 = accB[a * 4 + 1];
        float dw = fminf(fmaxf(accB[a * 4 + 2], -4.f), 4.f);
        float dh = fminf(fmaxf(accB[a * 4 + 3], -4.f), 4.f);
        float cx = acx + d0 * aw;
        float cy = acy + d1 * ah;
        float w = aw * expf(dw);
        float h = ah * expf(dh);
        int i = p * 3 + a;
        dec_boxes[i * 4 + 0] = fminf(fmaxf(cx - w * 0.5f, 0.f), 800.f);
        dec_boxes[i * 4 + 1] = fminf(fmaxf(cy - h * 0.5f, 0.f), 800.f);
        dec_boxes[i * 4 + 2] = fminf(fmaxf(cx + w * 0.5f, 0.f), 800.f);
        dec_boxes[i * 4 + 3] = fminf(fmaxf(cy + h * 0.5f, 0.f), 800.f);
        dec_scores[i] = accC[a];
    }
}

// ---------------------------------------------------------------------------
// Top-k (k = 1000): 4 levels in ONE launch, one block per level.
// ---------------------------------------------------------------------------
__device__ __forceinline__ unsigned keyof(float f) {
    unsigned u = __float_as_uint(f);
    return (u & 0x80000000u) ? ~u : (u | 0x80000000u);
}

__global__ void topk4_kernel(const float* __restrict__ all_scores,
                             const float* __restrict__ all_boxes,
                             const int4 offs, const int4 lens,
                             float* __restrict__ out_scores4k,
                             float* __restrict__ out_boxes4k) {
    const int lvl = blockIdx.x;
    const int off = (lvl == 0) ? offs.x : (lvl == 1) ? offs.y : (lvl == 2) ? offs.z : offs.w;
    const int n   = (lvl == 0) ? lens.x : (lvl == 1) ? lens.y : (lvl == 2) ? lens.z : lens.w;
    const int k = 1000;
    const float* scores = all_scores + off;
    const float* boxes = all_boxes + (size_t)off * 4;
    float* out_scores = out_scores4k + lvl * 1000;
    float* out_boxes = out_boxes4k + lvl * 4000;

    __shared__ unsigned hist[256];
    __shared__ unsigned sh_prefix, sh_kk, sh_cgt, sh_ceq;
    int tid = threadIdx.x;
    int NT = blockDim.x;
    if (tid == 0) { sh_prefix = 0; sh_kk = (unsigned)k; }
    unsigned mask = 0;
    __syncthreads();
    for (int shift = 24; shift >= 0; shift -= 8) {
        for (int b = tid; b < 256; b += NT) hist[b] = 0;
        __syncthreads();
        unsigned prefix = sh_prefix;
        for (int i = tid; i < n; i += NT) {
            unsigned key = keyof(scores[i]);
            if ((key & mask) == prefix) atomicAdd(&hist[(key >> shift) & 255], 1u);
        }
        __syncthreads();
        if (tid == 0) {
            unsigned kk = sh_kk, cum = 0;
            int b = 255;
            for (; b > 0; b--) {
                if (cum + hist[b] >= kk) break;
                cum += hist[b];
            }
            sh_prefix = prefix | ((unsigned)b << shift);
            sh_kk = kk - cum;
        }
        mask |= (0xFFu << shift);
        __syncthreads();
    }
    unsigned T = sh_prefix;
    unsigned kk = sh_kk;
    if (tid == 0) { sh_cgt = 0; sh_ceq = 0; }
    __syncthreads();
    int gtcount = k - (int)kk;
    for (int i = tid; i < n; i += NT) {
        unsigned key = keyof(scores[i]);
        int slot = -1;
        if (key > T) {
            slot = (int)atomicAdd(&sh_cgt, 1u);
        } else if (key == T) {
            unsigned e = atomicAdd(&sh_ceq, 1u);
            if (e < kk) slot = gtcount + (int)e;
        }
        if (slot >= 0) {
            out_scores[slot] = scores[i];
            out_boxes[slot * 4 + 0] = boxes[i * 4 + 0];
            out_boxes[slot * 4 + 1] = boxes[i * 4 + 1];
            out_boxes[slot * 4 + 2] = boxes[i * 4 + 2];
            out_boxes[slot * 4 + 3] = boxes[i * 4 + 3];
        }
    }
}

// ---------------------------------------------------------------------------
// NMS: one block, 512 threads, 512 sequential selections over 4000 candidates.
// ---------------------------------------------------------------------------
__global__ void nms_kernel(const float* __restrict__ boxes, const float* __restrict__ scores,
                           float* __restrict__ props, float* __restrict__ out_props,
                           float* __restrict__ out_scores) {
    constexpr int N = 4000, NT = 512, POST = 512;
    extern __shared__ float sm[];
    float* sx1 = sm;
    float* sy1 = sm + N;
    float* sx2 = sm + 2 * N;
    float* sy2 = sm + 3 * N;
    float* sar = sm + 4 * N;
    float* ss  = sm + 5 * N;
    __shared__ float rv[NT / 32];
    __shared__ int ri[NT / 32];
    __shared__ int s_best;

    int tid = threadIdx.x;
    for (int i = tid; i < N; i += NT) {
        float a = boxes[i * 4 + 0], b = boxes[i * 4 + 1];
        float c = boxes[i * 4 + 2], d = boxes[i * 4 + 3];
        sx1[i] = a; sy1[i] = b; sx2[i] = c; sy2[i] = d;
        sar[i] = (c - a) * (d - b);
        ss[i] = scores[i];
    }
    __syncthreads();

    for (int it = 0; it < POST; it++) {
        float bv = -INFINITY;
        int bi = 0x7FFFFFFF;
        for (int i = tid; i < N; i += NT) {
            float v = ss[i];
            if (v > bv || (v == bv && i < bi)) { bv = v; bi = i; }
        }
#pragma unroll
        for (int off = 16; off; off >>= 1) {
            float ov = __shfl_down_sync(0xFFFFFFFFu, bv, off);
            int oi = __shfl_down_sync(0xFFFFFFFFu, bi, off);
            if (ov > bv || (ov == bv && oi < bi)) { bv = ov; bi = oi; }
        }
        if ((tid & 31) == 0) { rv[tid >> 5] = bv; ri[tid >> 5] = bi; }
        __syncthreads();
        if (tid == 0) {
            float fbv = rv[0]; int fbi = ri[0];
            for (int wz = 1; wz < NT / 32; wz++) {
                float ov = rv[wz]; int oi = ri[wz];
                if (ov > fbv || (ov == fbv && oi < fbi)) { fbv = ov; fbi = oi; }
            }
            s_best = fbi;
        }
        __syncthreads();
        int idx = s_best;
        if (tid == 0) {
            float a = sx1[idx], b = sy1[idx], c = sx2[idx], d = sy2[idx];
            props[it * 4 + 0] = a; props[it * 4 + 1] = b;
            props[it * 4 + 2] = c; props[it * 4 + 3] = d;
            out_props[it * 4 + 0] = a; out_props[it * 4 + 1] = b;
            out_props[it * 4 + 2] = c; out_props[it * 4 + 3] = d;
            out_scores[it] = scores[idx];
        }
        float X1 = sx1[idx], Y1 = sy1[idx], X2 = sx2[idx], Y2 = sy2[idx], AR = sar[idx];
        for (int i = tid; i < N; i += NT) {
            float ix1 = fmaxf(sx1[i], X1), iy1 = fmaxf(sy1[i], Y1);
            float ix2 = fminf(sx2[i], X2), iy2 = fminf(sy2[i], Y2);
            float inter = fmaxf(ix2 - ix1, 0.f) * fmaxf(iy2 - iy1, 0.f);
            float iou = inter / (sar[i] + AR - inter + 1e-6f);
            if (iou > 0.7f) ss[i] = -INFINITY;
        }
        __syncthreads();
    }
}

// ---------------------------------------------------------------------------
// ROI Align on feats[0] (256, 200, 200), scale 0.25, POOL 7.
// ---------------------------------------------------------------------------
__global__ void roi_align_kernel(const float* __restrict__ feat, const float* __restrict__ rois,
                                 float* __restrict__ out) {
    __shared__ int six0[49], siy0[49], six1[49], siy1[49];
    __shared__ float swx[49], swy[49];
    int roi = blockIdx.x;
    int c = threadIdx.x;
    if (threadIdx.x < 49) {
        int p = threadIdx.x;
        int py = p / 7, px = p % 7;
        float r0 = rois[roi * 4 + 0] * 0.25f;
        float r1 = rois[roi * 4 + 1] * 0.25f;
        float bw = (rois[roi * 4 + 2] - rois[roi * 4 + 0]) * 0.25f / 7.0f;
        float bh = (rois[roi * 4 + 3] - rois[roi * 4 + 1]) * 0.25f / 7.0f;
        float gx = r0 + (px + 0.5f) * bw - 0.5f;
        float gy = r1 + (py + 0.5f) * bh - 0.5f;
        float fx = fminf(fmaxf(floorf(gx), 0.f), 199.f);
        float fy = fminf(fmaxf(floorf(gy), 0.f), 199.f);
        int x0 = (int)fx, y0 = (int)fy;
        six0[p] = x0; siy0[p] = y0;
        six1[p] = min(x0 + 1, 199);
        siy1[p] = min(y0 + 1, 199);
        swx[p] = fminf(fmaxf(gx - fx, 0.f), 1.f);
        swy[p] = fminf(fmaxf(gy - fy, 0.f), 1.f);
    }
    __syncthreads();
    const float* f = feat + (size_t)c * 40000;
    float* o = out + (size_t)roi * 12544 + (size_t)c * 49;
#pragma unroll 7
    for (int p = 0; p < 49; p++) {
        int x0 = six0[p], y0 = siy0[p], x1 = six1[p], y1 = siy1[p];
        float wx = swx[p], wy = swy[p];
        float v00 = f[y0 * 200 + x0];
        float v01 = f[y0 * 200 + x1];
        float v10 = f[y1 * 200 + x0];
        float v11 = f[y1 * 200 + x1];
        o[p] = v00 * (1.f - wy) * (1.f - wx) + v01 * (1.f - wy) * wx +
               v10 * wy * (1.f - wx) + v11 * wy * wx;
    }
}

// ---------------------------------------------------------------------------
// SGEMM: C = relu(A @ B + bias). f32x2 over N-column pairs.
// ---------------------------------------------------------------------------
__global__ void sgemm_bias_relu(const float* __restrict__ A, const float* __restrict__ B,
                                const float* __restrict__ bias, float* __restrict__ C,
                                int M, int N, int K, int do_relu) {
    constexpr int BM = 64, BN = 64, BK = 16;
    __shared__ float sA[BK][BM + 1];
    __shared__ __align__(16) float sB[BK][BN + 2];
    int tid = threadIdx.x;
    int trow = tid / 16, tcol = tid % 16;
    int bm0 = blockIdx.y * BM, bn0 = blockIdx.x * BN;
    unsigned long long acc2[4][2];
#pragma unroll
    for (int i = 0; i < 4; i++) { acc2[i][0] = 0ull; acc2[i][1] = 0ull; }

    for (int k0 = 0; k0 < K; k0 += BK) {
#pragma unroll
        for (int l = 0; l < 4; l++) {
            int e = tid + l * 256;
            int ar = e / BK, ac = e % BK;
            sA[ac][ar] = A[(size_t)(bm0 + ar) * K + k0 + ac];
        }
#pragma unroll
        for (int l = 0; l < 4; l++) {
            int e = tid + l * 256;
            int br = e >> 6, bc = e & 63;
            sB[br][bc] = B[(size_t)(k0 + br) * N + bn0 + bc];
        }
        __syncthreads();
#pragma unroll
        for (int kk = 0; kk < BK; kk++) {
            unsigned long long b0 = *(const unsigned long long*)&sB[kk][tcol * 4];
            unsigned long long b1 = *(const unsigned long long*)&sB[kk][tcol * 4 + 2];
#pragma unroll
            for (int i = 0; i < 4; i++) {
                unsigned long long vv = dup2(sA[kk][trow * 4 + i]);
                ffma2(acc2[i][0], vv, b0);
                ffma2(acc2[i][1], vv, b1);
            }
        }
        __syncthreads();
    }
#pragma unroll
    for (int i = 0; i < 4; i++) {
        int r = bm0 + trow * 4 + i;
#pragma unroll
        for (int jp = 0; jp < 2; jp++) {
            int cidx = bn0 + tcol * 4 + 2 * jp;
            float2 f = unpack2(acc2[i][jp]);
            f.x += bias[cidx];
            f.y += bias[cidx + 1];
            if (do_relu) { f.x = fmaxf(f.x, 0.f); f.y = fmaxf(f.y, 0.f); }
            C[(size_t)r * N + cidx] = f.x;
            C[(size_t)r * N + cidx + 1] = f.y;
        }
    }
}

// ---------------------------------------------------------------------------
// Final heads: cls (1024->2) and breg (1024->8), write directly to d_out.
// ---------------------------------------------------------------------------
__global__ void head_kernel(const float* __restrict__ A, const float* __restrict__ cw,
                            const float* __restrict__ cb, const float* __restrict__ bw,
                            const float* __restrict__ bb, float* __restrict__ out) {
    int m = blockIdx.x;
    int j = threadIdx.x;
    if (j >= 10) return;
    const float* a = A + (size_t)m * 1024;
    bool is_cls = (j < 2);
    const float* W = is_cls ? cw : bw;
    int n = is_cls ? j : j - 2;
    int N = is_cls ? 2 : 8;
    float acc = 0.f;
    for (int k = 0; k < 1024; k++) acc += a[k] * W[(size_t)k * N + n];
    acc += is_cls ? cb[n] : bb[n];
    if (is_cls) out[m * 2 + n] = acc;
    else out[1024 + m * 8 + n] = acc;
}

// ---------------------------------------------------------------------------
// Host: launch sequence
// ---------------------------------------------------------------------------
static inline void* symaddr(const void* sym) {
    void* p = nullptr;
    cudaGetSymbolAddress(&p, sym);
    return p;
}

static inline int ceil_div(int a, int b) { return (a + b - 1) / b; }

extern "C" void kernel_launch(void* const* d_in, const int* in_sizes, int n_in,
                              void* d_out, int out_size) {
    const float* x       = (const float*)d_in[0];
    const float* stem_w  = (const float*)d_in[1];
    const float* c2_w    = (const float*)d_in[2];
    const float* c3_w    = (const float*)d_in[3];
    const float* c4_w    = (const float*)d_in[4];
    const float* c5_w    = (const float*)d_in[5];
    const float* fpn_w[4] = {(const float*)d_in[6], (const float*)d_in[7],
                             (const float*)d_in[8], (const float*)d_in[9]};
    const float* rpn_w     = (const float*)d_in[10];
    const float* rpn_cls_w = (const float*)d_in[11];
    const float* rpn_box_w = (const float*)d_in[12];
    const float* fc1_w = (const float*)d_in[13];
    const float* fc1_b = (const float*)d_in[14];
    const float* fc2_w = (const float*)d_in[15];
    const float* fc2_b = (const float*)d_in[16];
    const float* cls_w = (const float*)d_in[17];
    const float* cls_b = (const float*)d_in[18];
    const float* breg_w = (const float*)d_in[19];
    const float* breg_b = (const float*)d_in[20];
    float* out = (float*)d_out;

    float* p_stem = (float*)symaddr(g_stem);
    float* p_c2   = (float*)symaddr(g_c2);
    float* p_c3   = (float*)symaddr(g_c3);
    float* p_c4   = (float*)symaddr(g_c4);
    float* p_c5   = (float*)symaddr(g_c5);
    float* p_f[4] = {(float*)symaddr(g_f2), (float*)symaddr(g_f3),
                     (float*)symaddr(g_f4), (float*)symaddr(g_f5)};
    float* p_t    = (float*)symaddr(g_t);
    float* p_part = (float*)symaddr(g_part);
    float* p_U    = (float*)symaddr(g_winoU);
    float* p_V    = (float*)symaddr(g_winoV);
    float* p_M    = (float*)symaddr(g_winoM);
    float* p_decb = (float*)symaddr(g_decb);
    float* p_decs = (float*)symaddr(g_decs);
    float* p_b4k  = (float*)symaddr(g_boxes4k);
    float* p_s4k  = (float*)symaddr(g_scores4k);
    float* p_props = (float*)symaddr(g_props);
    float* p_pool = (float*)symaddr(g_pooled);
    float* p_fc1  = (float*)symaddr(g_fc1);
    float* p_fc2  = (float*)symaddr(g_fc2);

    const int fh[4] = {200, 100, 50, 25};
    const int ksv4[4] = {2, 2, 8, 16};  // Cin-splits for small stride-1 convs
    const int doff[4] = {0, 120000, 150000, 157500};  // decode region offsets

    // Winograd helper (Cin=Cout=256, pad 1, H even)
    auto wino_conv = [&](const float* in, const float* w, float* outp, int H,
                         int relu) {
        int tpr = H / 2, ntiles = tpr * tpr;
        wino_weight_kernel<<<256, 256>>>(w, p_U);
        wino_input_kernel<<<ceil_div(256 * ntiles, 256), 256>>>(in, p_V, H, tpr,
                                                                ntiles);
        wino_gemm_kernel<<<dim3(ceil_div(ntiles, 64), 4, 16), 256>>>(p_U, p_V, p_M,
                                                                     ntiles);
        wino_output_kernel<<<ceil_div(256 * ntiles, 256), 256>>>(p_M, outp, H, tpr,
                                                                 ntiles, relu);
    };

    // 1. stem 7x7 s2 with fused normalize
    stem_v2<<<dim3(13, 50, 4), 128>>>(x, stem_w, p_stem);

    // 2. backbone strided 3x3 convs (relu) — v3 path
    conv3x3_v3<2, 0><<<dim3(7, 13, 16), 256>>>(p_stem, c2_w, p_c2, 64, 400, 400,
                                               200, 200, 1, 1, 16, 256);
    conv3x3_v3<2, 0><<<dim3(4, 7, 16 * 4), 256>>>(p_c2, c3_w, p_part, 256, 200, 200,
                                                  100, 100, 1, 4, 16, 256);
    reduce_split_kernel<<<ceil_div(256 * 10000, 256), 256>>>(p_part, p_c3,
                                                             256 * 10000, 4, 1);
    conv3x3_v3<2, 0><<<dim3(2, 4, 16 * 8), 256>>>(p_c3, c4_w, p_part, 256, 100, 100,
                                                  50, 50, 1, 8, 16, 256);
    reduce_split_kernel<<<ceil_div(256 * 2500, 256), 256>>>(p_part, p_c4,
                                                            256 * 2500, 8, 1);
    conv3x3_v3<2, 0><<<dim3(1, 2, 16 * 16), 256>>>(p_c4, c5_w, p_part, 256, 50, 50,
                                                   25, 25, 1, 16, 16, 256);
    reduce_split_kernel<<<ceil_div(256 * 625, 256), 256>>>(p_part, p_c5,
                                                           256 * 625, 16, 1);

    // 3. FPN lateral convs (no relu): Winograd for levels 0-1, v4 for 2-3
    const float* csrc[4] = {p_c2, p_c3, p_c4, p_c5};
    for (int l = 0; l < 4; l++) {
        int H = fh[l], HW = H * H;
        if (l < 2) {
            wino_conv(csrc[l], fpn_w[l], p_f[l], H, 0);
        } else {
            int k = ksv4[l];
            dim3 g(ceil_div(H, 32), ceil_div(H, 32), 16 * k);
            conv3x3_v4<<<g, 256>>>(csrc[l], fpn_w[l], p_part, 256, H, H, H, H,
                                   0, k, 16, 256);
            reduce_split_kernel<<<ceil_div(256 * HW, 256), 256>>>(p_part, p_f[l],
                                                                  256 * HW, k, 0);
        }
    }

    // 4. RPN per level: conv-relu (wino/v4), fused head+decode
    const float strides[4] = {4.f, 8.f, 16.f, 32.f};
    const float sizes[4] = {32.f, 64.f, 128.f, 256.f};
    for (int l = 0; l < 4; l++) {
        int H = fh[l], HW = H * H;
        if (l < 2) {
            wino_conv(p_f[l], rpn_w, p_t, H, 1);
        } else {
            int k = ksv4[l];
            dim3 g(ceil_div(H, 32), ceil_div(H, 32), 16 * k);
            conv3x3_v4<<<g, 256>>>(p_f[l], rpn_w, p_part, 256, H, H, H, H,
                                   1, k, 16, 256);
            reduce_split_kernel<<<ceil_div(256 * HW, 256), 256>>>(p_part, p_t,
                                                                  256 * HW, k, 1);
        }
        rpn_head_kernel<<<ceil_div(HW, 256), 256>>>(p_t, rpn_cls_w, rpn_box_w,
                                                    HW, H, strides[l], sizes[l],
                                                    p_decb + (size_t)doff[l] * 4,
                                                    p_decs + doff[l]);
    }

    // 5. Combined top-1000 over 4 levels (one launch, 4 blocks)
    {
        int4 offs = make_int4(doff[0], doff[1], doff[2], doff[3]);
        int4 lens = make_int4(120000, 30000, 7500, 1875);
        topk4_kernel<<<4, 1024>>>(p_decs, p_decb, offs, lens, p_s4k, p_b4k);
    }

    // 6. NMS (512 out of 4000)
    cudaFuncSetAttribute(nms_kernel, cudaFuncAttributeMaxDynamicSharedMemorySize, 96000);
    nms_kernel<<<1, 512, 96000>>>(p_b4k, p_s4k, p_props, out + 5120, out + 7168);

    // 7. ROI align on feats[0]
    roi_align_kernel<<<512, 256>>>(p_f[0], p_props, p_pool);

    // 8. FC head
    sgemm_bias_relu<<<dim3(1024 / 64, 512 / 64), 256>>>(p_pool, fc1_w, fc1_b, p_fc1,
                                                        512, 1024, 12544, 1);
    sgemm_bias_relu<<<dim3(1024 / 64, 512 / 64), 256>>>(p_fc1, fc2_w, fc2_b, p_fc2,
                                                        512, 1024, 1024, 1);
    head_kernel<<<512, 32>>>(p_fc2, cls_w, cls_b, breg_w, breg_b, out);
}

// round 12
// speedup vs baseline: 2.5737x; 1.1277x over previous
#include <cuda_runtime.h>
#include <cuda_bf16.h>
#include <math.h>

// ---------------------------------------------------------------------------
// Static scratch (allocation-free rule: __device__ globals)
// ---------------------------------------------------------------------------
__device__ float g_stem[64 * 400 * 400];
__device__ float g_c2[256 * 200 * 200];
__device__ float g_c3[256 * 100 * 100];
__device__ float g_c4[256 * 50 * 50];
__device__ float g_c5[256 * 25 * 25];
__device__ float g_f2[256 * 200 * 200];
__device__ float g_f3[256 * 100 * 100];
__device__ float g_f4[256 * 50 * 50];
__device__ float g_f5[256 * 25 * 25];
__device__ float g_t[256 * 200 * 200];          // RPN hidden, reused per level
__device__ float g_part[2 * 256 * 200 * 200];   // k-split partials (reused)
__device__ float g_winoU[16 * 256 * 256];       // Winograd weight transform (fpn)
__device__ float g_winoUrpn[16 * 256 * 256];    // Winograd weight transform (rpn)
__device__ float g_winoV[16 * 256 * 10000];     // Winograd input transform
__device__ float g_winoM[16 * 256 * 10000];     // Winograd GEMM output
__device__ float g_decb[159375 * 4];            // all levels' decoded boxes
__device__ float g_decs[159375];                // all levels' scores
__device__ float g_boxes4k[4000 * 4];
__device__ float g_scores4k[4000];
__device__ float g_props[512 * 4];
__device__ float g_pooled[512 * 12544];
__device__ float g_fc1[512 * 1024];
__device__ float g_fc2[512 * 1024];

__constant__ float c_mean[3] = {0.485f, 0.456f, 0.406f};
__constant__ float c_std[3]  = {0.229f, 0.224f, 0.225f};

// ---------------------------------------------------------------------------
// Packed f32x2 helpers (Blackwell FFMA2 — ptxas never auto-generates this)
// ---------------------------------------------------------------------------
__device__ __forceinline__ void ffma2(unsigned long long& d, unsigned long long a,
                                      unsigned long long b) {
    asm("fma.rn.f32x2 %0, %1, %2, %0;" : "+l"(d) : "l"(a), "l"(b));
}
__device__ __forceinline__ unsigned long long dup2(float v) {
    unsigned long long r;
    unsigned u = __float_as_uint(v);
    asm("mov.b64 %0, {%1, %1};" : "=l"(r) : "r"(u));
    return r;
}
__device__ __forceinline__ float2 unpack2(unsigned long long v) {
    unsigned lo, hi;
    asm("mov.b64 {%0, %1}, %2;" : "=r"(lo), "=r"(hi) : "l"(v));
    float2 f;
    f.x = __uint_as_float(lo);
    f.y = __uint_as_float(hi);
    return f;
}

// ---------------------------------------------------------------------------
// Stem conv 7x7 s2 (800->400, Cin=3, Cout=64) with fused normalize.
// ---------------------------------------------------------------------------
__global__ void stem_v2(const float* __restrict__ x, const float* __restrict__ w,
                        float* __restrict__ out) {
    constexpr int IH = 21, IW = 69;
    __shared__ float sIn[3][IH][IW];
    __shared__ __align__(16) float sW[3][49][16];

    const int tid = threadIdx.x;
    const int tx = tid & 31, ty = tid >> 5;
    const int ox0 = blockIdx.x * 32, oy0 = blockIdx.y * 8, oc0 = blockIdx.z * 16;
    const int ix0 = ox0 * 2 - 2, iy0 = oy0 * 2 - 2;

    for (int idx = tid; idx < 3 * IH * IW; idx += 128) {
        int ci = idx / (IH * IW);
        int rem = idx % (IH * IW);
        int r = rem / IW, c = rem % IW;
        int gy = iy0 + r, gx = ix0 + c;
        float v = 0.f;
        if (gy >= 0 && gy < 800 && gx >= 0 && gx < 800)
            v = (x[ci * 640000 + gy * 800 + gx] - c_mean[ci]) / c_std[ci];
        sIn[ci][r][c] = v;
    }
    for (int idx = tid; idx < 3 * 49 * 16; idx += 128) {
        int j = idx & 15;
        int t = (idx >> 4) % 49;
        int ci = idx / (49 * 16);
        sW[ci][t][j] = w[(oc0 + j) * 147 + ci * 49 + t];
    }
    __syncthreads();

    unsigned long long acc[2][8];
#pragma unroll
    for (int r = 0; r < 2; r++)
#pragma unroll
        for (int jp = 0; jp < 8; jp++) acc[r][jp] = 0ull;

#pragma unroll 1
    for (int ci = 0; ci < 3; ci++) {
#pragma unroll 1
        for (int ky = 0; ky < 7; ky++) {
#pragma unroll
            for (int kx = 0; kx < 7; kx++) {
                int t = ky * 7 + kx;
                const longlong2* wp2 = (const longlong2*)&sW[ci][t][0];
                longlong2 q0 = wp2[0], q1 = wp2[1], q2 = wp2[2], q3 = wp2[3];
                unsigned long long wv[8] = {
                    (unsigned long long)q0.x, (unsigned long long)q0.y,
                    (unsigned long long)q1.x, (unsigned long long)q1.y,
                    (unsigned long long)q2.x, (unsigned long long)q2.y,
                    (unsigned long long)q3.x, (unsigned long long)q3.y};
#pragma unroll
                for (int r = 0; r < 2; r++) {
                    float v = sIn[ci][(ty * 2 + r) * 2 + ky][tx * 2 + kx];
                    unsigned long long vv = dup2(v);
#pragma unroll
                    for (int jp = 0; jp < 8; jp++) ffma2(acc[r][jp], vv, wv[jp]);
                }
            }
        }
    }

    int xo = ox0 + tx;
    if (xo < 400) {
#pragma unroll
        for (int r = 0; r < 2; r++) {
            int yo = oy0 + ty * 2 + r;
#pragma unroll
            for (int jp = 0; jp < 8; jp++) {
                float2 f = unpack2(acc[r][jp]);
                out[(size_t)(oc0 + 2 * jp) * 160000 + yo * 400 + xo] = fmaxf(f.x, 0.f);
                out[(size_t)(oc0 + 2 * jp + 1) * 160000 + yo * 400 + xo] = fmaxf(f.y, 0.f);
            }
        }
    }
}

// ---------------------------------------------------------------------------
// 3x3 conv v3 (stride-2 path): tile 32x16 out, 16 oc/block, 256 threads,
// 2 px x 16 oc per thread, 2-stage smem pipeline, optional Cin-split.
// ---------------------------------------------------------------------------
template <int S, int PADLO>
__global__ void __launch_bounds__(256, 2)
conv3x3_v3(const float* __restrict__ in, const float* __restrict__ w,
           float* __restrict__ out, int Cin, int Hin, int Win,
           int Hout, int Wout, int do_relu, int nsplit, int nOcG, int Cout) {
    constexpr int TW = 32, TH = 16, OCB = 16;
    constexpr int IW = (TW - 1) * S + 3;
    constexpr int IH = (TH - 1) * S + 3;
    constexpr int NPIX = IH * IW;
    constexpr int NLD = (NPIX + 255) / 256;
    __shared__ float sIn[2][NPIX];
    __shared__ __align__(16) float sW[2][9][OCB];

    const int tid = threadIdx.x;
    const int tx = tid & 31, ty = tid >> 5;
    const int ocg = blockIdx.z % nOcG, split = blockIdx.z / nOcG;
    const int oc0 = ocg * OCB;
    const int cs = Cin / nsplit;
    const int ci0 = split * cs;
    const int ox0 = blockIdx.x * TW, oy0 = blockIdx.y * TH;
    const int ix0 = ox0 * S - PADLO, iy0 = oy0 * S - PADLO;
    const bool interior =
        (ix0 >= 0) && (iy0 >= 0) && (ix0 + IW <= Win) && (iy0 + IH <= Hin);

    float rbuf[NLD];
    float wreg = 0.f;
    const int wj = tid & 15, wt = tid >> 4;

    auto fetch = [&](int ci) {
        const float* inp = in + (size_t)ci * Hin * Win;
        if (interior) {
#pragma unroll
            for (int l = 0; l < NLD; l++) {
                int idx = tid + l * 256;
                if (idx < NPIX) {
                    int r = idx / IW, c = idx % IW;
                    rbuf[l] = __ldg(&inp[(iy0 + r) * Win + ix0 + c]);
                }
            }
        } else {
#pragma unroll
            for (int l = 0; l < NLD; l++) {
                int idx = tid + l * 256;
                if (idx < NPIX) {
                    int r = idx / IW, c = idx % IW;
                    int gy = iy0 + r, gx = ix0 + c;
                    float v = 0.f;
                    if (gy >= 0 && gy < Hin && gx >= 0 && gx < Win)
                        v = inp[gy * Win + gx];
                    rbuf[l] = v;
                }
            }
        }
        if (tid < 144) wreg = w[((size_t)(oc0 + wj) * Cin + ci) * 9 + wt];
    };
    auto sts = [&](int b) {
#pragma unroll
        for (int l = 0; l < NLD; l++) {
            int idx = tid + l * 256;
            if (idx < NPIX) sIn[b][idx] = rbuf[l];
        }
        if (tid < 144) sW[b][wt][wj] = wreg;
    };

    unsigned long long acc[2][8];
#pragma unroll
    for (int r = 0; r < 2; r++)
#pragma unroll
        for (int jp = 0; jp < 8; jp++) acc[r][jp] = 0ull;

    fetch(ci0);
    sts(0);
    __syncthreads();

    for (int i = 0; i < cs; i++) {
        const int b = i & 1;
        const bool more = (i + 1 < cs);
        if (more) fetch(ci0 + i + 1);

#pragma unroll
        for (int ky = 0; ky < 3; ky++) {
#pragma unroll
            for (int kx = 0; kx < 3; kx++) {
                const int t = ky * 3 + kx;
                const longlong2* wp2 = (const longlong2*)&sW[b][t][0];
                longlong2 q0 = wp2[0], q1 = wp2[1], q2 = wp2[2], q3 = wp2[3];
                unsigned long long wv0 = (unsigned long long)q0.x,
                                  wv1 = (unsigned long long)q0.y,
                                  wv2 = (unsigned long long)q1.x,
                                  wv3 = (unsigned long long)q1.y,
                                  wv4 = (unsigned long long)q2.x,
                                  wv5 = (unsigned long long)q2.y,
                                  wv6 = (unsigned long long)q3.x,
                                  wv7 = (unsigned long long)q3.y;
#pragma unroll
                for (int rr = 0; rr < 2; rr++) {
                    float v = sIn[b][((ty * 2 + rr) * S + ky) * IW + tx * S + kx];
                    unsigned long long vv = dup2(v);
                    ffma2(acc[rr][0], vv, wv0);
                    ffma2(acc[rr][1], vv, wv1);
                    ffma2(acc[rr][2], vv, wv2);
                    ffma2(acc[rr][3], vv, wv3);
                    ffma2(acc[rr][4], vv, wv4);
                    ffma2(acc[rr][5], vv, wv5);
                    ffma2(acc[rr][6], vv, wv6);
                    ffma2(acc[rr][7], vv, wv7);
                }
            }
        }
        if (more) {
            sts(b ^ 1);
            __syncthreads();
        }
    }

    const int xo = ox0 + tx;
    if (xo < Wout) {
#pragma unroll
        for (int rr = 0; rr < 2; rr++) {
            int yo = oy0 + ty * 2 + rr;
            if (yo < Hout) {
#pragma unroll
                for (int jp = 0; jp < 8; jp++) {
                    float2 f = unpack2(acc[rr][jp]);
                    if (nsplit == 1) {
                        if (do_relu) {
                            f.x = fmaxf(f.x, 0.f);
                            f.y = fmaxf(f.y, 0.f);
                        }
                        out[((size_t)(oc0 + 2 * jp) * Hout + yo) * Wout + xo] = f.x;
                        out[((size_t)(oc0 + 2 * jp + 1) * Hout + yo) * Wout + xo] = f.y;
                    } else {
                        size_t base = (size_t)split * Cout;
                        out[((base + oc0 + 2 * jp) * Hout + yo) * Wout + xo] = f.x;
                        out[((base + oc0 + 2 * jp + 1) * Hout + yo) * Wout + xo] = f.y;
                    }
                }
            }
        }
    }
}

// ---------------------------------------------------------------------------
// 3x3 conv v4 (stride-1, small levels): tile 32x32, 16 oc/block, Cin-split.
// ---------------------------------------------------------------------------
__global__ void __launch_bounds__(256, 2)
conv3x3_v4(const float* __restrict__ in, const float* __restrict__ w,
           float* __restrict__ out, int Cin, int Hin, int Win,
           int Hout, int Wout, int do_relu, int nsplit, int nOcG, int Cout) {
    constexpr int TW = 32, TH = 32, OCB = 16;
    constexpr int IW = TW + 2, IH = TH + 2;
    constexpr int NPIX = IH * IW;
    constexpr int NLD = (NPIX + 255) / 256;
    __shared__ float sIn[2][NPIX];
    __shared__ __align__(16) float sW[2][9][OCB];

    const int tid = threadIdx.x;
    const int tx = tid & 31, ty = tid >> 5;
    const int ocg = blockIdx.z % nOcG, split = blockIdx.z / nOcG;
    const int oc0 = ocg * OCB;
    const int cs = Cin / nsplit;
    const int ci0 = split * cs;
    const int ox0 = blockIdx.x * TW, oy0 = blockIdx.y * TH;
    const int ix0 = ox0 - 1, iy0 = oy0 - 1;
    const bool interior =
        (ix0 >= 0) && (iy0 >= 0) && (ix0 + IW <= Win) && (iy0 + IH <= Hin);

    float rbuf[NLD];
    float wreg = 0.f;
    const int wj = tid & 15, wt = tid >> 4;

    auto fetch = [&](int ci) {
        const float* inp = in + (size_t)ci * Hin * Win;
        if (interior) {
#pragma unroll
            for (int l = 0; l < NLD; l++) {
                int idx = tid + l * 256;
                if (idx < NPIX) {
                    int r = idx / IW, c = idx % IW;
                    rbuf[l] = __ldg(&inp[(iy0 + r) * Win + ix0 + c]);
                }
            }
        } else {
#pragma unroll
            for (int l = 0; l < NLD; l++) {
                int idx = tid + l * 256;
                if (idx < NPIX) {
                    int r = idx / IW, c = idx % IW;
                    int gy = iy0 + r, gx = ix0 + c;
                    float v = 0.f;
                    if (gy >= 0 && gy < Hin && gx >= 0 && gx < Win)
                        v = inp[gy * Win + gx];
                    rbuf[l] = v;
                }
            }
        }
        if (tid < 144) wreg = w[((size_t)(oc0 + wj) * Cin + ci) * 9 + wt];
    };
    auto sts = [&](int b) {
#pragma unroll
        for (int l = 0; l < NLD; l++) {
            int idx = tid + l * 256;
            if (idx < NPIX) sIn[b][idx] = rbuf[l];
        }
        if (tid < 144) sW[b][wt][wj] = wreg;
    };

    unsigned long long acc[4][8];
#pragma unroll
    for (int r = 0; r < 4; r++)
#pragma unroll
        for (int jp = 0; jp < 8; jp++) acc[r][jp] = 0ull;

    fetch(ci0);
    sts(0);
    __syncthreads();

    for (int i = 0; i < cs; i++) {
        const int b = i & 1;
        const bool more = (i + 1 < cs);
        if (more) fetch(ci0 + i + 1);

#pragma unroll
        for (int ky = 0; ky < 3; ky++) {
#pragma unroll
            for (int kx = 0; kx < 3; kx++) {
                const int t = ky * 3 + kx;
                const longlong2* wp2 = (const longlong2*)&sW[b][t][0];
                longlong2 q0 = wp2[0], q1 = wp2[1], q2 = wp2[2], q3 = wp2[3];
                unsigned long long wv0 = (unsigned long long)q0.x,
                                  wv1 = (unsigned long long)q0.y,
                                  wv2 = (unsigned long long)q1.x,
                                  wv3 = (unsigned long long)q1.y,
                                  wv4 = (unsigned long long)q2.x,
                                  wv5 = (unsigned long long)q2.y,
                                  wv6 = (unsigned long long)q3.x,
                                  wv7 = (unsigned long long)q3.y;
#pragma unroll
                for (int rr = 0; rr < 4; rr++) {
                    float v = sIn[b][(ty * 4 + rr + ky) * IW + tx + kx];
                    unsigned long long vv = dup2(v);
                    ffma2(acc[rr][0], vv, wv0);
                    ffma2(acc[rr][1], vv, wv1);
                    ffma2(acc[rr][2], vv, wv2);
                    ffma2(acc[rr][3], vv, wv3);
                    ffma2(acc[rr][4], vv, wv4);
                    ffma2(acc[rr][5], vv, wv5);
                    ffma2(acc[rr][6], vv, wv6);
                    ffma2(acc[rr][7], vv, wv7);
                }
            }
        }
        if (more) {
            sts(b ^ 1);
            __syncthreads();
        }
    }

    const int xo = ox0 + tx;
    if (xo < Wout) {
#pragma unroll
        for (int rr = 0; rr < 4; rr++) {
            int yo = oy0 + ty * 4 + rr;
            if (yo < Hout) {
#pragma unroll
                for (int jp = 0; jp < 8; jp++) {
                    float2 f = unpack2(acc[rr][jp]);
                    if (nsplit == 1) {
                        if (do_relu) {
                            f.x = fmaxf(f.x, 0.f);
                            f.y = fmaxf(f.y, 0.f);
                        }
                        out[((size_t)(oc0 + 2 * jp) * Hout + yo) * Wout + xo] = f.x;
                        out[((size_t)(oc0 + 2 * jp + 1) * Hout + yo) * Wout + xo] = f.y;
                    } else {
                        size_t base = (size_t)split * Cout;
                        out[((base + oc0 + 2 * jp) * Hout + yo) * Wout + xo] = f.x;
                        out[((base + oc0 + 2 * jp + 1) * Hout + yo) * Wout + xo] = f.y;
                    }
                }
            }
        }
    }
}

// Deterministic fixed-order reduction over Cin-splits (+ optional relu).
__global__ void reduce_split_kernel(const float* __restrict__ part,
                                    float* __restrict__ out, int n, int nsplit,
                                    int do_relu) {
    int i = blockIdx.x * blockDim.x + threadIdx.x;
    if (i >= n) return;
    float acc = 0.f;
    for (int s = 0; s < nsplit; s++) acc += part[(size_t)s * n + i];
    if (do_relu) acc = fmaxf(acc, 0.f);
    out[i] = acc;
}

// ---------------------------------------------------------------------------
// Winograd F(2x2,3x3) for stride-1 convs (Cin=Cout=256, pad 1, H even).
// ---------------------------------------------------------------------------
__global__ void wino_weight_kernel(const float* __restrict__ w,
                                   float* __restrict__ U) {
    int idx = blockIdx.x * blockDim.x + threadIdx.x;
    if (idx >= 65536) return;
    int oc = idx & 255, ci = idx >> 8;
    const float* g = w + ((size_t)oc * 256 + ci) * 9;
    float g00 = g[0], g01 = g[1], g02 = g[2];
    float g10 = g[3], g11 = g[4], g12 = g[5];
    float g20 = g[6], g21 = g[7], g22 = g[8];
    float t0[3] = {g00, g01, g02};
    float t1[3] = {0.5f * (g00 + g10 + g20), 0.5f * (g01 + g11 + g21),
                   0.5f * (g02 + g12 + g22)};
    float t2[3] = {0.5f * (g00 - g10 + g20), 0.5f * (g01 - g11 + g21),
                   0.5f * (g02 - g12 + g22)};
    float t3[3] = {g20, g21, g22};
    float* rows[4] = {t0, t1, t2, t3};
    float u[16];
#pragma unroll
    for (int r = 0; r < 4; r++) {
        float* t = rows[r];
        u[r * 4 + 0] = t[0];
        u[r * 4 + 1] = 0.5f * (t[0] + t[1] + t[2]);
        u[r * 4 + 2] = 0.5f * (t[0] - t[1] + t[2]);
        u[r * 4 + 3] = t[2];
    }
#pragma unroll
    for (int k = 0; k < 16; k++)
        U[(size_t)k * 65536 + ci * 256 + oc] = u[k];
}

__global__ void wino_input_kernel(const float* __restrict__ in,
                                  float* __restrict__ V, int H, int tpr,
                                  int ntiles) {
    int idx = blockIdx.x * blockDim.x + threadIdx.x;
    if (idx >= 256 * ntiles) return;
    int tile = idx % ntiles, ci = idx / ntiles;
    int ty = tile / tpr, tx = tile % tpr;
    const float* inp = in + (size_t)ci * H * H;
    int iy0 = ty * 2 - 1, ix0 = tx * 2 - 1;
    float d[4][4];
#pragma unroll
    for (int r = 0; r < 4; r++) {
        int iy = iy0 + r;
#pragma unroll
        for (int c = 0; c < 4; c++) {
            int ix = ix0 + c;
            d[r][c] = (iy >= 0 && iy < H && ix >= 0 && ix < H) ? inp[iy * H + ix]
                                                               : 0.f;
        }
    }
    float e[4][4];
#pragma unroll
    for (int c = 0; c < 4; c++) {
        e[0][c] = d[0][c] - d[2][c];
        e[1][c] = d[1][c] + d[2][c];
        e[2][c] = d[2][c] - d[1][c];
        e[3][c] = d[1][c] - d[3][c];
    }
    float v[16];
#pragma unroll
    for (int r = 0; r < 4; r++) {
        v[r * 4 + 0] = e[r][0] - e[r][2];
        v[r * 4 + 1] = e[r][1] + e[r][2];
        v[r * 4 + 2] = e[r][2] - e[r][1];
        v[r * 4 + 3] = e[r][1] - e[r][3];
    }
    size_t base = (size_t)ci * ntiles + tile;
    size_t kstride = (size_t)256 * ntiles;
#pragma unroll
    for (int k = 0; k < 16; k++) V[base + (size_t)k * kstride] = v[k];
}

// Batched GEMM: M[k][oc][tile] = sum_ci U[k][ci][oc] * V[k][ci][tile].
__global__ void wino_gemm_kernel(const float* __restrict__ U,
                                 const float* __restrict__ V,
                                 float* __restrict__ M, int ntiles) {
    constexpr int BM = 64, BN = 64, BK = 16;
    __shared__ float sA[BK][BM + 1];
    __shared__ __align__(16) float sB[BK][BN + 2];
    const int tid = threadIdx.x;
    const int trow = tid / 16, tcol = tid % 16;
    const int bn0 = blockIdx.x * BN, bm0 = blockIdx.y * BM;
    const int k = blockIdx.z;
    const float* A = U + (size_t)k * 65536;
    const float* B = V + (size_t)k * 256 * ntiles;
    float* C = M + (size_t)k * 256 * ntiles;

    unsigned long long acc2[4][2];
#pragma unroll
    for (int i = 0; i < 4; i++) { acc2[i][0] = 0ull; acc2[i][1] = 0ull; }

    for (int k0 = 0; k0 < 256; k0 += BK) {
#pragma unroll
        for (int l = 0; l < 4; l++) {
            int e = tid + l * 256;
            int ar = e & 63, ac = e >> 6;
            sA[ac][ar] = A[(size_t)(k0 + ac) * 256 + bm0 + ar];
        }
#pragma unroll
        for (int l = 0; l < 4; l++) {
            int e = tid + l * 256;
            int bc = e & 63, br = e >> 6;
            int n = bn0 + bc;
            sB[br][bc] = (n < ntiles) ? B[(size_t)(k0 + br) * ntiles + n] : 0.f;
        }
        __syncthreads();
#pragma unroll
        for (int kk = 0; kk < BK; kk++) {
            unsigned long long b0 = *(const unsigned long long*)&sB[kk][tcol * 4];
            unsigned long long b1 = *(const unsigned long long*)&sB[kk][tcol * 4 + 2];
#pragma unroll
            for (int i = 0; i < 4; i++) {
                unsigned long long vv = dup2(sA[kk][trow * 4 + i]);
                ffma2(acc2[i][0], vv, b0);
                ffma2(acc2[i][1], vv, b1);
            }
        }
        __syncthreads();
    }
#pragma unroll
    for (int i = 0; i < 4; i++) {
        int r = bm0 + trow * 4 + i;
#pragma unroll
        for (int jp = 0; jp < 2; jp++) {
            int c = bn0 + tcol * 4 + 2 * jp;
            float2 f = unpack2(acc2[i][jp]);
            if (c < ntiles) C[(size_t)r * ntiles + c] = f.x;
            if (c + 1 < ntiles) C[(size_t)r * ntiles + c + 1] = f.y;
        }
    }
}

__global__ void wino_output_kernel(const float* __restrict__ M,
                                   float* __restrict__ out, int H, int tpr,
                                   int ntiles, int do_relu) {
    int idx = blockIdx.x * blockDim.x + threadIdx.x;
    if (idx >= 256 * ntiles) return;
    int tile = idx % ntiles, oc = idx / ntiles;
    size_t base = (size_t)oc * ntiles + tile;
    size_t kstride = (size_t)256 * ntiles;
    float m[16];
#pragma unroll
    for (int k = 0; k < 16; k++) m[k] = M[base + (size_t)k * kstride];
    float f0[4], f1[4];
#pragma unroll
    for (int c = 0; c < 4; c++) {
        f0[c] = m[0 * 4 + c] + m[1 * 4 + c] + m[2 * 4 + c];
        f1[c] = m[1 * 4 + c] - m[2 * 4 + c] - m[3 * 4 + c];
    }
    float y00 = f0[0] + f0[1] + f0[2];
    float y01 = f0[1] - f0[2] - f0[3];
    float y10 = f1[0] + f1[1] + f1[2];
    float y11 = f1[1] - f1[2] - f1[3];
    if (do_relu) {
        y00 = fmaxf(y00, 0.f);
        y01 = fmaxf(y01, 0.f);
        y10 = fmaxf(y10, 0.f);
        y11 = fmaxf(y11, 0.f);
    }
    int ty = tile / tpr, tx = tile % tpr;
    float* o = out + (size_t)oc * H * H + (ty * 2) * H + tx * 2;
    o[0] = y00;
    o[1] = y01;
    o[H] = y10;
    o[H + 1] = y11;
}

// ---------------------------------------------------------------------------
// Fused RPN head: 1x1 cls (3) + 1x1 box (12) + anchor decode.
// ---------------------------------------------------------------------------
__global__ void rpn_head_kernel(const float* __restrict__ t,
                                const float* __restrict__ cls_w,
                                const float* __restrict__ box_w,
                                int HW, int fw, float stride, float size,
                                float* __restrict__ dec_boxes,
                                float* __restrict__ dec_scores) {
    __shared__ float sCW[3][256];
    __shared__ float sBW[12][256];
    const int tid = threadIdx.x;
    for (int idx = tid; idx < 3 * 256; idx += 256) sCW[idx >> 8][idx & 255] = cls_w[idx];
    for (int idx = tid; idx < 12 * 256; idx += 256) sBW[idx >> 8][idx & 255] = box_w[idx];
    __syncthreads();

    const int p = blockIdx.x * 256 + tid;
    if (p >= HW) return;

    float accC[3] = {0.f, 0.f, 0.f};
    float accB[12];
#pragma unroll
    for (int j = 0; j < 12; j++) accB[j] = 0.f;

    for (int ci = 0; ci < 256; ci++) {
        float v = t[(size_t)ci * HW + p];
#pragma unroll
        for (int j = 0; j < 3; j++) accC[j] += v * sCW[j][ci];
#pragma unroll
        for (int j = 0; j < 12; j++) accB[j] += v * sBW[j][ci];
    }

    const int x = p % fw, y = p / fw;
    const double wm[3] = {1.4142135623730951, 1.0, 0.7071067811865476};
    const double hm[3] = {0.7071067811865476, 1.0, 1.4142135623730951};
    float acx = (x + 0.5f) * stride;
    float acy = (y + 0.5f) * stride;

#pragma unroll
    for (int a = 0; a < 3; a++) {
        float aw = (float)(size * wm[a]);
        float ah = (float)(size * hm[a]);
        float d0 = accB[a * 4 + 0];
        float d1 = accB[a * 4 + 1];
        float dw = fminf(fmaxf(accB[a * 4 + 2], -4.f), 4.f);
        float dh = fminf(fmaxf(accB[a * 4 + 3], -4.f), 4.f);
        float cx = acx + d0 * aw;
        float cy = acy + d1 * ah;
        float w = aw * expf(dw);
        float h = ah * expf(dh);
        int i = p * 3 + a;
        dec_boxes[i * 4 + 0] = fminf(fmaxf(cx - w * 0.5f, 0.f), 800.f);
        dec_boxes[i * 4 + 1] = fminf(fmaxf(cy - h * 0.5f, 0.f), 800.f);
        dec_boxes[i * 4 + 2] = fminf(fmaxf(cx + w * 0.5f, 0.f), 800.f);
        dec_boxes[i * 4 + 3] = fminf(fmaxf(cy + h * 0.5f, 0.f), 800.f);
        dec_scores[i] = accC[a];
    }
}

// ---------------------------------------------------------------------------
// Top-k (k = 1000): 4 levels in ONE launch, one block per level.
// ---------------------------------------------------------------------------
__device__ __forceinline__ unsigned keyof(float f) {
    unsigned u = __float_as_uint(f);
    return (u & 0x80000000u) ? ~u : (u | 0x80000000u);
}

__global__ void topk4_kernel(const float* __restrict__ all_scores,
                             const float* __restrict__ all_boxes,
                             const int4 offs, const int4 lens,
                             float* __restrict__ out_scores4k,
                             float* __restrict__ out_boxes4k) {
    const int lvl = blockIdx.x;
    const int off = (lvl == 0) ? offs.x : (lvl == 1) ? offs.y : (lvl == 2) ? offs.z : offs.w;
    const int n   = (lvl == 0) ? lens.x : (lvl == 1) ? lens.y : (lvl == 2) ? lens.z : lens.w;
    const int k = 1000;
    const float* scores = all_scores + off;
    const float* boxes = all_boxes + (size_t)off * 4;
    float* out_scores = out_scores4k + lvl * 1000;
    float* out_boxes = out_boxes4k + lvl * 4000;

    __shared__ unsigned hist[256];
    __shared__ unsigned sh_prefix, sh_kk, sh_cgt, sh_ceq;
    int tid = threadIdx.x;
    int NT = blockDim.x;
    if (tid == 0) { sh_prefix = 0; sh_kk = (unsigned)k; }
    unsigned mask = 0;
    __syncthreads();
    for (int shift = 24; shift >= 0; shift -= 8) {
        for (int b = tid; b < 256; b += NT) hist[b] = 0;
        __syncthreads();
        unsigned prefix = sh_prefix;
        for (int i = tid; i < n; i += NT) {
            unsigned key = keyof(scores[i]);
            if ((key & mask) == prefix) atomicAdd(&hist[(key >> shift) & 255], 1u);
        }
        __syncthreads();
        if (tid == 0) {
            unsigned kk = sh_kk, cum = 0;
            int b = 255;
            for (; b > 0; b--) {
                if (cum + hist[b] >= kk) break;
                cum += hist[b];
            }
            sh_prefix = prefix | ((unsigned)b << shift);
            sh_kk = kk - cum;
        }
        mask |= (0xFFu << shift);
        __syncthreads();
    }
    unsigned T = sh_prefix;
    unsigned kk = sh_kk;
    if (tid == 0) { sh_cgt = 0; sh_ceq = 0; }
    __syncthreads();
    int gtcount = k - (int)kk;
    for (int i = tid; i < n; i += NT) {
        unsigned key = keyof(scores[i]);
        int slot = -1;
        if (key > T) {
            slot = (int)atomicAdd(&sh_cgt, 1u);
        } else if (key == T) {
            unsigned e = atomicAdd(&sh_ceq, 1u);
            if (e < kk) slot = gtcount + (int)e;
        }
        if (slot >= 0) {
            out_scores[slot] = scores[i];
            out_boxes[slot * 4 + 0] = boxes[i * 4 + 0];
            out_boxes[slot * 4 + 1] = boxes[i * 4 + 1];
            out_boxes[slot * 4 + 2] = boxes[i * 4 + 2];
            out_boxes[slot * 4 + 3] = boxes[i * 4 + 3];
        }
    }
}

// ---------------------------------------------------------------------------
// NMS: one block, 512 threads, 512 sequential selections over 4000 candidates.
// ---------------------------------------------------------------------------
__global__ void nms_kernel(const float* __restrict__ boxes, const float* __restrict__ scores,
                           float* __restrict__ props, float* __restrict__ out_props,
                           float* __restrict__ out_scores) {
    constexpr int N = 4000, NT = 512, POST = 512;
    extern __shared__ float sm[];
    float* sx1 = sm;
    float* sy1 = sm + N;
    float* sx2 = sm + 2 * N;
    float* sy2 = sm + 3 * N;
    float* sar = sm + 4 * N;
    float* ss  = sm + 5 * N;
    __shared__ float rv[NT / 32];
    __shared__ int ri[NT / 32];
    __shared__ int s_best;

    int tid = threadIdx.x;
    for (int i = tid; i < N; i += NT) {
        float a = boxes[i * 4 + 0], b = boxes[i * 4 + 1];
        float c = boxes[i * 4 + 2], d = boxes[i * 4 + 3];
        sx1[i] = a; sy1[i] = b; sx2[i] = c; sy2[i] = d;
        sar[i] = (c - a) * (d - b);
        ss[i] = scores[i];
    }
    __syncthreads();

    for (int it = 0; it < POST; it++) {
        float bv = -INFINITY;
        int bi = 0x7FFFFFFF;
        for (int i = tid; i < N; i += NT) {
            float v = ss[i];
            if (v > bv || (v == bv && i < bi)) { bv = v; bi = i; }
        }
#pragma unroll
        for (int off = 16; off; off >>= 1) {
            float ov = __shfl_down_sync(0xFFFFFFFFu, bv, off);
            int oi = __shfl_down_sync(0xFFFFFFFFu, bi, off);
            if (ov > bv || (ov == bv && oi < bi)) { bv = ov; bi = oi; }
        }
        if ((tid & 31) == 0) { rv[tid >> 5] = bv; ri[tid >> 5] = bi; }
        __syncthreads();
        if (tid == 0) {
            float fbv = rv[0]; int fbi = ri[0];
            for (int wz = 1; wz < NT / 32; wz++) {
                float ov = rv[wz]; int oi = ri[wz];
                if (ov > fbv || (ov == fbv && oi < fbi)) { fbv = ov; fbi = oi; }
            }
            s_best = fbi;
        }
        __syncthreads();
        int idx = s_best;
        if (tid == 0) {
            float a = sx1[idx], b = sy1[idx], c = sx2[idx], d = sy2[idx];
            props[it * 4 + 0] = a; props[it * 4 + 1] = b;
            props[it * 4 + 2] = c; props[it * 4 + 3] = d;
            out_props[it * 4 + 0] = a; out_props[it * 4 + 1] = b;
            out_props[it * 4 + 2] = c; out_props[it * 4 + 3] = d;
            out_scores[it] = scores[idx];
        }
        float X1 = sx1[idx], Y1 = sy1[idx], X2 = sx2[idx], Y2 = sy2[idx], AR = sar[idx];
        for (int i = tid; i < N; i += NT) {
            float ix1 = fmaxf(sx1[i], X1), iy1 = fmaxf(sy1[i], Y1);
            float ix2 = fminf(sx2[i], X2), iy2 = fminf(sy2[i], Y2);
            float inter = fmaxf(ix2 - ix1, 0.f) * fmaxf(iy2 - iy1, 0.f);
            float iou = inter / (sar[i] + AR - inter + 1e-6f);
            if (iou > 0.7f) ss[i] = -INFINITY;
        }
        __syncthreads();
    }
}

// ---------------------------------------------------------------------------
// ROI Align on feats[0] (256, 200, 200), scale 0.25, POOL 7.
// ---------------------------------------------------------------------------
__global__ void roi_align_kernel(const float* __restrict__ feat, const float* __restrict__ rois,
                                 float* __restrict__ out) {
    __shared__ int six0[49], siy0[49], six1[49], siy1[49];
    __shared__ float swx[49], swy[49];
    int roi = blockIdx.x;
    int c = threadIdx.x;
    if (threadIdx.x < 49) {
        int p = threadIdx.x;
        int py = p / 7, px = p % 7;
        float r0 = rois[roi * 4 + 0] * 0.25f;
        float r1 = rois[roi * 4 + 1] * 0.25f;
        float bw = (rois[roi * 4 + 2] - rois[roi * 4 + 0]) * 0.25f / 7.0f;
        float bh = (rois[roi * 4 + 3] - rois[roi * 4 + 1]) * 0.25f / 7.0f;
        float gx = r0 + (px + 0.5f) * bw - 0.5f;
        float gy = r1 + (py + 0.5f) * bh - 0.5f;
        float fx = fminf(fmaxf(floorf(gx), 0.f), 199.f);
        float fy = fminf(fmaxf(floorf(gy), 0.f), 199.f);
        int x0 = (int)fx, y0 = (int)fy;
        six0[p] = x0; siy0[p] = y0;
        six1[p] = min(x0 + 1, 199);
        siy1[p] = min(y0 + 1, 199);
        swx[p] = fminf(fmaxf(gx - fx, 0.f), 1.f);
        swy[p] = fminf(fmaxf(gy - fy, 0.f), 1.f);
    }
    __syncthreads();
    const float* f = feat + (size_t)c * 40000;
    float* o = out + (size_t)roi * 12544 + (size_t)c * 49;
#pragma unroll 7
    for (int p = 0; p < 49; p++) {
        int x0 = six0[p], y0 = siy0[p], x1 = six1[p], y1 = siy1[p];
        float wx = swx[p], wy = swy[p];
        float v00 = f[y0 * 200 + x0];
        float v01 = f[y0 * 200 + x1];
        float v10 = f[y1 * 200 + x0];
        float v11 = f[y1 * 200 + x1];
        o[p] = v00 * (1.f - wy) * (1.f - wx) + v01 * (1.f - wy) * wx +
               v10 * wy * (1.f - wx) + v11 * wy * wx;
    }
}

// ---------------------------------------------------------------------------
// SGEMM: C = relu(A @ B + bias). f32x2 over N-column pairs.
// ---------------------------------------------------------------------------
__global__ void sgemm_bias_relu(const float* __restrict__ A, const float* __restrict__ B,
                                const float* __restrict__ bias, float* __restrict__ C,
                                int M, int N, int K, int do_relu) {
    constexpr int BM = 64, BN = 64, BK = 16;
    __shared__ float sA[BK][BM + 1];
    __shared__ __align__(16) float sB[BK][BN + 2];
    int tid = threadIdx.x;
    int trow = tid / 16, tcol = tid % 16;
    int bm0 = blockIdx.y * BM, bn0 = blockIdx.x * BN;
    unsigned long long acc2[4][2];
#pragma unroll
    for (int i = 0; i < 4; i++) { acc2[i][0] = 0ull; acc2[i][1] = 0ull; }

    for (int k0 = 0; k0 < K; k0 += BK) {
#pragma unroll
        for (int l = 0; l < 4; l++) {
            int e = tid + l * 256;
            int ar = e / BK, ac = e % BK;
            sA[ac][ar] = A[(size_t)(bm0 + ar) * K + k0 + ac];
        }
#pragma unroll
        for (int l = 0; l < 4; l++) {
            int e = tid + l * 256;
            int br = e >> 6, bc = e & 63;
            sB[br][bc] = B[(size_t)(k0 + br) * N + bn0 + bc];
        }
        __syncthreads();
#pragma unroll
        for (int kk = 0; kk < BK; kk++) {
            unsigned long long b0 = *(const unsigned long long*)&sB[kk][tcol * 4];
            unsigned long long b1 = *(const unsigned long long*)&sB[kk][tcol * 4 + 2];
#pragma unroll
            for (int i = 0; i < 4; i++) {
                unsigned long long vv = dup2(sA[kk][trow * 4 + i]);
                ffma2(acc2[i][0], vv, b0);
                ffma2(acc2[i][1], vv, b1);
            }
        }
        __syncthreads();
    }
#pragma unroll
    for (int i = 0; i < 4; i++) {
        int r = bm0 + trow * 4 + i;
#pragma unroll
        for (int jp = 0; jp < 2; jp++) {
            int cidx = bn0 + tcol * 4 + 2 * jp;
            float2 f = unpack2(acc2[i][jp]);
            f.x += bias[cidx];
            f.y += bias[cidx + 1];
            if (do_relu) { f.x = fmaxf(f.x, 0.f); f.y = fmaxf(f.y, 0.f); }
            C[(size_t)r * N + cidx] = f.x;
            C[(size_t)r * N + cidx + 1] = f.y;
        }
    }
}

// K-split partial SGEMM: Cpart[z] = A[:, zKc:(z+1)Kc] @ B[zKc:(z+1)Kc, :].
__global__ void sgemm_part(const float* __restrict__ A, const float* __restrict__ B,
                           float* __restrict__ Cpart, int M, int N, int K, int Kc) {
    constexpr int BM = 64, BN = 64, BK = 16;
    __shared__ float sA[BK][BM + 1];
    __shared__ __align__(16) float sB[BK][BN + 2];
    int tid = threadIdx.x;
    int trow = tid / 16, tcol = tid % 16;
    int bm0 = blockIdx.y * BM, bn0 = blockIdx.x * BN;
    int kbase = blockIdx.z * Kc;
    float* C = Cpart + (size_t)blockIdx.z * M * N;
    unsigned long long acc2[4][2];
#pragma unroll
    for (int i = 0; i < 4; i++) { acc2[i][0] = 0ull; acc2[i][1] = 0ull; }

    for (int k0 = kbase; k0 < kbase + Kc; k0 += BK) {
#pragma unroll
        for (int l = 0; l < 4; l++) {
            int e = tid + l * 256;
            int ar = e / BK, ac = e % BK;
            sA[ac][ar] = A[(size_t)(bm0 + ar) * K + k0 + ac];
        }
#pragma unroll
        for (int l = 0; l < 4; l++) {
            int e = tid + l * 256;
            int br = e >> 6, bc = e & 63;
            sB[br][bc] = B[(size_t)(k0 + br) * N + bn0 + bc];
        }
        __syncthreads();
#pragma unroll
        for (int kk = 0; kk < BK; kk++) {
            unsigned long long b0 = *(const unsigned long long*)&sB[kk][tcol * 4];
            unsigned long long b1 = *(const unsigned long long*)&sB[kk][tcol * 4 + 2];
#pragma unroll
            for (int i = 0; i < 4; i++) {
                unsigned long long vv = dup2(sA[kk][trow * 4 + i]);
                ffma2(acc2[i][0], vv, b0);
                ffma2(acc2[i][1], vv, b1);
            }
        }
        __syncthreads();
    }
#pragma unroll
    for (int i = 0; i < 4; i++) {
        int r = bm0 + trow * 4 + i;
#pragma unroll
        for (int jp = 0; jp < 2; jp++) {
            int cidx = bn0 + tcol * 4 + 2 * jp;
            float2 f = unpack2(acc2[i][jp]);
            C[(size_t)r * N + cidx] = f.x;
            C[(size_t)r * N + cidx + 1] = f.y;
        }
    }
}

// Fixed-order K-split reduce + bias + relu. n = M*N.
__global__ void fc_reduce_kernel(const float* __restrict__ part,
                                 const float* __restrict__ bias,
                                 float* __restrict__ out, int n, int N,
                                 int nsplit) {
    int i = blockIdx.x * blockDim.x + threadIdx.x;
    if (i >= n) return;
    float acc = 0.f;
    for (int s = 0; s < nsplit; s++) acc += part[(size_t)s * n + i];
    acc += bias[i % N];
    out[i] = fmaxf(acc, 0.f);
}

// ---------------------------------------------------------------------------
// Final heads: cls (1024->2) and breg (1024->8), write directly to d_out.
// ---------------------------------------------------------------------------
__global__ void head_kernel(const float* __restrict__ A, const float* __restrict__ cw,
                            const float* __restrict__ cb, const float* __restrict__ bw,
                            const float* __restrict__ bb, float* __restrict__ out) {
    int m = blockIdx.x;
    int j = threadIdx.x;
    if (j >= 10) return;
    const float* a = A + (size_t)m * 1024;
    bool is_cls = (j < 2);
    const float* W = is_cls ? cw : bw;
    int n = is_cls ? j : j - 2;
    int N = is_cls ? 2 : 8;
    float acc = 0.f;
    for (int k = 0; k < 1024; k++) acc += a[k] * W[(size_t)k * N + n];
    acc += is_cls ? cb[n] : bb[n];
    if (is_cls) out[m * 2 + n] = acc;
    else out[1024 + m * 8 + n] = acc;
}

// ---------------------------------------------------------------------------
// Host: launch sequence
// ---------------------------------------------------------------------------
static inline void* symaddr(const void* sym) {
    void* p = nullptr;
    cudaGetSymbolAddress(&p, sym);
    return p;
}

static inline int ceil_div(int a, int b) { return (a + b - 1) / b; }

extern "C" void kernel_launch(void* const* d_in, const int* in_sizes, int n_in,
                              void* d_out, int out_size) {
    const float* x       = (const float*)d_in[0];
    const float* stem_w  = (const float*)d_in[1];
    const float* c2_w    = (const float*)d_in[2];
    const float* c3_w    = (const float*)d_in[3];
    const float* c4_w    = (const float*)d_in[4];
    const float* c5_w    = (const float*)d_in[5];
    const float* fpn_w[4] = {(const float*)d_in[6], (const float*)d_in[7],
                             (const float*)d_in[8], (const float*)d_in[9]};
    const float* rpn_w     = (const float*)d_in[10];
    const float* rpn_cls_w = (const float*)d_in[11];
    const float* rpn_box_w = (const float*)d_in[12];
    const float* fc1_w = (const float*)d_in[13];
    const float* fc1_b = (const float*)d_in[14];
    const float* fc2_w = (const float*)d_in[15];
    const float* fc2_b = (const float*)d_in[16];
    const float* cls_w = (const float*)d_in[17];
    const float* cls_b = (const float*)d_in[18];
    const float* breg_w = (const float*)d_in[19];
    const float* breg_b = (const float*)d_in[20];
    float* out = (float*)d_out;

    float* p_stem = (float*)symaddr(g_stem);
    float* p_c2   = (float*)symaddr(g_c2);
    float* p_c3   = (float*)symaddr(g_c3);
    float* p_c4   = (float*)symaddr(g_c4);
    float* p_c5   = (float*)symaddr(g_c5);
    float* p_f[4] = {(float*)symaddr(g_f2), (float*)symaddr(g_f3),
                     (float*)symaddr(g_f4), (float*)symaddr(g_f5)};
    float* p_t    = (float*)symaddr(g_t);
    float* p_part = (float*)symaddr(g_part);
    float* p_U    = (float*)symaddr(g_winoU);
    float* p_Ur   = (float*)symaddr(g_winoUrpn);
    float* p_V    = (float*)symaddr(g_winoV);
    float* p_M    = (float*)symaddr(g_winoM);
    float* p_decb = (float*)symaddr(g_decb);
    float* p_decs = (float*)symaddr(g_decs);
    float* p_b4k  = (float*)symaddr(g_boxes4k);
    float* p_s4k  = (float*)symaddr(g_scores4k);
    float* p_props = (float*)symaddr(g_props);
    float* p_pool = (float*)symaddr(g_pooled);
    float* p_fc1  = (float*)symaddr(g_fc1);
    float* p_fc2  = (float*)symaddr(g_fc2);

    const int fh[4] = {200, 100, 50, 25};
    const int doff[4] = {0, 120000, 150000, 157500};  // decode region offsets

    // Winograd conv using a precomputed U (Cin=Cout=256, pad 1, H even)
    auto wino_conv_u = [&](const float* in, const float* U, float* outp, int H,
                           int relu) {
        int tpr = H / 2, ntiles = tpr * tpr;
        wino_input_kernel<<<ceil_div(256 * ntiles, 256), 256>>>(in, p_V, H, tpr,
                                                                ntiles);
        wino_gemm_kernel<<<dim3(ceil_div(ntiles, 64), 4, 16), 256>>>(
            (float*)U, p_V, p_M, ntiles);
        wino_output_kernel<<<ceil_div(256 * ntiles, 256), 256>>>(p_M, outp, H, tpr,
                                                                 ntiles, relu);
    };

    // 1. stem 7x7 s2 with fused normalize
    stem_v2<<<dim3(13, 50, 4), 128>>>(x, stem_w, p_stem);

    // Precompute U for the shared RPN weight (reused at levels 0-2)
    wino_weight_kernel<<<256, 256>>>(rpn_w, p_Ur);

    // 2. backbone strided 3x3 convs (relu) — v3 path
    conv3x3_v3<2, 0><<<dim3(7, 13, 16), 256>>>(p_stem, c2_w, p_c2, 64, 400, 400,
                                               200, 200, 1, 1, 16, 256);
    conv3x3_v3<2, 0><<<dim3(4, 7, 16 * 4), 256>>>(p_c2, c3_w, p_part, 256, 200, 200,
                                                  100, 100, 1, 4, 16, 256);
    reduce_split_kernel<<<ceil_div(256 * 10000, 256), 256>>>(p_part, p_c3,
                                                             256 * 10000, 4, 1);
    conv3x3_v3<2, 0><<<dim3(2, 4, 16 * 8), 256>>>(p_c3, c4_w, p_part, 256, 100, 100,
                                                  50, 50, 1, 8, 16, 256);
    reduce_split_kernel<<<ceil_div(256 * 2500, 256), 256>>>(p_part, p_c4,
                                                            256 * 2500, 8, 1);
    conv3x3_v3<2, 0><<<dim3(1, 2, 16 * 16), 256>>>(p_c4, c5_w, p_part, 256, 50, 50,
                                                   25, 25, 1, 16, 16, 256);
    reduce_split_kernel<<<ceil_div(256 * 625, 256), 256>>>(p_part, p_c5,
                                                           256 * 625, 16, 1);

    // 3. FPN lateral convs (no relu): Winograd for levels 0-2 (H even), v4 for 3
    const float* csrc[4] = {p_c2, p_c3, p_c4, p_c5};
    for (int l = 0; l < 4; l++) {
        int H = fh[l], HW = H * H;
        if (l < 3) {
            wino_weight_kernel<<<256, 256>>>(fpn_w[l], p_U);
            wino_conv_u(csrc[l], p_U, p_f[l], H, 0);
        } else {
            int k = 16;
            dim3 g(ceil_div(H, 32), ceil_div(H, 32), 16 * k);
            conv3x3_v4<<<g, 256>>>(csrc[l], fpn_w[l], p_part, 256, H, H, H, H,
                                   0, k, 16, 256);
            reduce_split_kernel<<<ceil_div(256 * HW, 256), 256>>>(p_part, p_f[l],
                                                                  256 * HW, k, 0);
        }
    }

    // 4. RPN per level: conv-relu (wino with cached U / v4), fused head+decode
    const float strides[4] = {4.f, 8.f, 16.f, 32.f};
    const float sizes[4] = {32.f, 64.f, 128.f, 256.f};
    for (int l = 0; l < 4; l++) {
        int H = fh[l], HW = H * H;
        if (l < 3) {
            wino_conv_u(p_f[l], p_Ur, p_t, H, 1);
        } else {
            int k = 16;
            dim3 g(ceil_div(H, 32), ceil_div(H, 32), 16 * k);
            conv3x3_v4<<<g, 256>>>(p_f[l], rpn_w, p_part, 256, H, H, H, H,
                                   1, k, 16, 256);
            reduce_split_kernel<<<ceil_div(256 * HW, 256), 256>>>(p_part, p_t,
                                                                  256 * HW, k, 1);
        }
        rpn_head_kernel<<<ceil_div(HW, 256), 256>>>(p_t, rpn_cls_w, rpn_box_w,
                                                    HW, H, strides[l], sizes[l],
                                                    p_decb + (size_t)doff[l] * 4,
                                                    p_decs + doff[l]);
    }

    // 5. Combined top-1000 over 4 levels (one launch, 4 blocks)
    {
        int4 offs = make_int4(doff[0], doff[1], doff[2], doff[3]);
        int4 lens = make_int4(120000, 30000, 7500, 1875);
        topk4_kernel<<<4, 1024>>>(p_decs, p_decb, offs, lens, p_s4k, p_b4k);
    }

    // 6. NMS (512 out of 4000)
    cudaFuncSetAttribute(nms_kernel, cudaFuncAttributeMaxDynamicSharedMemorySize, 96000);
    nms_kernel<<<1, 512, 96000>>>(p_b4k, p_s4k, p_props, out + 5120, out + 7168);

    // 7. ROI align on feats[0]
    roi_align_kernel<<<512, 256>>>(p_f[0], p_props, p_pool);

    // 8. FC head: fc1 via K-split (4 x 3136) for full-chip occupancy
    sgemm_part<<<dim3(16, 8, 4), 256>>>(p_pool, fc1_w, p_part, 512, 1024, 12544,
                                        3136);
    fc_reduce_kernel<<<ceil_div(512 * 1024, 256), 256>>>(p_part, fc1_b, p_fc1,
                                                         512 * 1024, 1024, 4);
    sgemm_bias_relu<<<dim3(1024 / 64, 512 / 64), 256>>>(p_fc1, fc2_w, fc2_b, p_fc2,
                                                        512, 1024, 1024, 1);
    head_kernel<<<512, 32>>>(p_fc2, cls_w, cls_b, breg_w, breg_b, out);
}